// round 1
// baseline (speedup 1.0000x reference)
#include <cuda_runtime.h>
#include <math.h>

// ---------------- problem constants ----------------
#define B   2
#define S   1024
#define H   4096
#define NH  32
#define NKV 8
#define D   128
#define GROUPS (NH / NKV)   // 4
#define EPS 1e-6f
#define QSCALE 0.08838834764831845f   // 1/sqrt(128)

#define MSEQ (B * S)        // 2048 rows

// ---------------- scratch (device globals; no allocations allowed) ----------------
__device__ float g_q [MSEQ * NH  * D];   // [B*S, NH*D]   proj output
__device__ float g_k [MSEQ * NKV * D];   // [B*S, NKV*D]
__device__ float g_v [MSEQ * NKV * D];
__device__ float g_qt[B * NH  * S * D];  // [B,NH,S,D]  rope'd, scaled
__device__ float g_kt[B * NKV * S * D];  // [B,NKV,S,D] rope'd
__device__ float g_vt[B * NKV * S * D];  // [B,NKV,S,D]
__device__ float g_ao[MSEQ * NH * D];    // attention out [B*S, NH*D]

// ============================================================================
// SGEMM (NT): C[M,N] = A[M,K] * B[N,K]^T, all row-major, fp32.
// Tile 128x128, K-tile 16, 256 threads, 8x8 per thread.
// M,N,K assumed multiples of 128/128/16 (true for all calls here).
// ============================================================================
__global__ void __launch_bounds__(256) sgemm_nt(
    const float* __restrict__ A, const float* __restrict__ Bm,
    float* __restrict__ C, int M, int N, int K)
{
    __shared__ float As[16][128];
    __shared__ float Bs[16][128];

    const int tid = threadIdx.x;
    const int tr = tid >> 4;          // 0..15 -> rows tr*8..+7
    const int tc = tid & 15;          // 0..15 -> cols tc*8..+7
    const size_t m0 = (size_t)blockIdx.y * 128;
    const size_t n0 = (size_t)blockIdx.x * 128;

    float acc[8][8];
#pragma unroll
    for (int i = 0; i < 8; i++)
#pragma unroll
        for (int j = 0; j < 8; j++) acc[i][j] = 0.f;

    for (int k0 = 0; k0 < K; k0 += 16) {
        __syncthreads();
        // 512 float4 per tile per matrix; 2 per thread
#pragma unroll
        for (int f = tid; f < 512; f += 256) {
            const int r  = f >> 2;
            const int c4 = (f & 3) << 2;
            float4 a = *(const float4*)(A  + (m0 + r) * (size_t)K + k0 + c4);
            As[c4 + 0][r] = a.x; As[c4 + 1][r] = a.y;
            As[c4 + 2][r] = a.z; As[c4 + 3][r] = a.w;
            float4 b = *(const float4*)(Bm + (n0 + r) * (size_t)K + k0 + c4);
            Bs[c4 + 0][r] = b.x; Bs[c4 + 1][r] = b.y;
            Bs[c4 + 2][r] = b.z; Bs[c4 + 3][r] = b.w;
        }
        __syncthreads();
#pragma unroll
        for (int kk = 0; kk < 16; kk++) {
            float a[8], b[8];
            *(float4*)&a[0] = *(const float4*)&As[kk][tr * 8];
            *(float4*)&a[4] = *(const float4*)&As[kk][tr * 8 + 4];
            *(float4*)&b[0] = *(const float4*)&Bs[kk][tc * 8];
            *(float4*)&b[4] = *(const float4*)&Bs[kk][tc * 8 + 4];
#pragma unroll
            for (int i = 0; i < 8; i++)
#pragma unroll
                for (int j = 0; j < 8; j++) acc[i][j] += a[i] * b[j];
        }
    }

#pragma unroll
    for (int i = 0; i < 8; i++) {
        float* cp = C + (m0 + tr * 8 + i) * (size_t)N + n0 + tc * 8;
        *(float4*)cp       = make_float4(acc[i][0], acc[i][1], acc[i][2], acc[i][3]);
        *(float4*)(cp + 4) = make_float4(acc[i][4], acc[i][5], acc[i][6], acc[i][7]);
    }
}

// ============================================================================
// Per-head RMSNorm + RoPE + transpose to [B,heads,S,D].
// grid: (B*S, NH+2*NKV=48), block: 128 (one thread per d)
//   hh in [0,32)  : q path (norm + rope + fold 1/sqrt(D))
//   hh in [32,40) : k path (norm + rope)
//   hh in [40,48) : v path (copy)
// ============================================================================
__global__ void __launch_bounds__(128) qkv_post(
    const float* __restrict__ cosb, const float* __restrict__ sinb,
    const float* __restrict__ qw,   const float* __restrict__ kw)
{
    const int bs = blockIdx.x;          // b*S + s
    const int hh = blockIdx.y;          // 0..47
    const int d  = threadIdx.x;         // 0..127
    const int b  = bs / S;
    const int s  = bs - b * S;

    __shared__ float xs[D];
    __shared__ float red[4];

    float x;
    if (hh < NH)            x = g_q[(size_t)bs * (NH * D)  + hh * D + d];
    else if (hh < NH + NKV) x = g_k[(size_t)bs * (NKV * D) + (hh - NH) * D + d];
    else                    x = g_v[(size_t)bs * (NKV * D) + (hh - NH - NKV) * D + d];

    if (hh < NH + NKV) {
        // rmsnorm over D
        float ss = x * x;
#pragma unroll
        for (int o = 16; o; o >>= 1) ss += __shfl_xor_sync(0xffffffffu, ss, o);
        if ((d & 31) == 0) red[d >> 5] = ss;
        __syncthreads();
        const float var = (red[0] + red[1] + red[2] + red[3]) * (1.0f / D);
        const float w = (hh < NH) ? qw[d] : kw[d];
        x = x * rsqrtf(var + EPS) * w;
        xs[d] = x;
        __syncthreads();
        // rope
        const float c  = cosb[(size_t)bs * D + d];
        const float sn = sinb[(size_t)bs * D + d];
        const float part = (d < 64) ? -xs[d + 64] : xs[d - 64];
        x = x * c + part * sn;
    }

    if (hh < NH) {
        g_qt[(((size_t)b * NH + hh) * S + s) * D + d] = x * QSCALE;
    } else if (hh < NH + NKV) {
        g_kt[(((size_t)b * NKV + (hh - NH)) * S + s) * D + d] = x;
    } else {
        g_vt[(((size_t)b * NKV + (hh - NH - NKV)) * S + s) * D + d] = x;
    }
}

// ============================================================================
// Causal flash attention, fp32.
// grid: (S/BM=16, B*NH=64), block 256 threads.
// BM=BN=64, D=128. Dynamic smem: Q(32K)+K(32K)+V(32K)+P(16K)+stats.
// Scale 1/sqrt(D) already folded into Q.
// Output written to g_ao as [B*S, NH*D].
// ============================================================================
#define BM 64
#define BN 64

__global__ void __launch_bounds__(256) flash_attn()
{
    extern __shared__ float sm[];
    float* sQ   = sm;                       // BM*D
    float* sK   = sQ + BM * D;              // BN*D
    float* sV   = sK + BN * D;              // BN*D
    float* sP   = sV + BN * D;              // BM*BN
    float* mrow = sP + BM * BN;             // BM
    float* lrow = mrow + BM;                // BM
    float* srow = lrow + BM;                // BM

    const int bh  = blockIdx.y;             // b*NH + h
    const int b   = bh / NH;
    const int h   = bh - b * NH;
    const int kvh = h / GROUPS;
    const int qt  = blockIdx.x;

    const float* Qb = g_qt + (((size_t)b * NH  + h)   * S + (size_t)qt * BM) * D;
    const float* Kb = g_kt + (((size_t)b * NKV + kvh) * S) * D;
    const float* Vb = g_vt + (((size_t)b * NKV + kvh) * S) * D;

    const int tid = threadIdx.x;
    const int ty = tid >> 4;   // 0..15 -> score rows ty*4..+3
    const int tx = tid & 15;   // 0..15 -> score cols tx*4..+3, O cols tx*8..+7

    // load Q tile (2048 float4)
#pragma unroll
    for (int i = tid; i < BM * D / 4; i += 256)
        ((float4*)sQ)[i] = ((const float4*)Qb)[i];
    if (tid < BM) { mrow[tid] = -1e30f; lrow[tid] = 0.f; }

    float o[4][8];
#pragma unroll
    for (int i = 0; i < 4; i++)
#pragma unroll
        for (int j = 0; j < 8; j++) o[i][j] = 0.f;

    for (int kt = 0; kt <= qt; kt++) {
        __syncthreads();   // protect smem from previous iteration readers
        const float* kp = Kb + (size_t)kt * BN * D;
        const float* vp = Vb + (size_t)kt * BN * D;
#pragma unroll
        for (int i = tid; i < BN * D / 4; i += 256) {
            ((float4*)sK)[i] = ((const float4*)kp)[i];
            ((float4*)sV)[i] = ((const float4*)vp)[i];
        }
        __syncthreads();

        // ---- scores: s[i][j] = q(ty*4+i) . k(tx*4+j) ----
        float sc[4][4];
#pragma unroll
        for (int i = 0; i < 4; i++)
#pragma unroll
            for (int j = 0; j < 4; j++) sc[i][j] = 0.f;

#pragma unroll 4
        for (int dd = 0; dd < D; dd += 4) {
            float4 qv[4], kv[4];
#pragma unroll
            for (int i = 0; i < 4; i++) qv[i] = *(const float4*)&sQ[(ty * 4 + i) * D + dd];
#pragma unroll
            for (int j = 0; j < 4; j++) kv[j] = *(const float4*)&sK[(tx * 4 + j) * D + dd];
#pragma unroll
            for (int i = 0; i < 4; i++)
#pragma unroll
                for (int j = 0; j < 4; j++) {
                    sc[i][j] += qv[i].x * kv[j].x;
                    sc[i][j] += qv[i].y * kv[j].y;
                    sc[i][j] += qv[i].z * kv[j].z;
                    sc[i][j] += qv[i].w * kv[j].w;
                }
        }

        if (kt == qt) {  // causal mask on diagonal tile: col > row
#pragma unroll
            for (int i = 0; i < 4; i++)
#pragma unroll
                for (int j = 0; j < 4; j++)
                    if (tx * 4 + j > ty * 4 + i) sc[i][j] = -1e30f;
        }

        // ---- online softmax ----
        float mloc[4], mold[4], mnew[4], scl[4], rsum[4];
#pragma unroll
        for (int i = 0; i < 4; i++) {
            float v = fmaxf(fmaxf(sc[i][0], sc[i][1]), fmaxf(sc[i][2], sc[i][3]));
#pragma unroll
            for (int off = 8; off; off >>= 1)
                v = fmaxf(v, __shfl_xor_sync(0xffffffffu, v, off));
            mloc[i] = v;
            mold[i] = mrow[ty * 4 + i];
            mnew[i] = fmaxf(mold[i], mloc[i]);
            scl[i]  = __expf(mold[i] - mnew[i]);
            float rs = 0.f;
#pragma unroll
            for (int j = 0; j < 4; j++) {
                sc[i][j] = __expf(sc[i][j] - mnew[i]);
                rs += sc[i][j];
            }
#pragma unroll
            for (int off = 8; off; off >>= 1)
                rs += __shfl_xor_sync(0xffffffffu, rs, off);
            rsum[i] = rs;
        }

        // write P tile
#pragma unroll
        for (int i = 0; i < 4; i++) {
            float* pp = &sP[(ty * 4 + i) * BN + tx * 4];
            pp[0] = sc[i][0]; pp[1] = sc[i][1]; pp[2] = sc[i][2]; pp[3] = sc[i][3];
        }
        if (tx == 0) {
#pragma unroll
            for (int i = 0; i < 4; i++) {
                const int r = ty * 4 + i;
                mrow[r] = mnew[i];
                lrow[r] = lrow[r] * scl[i] + rsum[i];
                srow[r] = scl[i];
            }
        }
        __syncthreads();

        // ---- O update: rescale then O += P * V ----
#pragma unroll
        for (int i = 0; i < 4; i++) {
            const float scale = srow[ty * 4 + i];
#pragma unroll
            for (int j = 0; j < 8; j++) o[i][j] *= scale;
        }

        for (int c = 0; c < BN; c += 4) {
            float4 p4[4];
#pragma unroll
            for (int i = 0; i < 4; i++) p4[i] = *(const float4*)&sP[(ty * 4 + i) * BN + c];
#pragma unroll
            for (int cc = 0; cc < 4; cc++) {
                const float4 v0 = *(const float4*)&sV[(c + cc) * D + tx * 8];
                const float4 v1 = *(const float4*)&sV[(c + cc) * D + tx * 8 + 4];
#pragma unroll
                for (int i = 0; i < 4; i++) {
                    const float* pf = (const float*)&p4[i];
                    const float p = pf[cc];
                    o[i][0] += p * v0.x; o[i][1] += p * v0.y;
                    o[i][2] += p * v0.z; o[i][3] += p * v0.w;
                    o[i][4] += p * v1.x; o[i][5] += p * v1.y;
                    o[i][6] += p * v1.z; o[i][7] += p * v1.w;
                }
            }
        }
    }

    // ---- epilogue: divide by l, write [B*S, NH*D] ----
#pragma unroll
    for (int i = 0; i < 4; i++) {
        const int r = ty * 4 + i;
        const float inv = 1.f / lrow[r];
        const int grow = qt * BM + r;   // sequence position
        float* op = g_ao + ((size_t)(b * S + grow) * NH + h) * D + tx * 8;
        *(float4*)op       = make_float4(o[i][0] * inv, o[i][1] * inv, o[i][2] * inv, o[i][3] * inv);
        *(float4*)(op + 4) = make_float4(o[i][4] * inv, o[i][5] * inv, o[i][6] * inv, o[i][7] * inv);
    }
}

#define FLASH_SMEM ((3 * BM * D + BM * BN + 3 * BM) * (int)sizeof(float))

// ============================================================================
// host launcher
// ============================================================================
extern "C" void kernel_launch(void* const* d_in, const int* in_sizes, int n_in,
                              void* d_out, int out_size)
{
    const float* hidden = (const float*)d_in[0];
    const float* cosb   = (const float*)d_in[1];
    const float* sinb   = (const float*)d_in[2];
    const float* Wq     = (const float*)d_in[3];
    const float* Wk     = (const float*)d_in[4];
    const float* Wv     = (const float*)d_in[5];
    const float* Wo     = (const float*)d_in[6];
    const float* qw     = (const float*)d_in[7];
    const float* kw     = (const float*)d_in[8];
    float* out = (float*)d_out;

    float *pq, *pk, *pv, *pao;
    cudaGetSymbolAddress((void**)&pq,  g_q);
    cudaGetSymbolAddress((void**)&pk,  g_k);
    cudaGetSymbolAddress((void**)&pv,  g_v);
    cudaGetSymbolAddress((void**)&pao, g_ao);

    cudaFuncSetAttribute(flash_attn, cudaFuncAttributeMaxDynamicSharedMemorySize, FLASH_SMEM);

    // QKV projections: C = X * W^T  (NT gemm)
    sgemm_nt<<<dim3((NH  * D) / 128, MSEQ / 128), 256>>>(hidden, Wq, pq, MSEQ, NH  * D, H);
    sgemm_nt<<<dim3((NKV * D) / 128, MSEQ / 128), 256>>>(hidden, Wk, pk, MSEQ, NKV * D, H);
    sgemm_nt<<<dim3((NKV * D) / 128, MSEQ / 128), 256>>>(hidden, Wv, pv, MSEQ, NKV * D, H);

    // norm + rope + transpose
    qkv_post<<<dim3(MSEQ, NH + 2 * NKV), 128>>>(cosb, sinb, qw, kw);

    // causal flash attention
    flash_attn<<<dim3(S / BM, B * NH), 256, FLASH_SMEM>>>();

    // output projection
    sgemm_nt<<<dim3(H / 128, MSEQ / 128), 256>>>(pao, Wo, out, MSEQ, H, NH * D);
}

// round 3
// speedup vs baseline: 1.6330x; 1.6330x over previous
#include <cuda_runtime.h>
#include <cuda_bf16.h>
#include <math.h>
#include <stdint.h>

// ---------------- problem constants ----------------
#define B   2
#define S   1024
#define H   4096
#define NH  32
#define NKV 8
#define D   128
#define GROUPS (NH / NKV)   // 4
#define EPS 1e-6f
#define QSCALE 0.08838834764831845f   // 1/sqrt(128)
#define MSEQ (B * S)        // 2048 rows
#define NQKV ((NH + 2 * NKV) * D)   // 6144

// ---------------- scratch (device globals) ----------------
__device__ __align__(16) __nv_bfloat16 g_xh [MSEQ * H];
__device__ __align__(16) __nv_bfloat16 g_xl [MSEQ * H];
__device__ __align__(16) __nv_bfloat16 g_wh [NQKV * H];
__device__ __align__(16) __nv_bfloat16 g_wl [NQKV * H];
__device__ __align__(16) __nv_bfloat16 g_woh[H * NH * D];
__device__ __align__(16) __nv_bfloat16 g_wol[H * NH * D];
__device__ __align__(16) __nv_bfloat16 g_aoh[MSEQ * NH * D];
__device__ __align__(16) __nv_bfloat16 g_aol[MSEQ * NH * D];
__device__ float g_qkv[MSEQ * NQKV];
__device__ float g_qt [B * NH  * S * D];
__device__ float g_kt [B * NKV * S * D];
__device__ float g_vt [B * NKV * S * D];
__device__ float g_ao [MSEQ * NH * D];

// ============================================================================
// fp32 -> bf16 hi/lo split
// ============================================================================
__global__ void __launch_bounds__(256) split_fp32(
    const float* __restrict__ src, __nv_bfloat16* __restrict__ hi,
    __nv_bfloat16* __restrict__ lo, int n4)
{
    int i = blockIdx.x * 256 + threadIdx.x;
    if (i >= n4) return;
    float4 x = ((const float4*)src)[i];
    __nv_bfloat16 h0 = __float2bfloat16(x.x);
    __nv_bfloat16 h1 = __float2bfloat16(x.y);
    __nv_bfloat16 h2 = __float2bfloat16(x.z);
    __nv_bfloat16 h3 = __float2bfloat16(x.w);
    __nv_bfloat16 l0 = __float2bfloat16(x.x - __bfloat162float(h0));
    __nv_bfloat16 l1 = __float2bfloat16(x.y - __bfloat162float(h1));
    __nv_bfloat16 l2 = __float2bfloat16(x.z - __bfloat162float(h2));
    __nv_bfloat16 l3 = __float2bfloat16(x.w - __bfloat162float(h3));
    __nv_bfloat162 hv0; hv0.x = h0; hv0.y = h1;
    __nv_bfloat162 hv1; hv1.x = h2; hv1.y = h3;
    __nv_bfloat162 lv0; lv0.x = l0; lv0.y = l1;
    __nv_bfloat162 lv1; lv1.x = l2; lv1.y = l3;
    ((__nv_bfloat162*)hi)[2 * i]     = hv0;
    ((__nv_bfloat162*)hi)[2 * i + 1] = hv1;
    ((__nv_bfloat162*)lo)[2 * i]     = lv0;
    ((__nv_bfloat162*)lo)[2 * i + 1] = lv1;
}

// ============================================================================
// mma.sync split-bf16 NT GEMM: C[M,N] = (Ah+Al)(Bh+Bl)^T  (hh+hl+lh terms)
// Block tile 128x128x32, 8 warps (2x4), warp tile 64x32.
// 3-stage cp.async pipeline. Smem rows padded to 80B for conflict-free ldmatrix.
// ============================================================================
#define ROWB 80                        // bytes per 32-bf16 row (padded)
#define MATB (128 * ROWB)              // 10240 per matrix tile
#define STGB (4 * MATB)                // Ah|Al|Bh|Bl = 40960 per stage
#define GSMEM (3 * STGB)               // 122880

__device__ __forceinline__ void cp16(uint32_t dst, const void* src) {
    asm volatile("cp.async.cg.shared.global [%0], [%1], 16;" :: "r"(dst), "l"(src) : "memory");
}
__device__ __forceinline__ void ldsm4(uint32_t addr, uint32_t& r0, uint32_t& r1,
                                      uint32_t& r2, uint32_t& r3) {
    asm volatile("ldmatrix.sync.aligned.m8n8.x4.shared.b16 {%0,%1,%2,%3}, [%4];"
        : "=r"(r0), "=r"(r1), "=r"(r2), "=r"(r3) : "r"(addr));
}
__device__ __forceinline__ void mma16816(float* c, const uint32_t* a,
                                         uint32_t b0, uint32_t b1) {
    asm volatile("mma.sync.aligned.m16n8k16.row.col.f32.bf16.bf16.f32 "
        "{%0,%1,%2,%3}, {%4,%5,%6,%7}, {%8,%9}, {%0,%1,%2,%3};"
        : "+f"(c[0]), "+f"(c[1]), "+f"(c[2]), "+f"(c[3])
        : "r"(a[0]), "r"(a[1]), "r"(a[2]), "r"(a[3]), "r"(b0), "r"(b1));
}

__global__ void __launch_bounds__(256) gemm_mma(
    const __nv_bfloat16* __restrict__ Ah, const __nv_bfloat16* __restrict__ Al,
    const __nv_bfloat16* __restrict__ Bh, const __nv_bfloat16* __restrict__ Bl,
    float* __restrict__ C, int M, int N, int K)
{
    extern __shared__ __align__(128) char smem[];
    const uint32_t sbase = (uint32_t)__cvta_generic_to_shared(smem);
    const int tid  = threadIdx.x;
    const int lane = tid & 31;
    const int wid  = tid >> 5;
    const int warp_m = wid >> 2;   // 0..1
    const int warp_n = wid & 3;    // 0..3
    const int m0 = blockIdx.y * 128;
    const int n0 = blockIdx.x * 128;
    const int KT = K >> 5;         // K / 32

    float acc[4][4][4];            // [mi][nj][4]
#pragma unroll
    for (int i = 0; i < 4; i++)
#pragma unroll
        for (int j = 0; j < 4; j++)
#pragma unroll
            for (int q = 0; q < 4; q++) acc[i][j][q] = 0.f;

    // --- stage fill: 2048 x 16B chunks, 8 per thread, matrix = i>>1 (compile-time)
    auto fill = [&](int s, int kt) {
        const uint32_t st = sbase + s * STGB;
#pragma unroll
        for (int i = 0; i < 8; i++) {
            const int v = ((i & 1) << 8) + tid;    // 0..511 within matrix
            const int r = v >> 2, c = v & 3;
            const __nv_bfloat16* gb =
                (i < 2) ? Ah : (i < 4) ? Al : (i < 6) ? Bh : Bl;
            const int grow = ((i < 4) ? m0 : n0) + r;
            cp16(st + (i >> 1) * MATB + r * ROWB + c * 16,
                 gb + (size_t)grow * K + (size_t)kt * 32 + c * 8);
        }
        asm volatile("cp.async.commit_group;" ::: "memory");
    };

    fill(0, 0); fill(1, 1); fill(2, 2);

    // per-lane ldmatrix base addresses (row = lane%16, col-half = lane/16)
    const uint32_t aOff = (uint32_t)((warp_m * 64 + (lane & 15)) * ROWB + ((lane >> 4) << 4));
    const uint32_t bOff = (uint32_t)(2 * MATB + (warp_n * 32 + (lane & 15)) * ROWB + ((lane >> 4) << 4));

    for (int kt = 0; kt < KT; kt++) {
        const int s = kt % 3;
        if (kt < KT - 2)       asm volatile("cp.async.wait_group 2;" ::: "memory");
        else if (kt == KT - 2) asm volatile("cp.async.wait_group 1;" ::: "memory");
        else                   asm volatile("cp.async.wait_group 0;" ::: "memory");
        __syncthreads();

        const uint32_t st = sbase + s * STGB;
#pragma unroll
        for (int k16 = 0; k16 < 2; k16++) {
            const uint32_t ko = k16 * 32;
            uint32_t a[4][4], bh[2][4], bl[2][4];
#pragma unroll
            for (int mi = 0; mi < 4; mi++)          // Ah frags
                ldsm4(st + aOff + mi * (16 * ROWB) + ko,
                      a[mi][0], a[mi][1], a[mi][2], a[mi][3]);
#pragma unroll
            for (int ni = 0; ni < 2; ni++) {        // Bh, Bl frags
                ldsm4(st + bOff + ni * (16 * ROWB) + ko,
                      bh[ni][0], bh[ni][1], bh[ni][2], bh[ni][3]);
                ldsm4(st + bOff + MATB + ni * (16 * ROWB) + ko,
                      bl[ni][0], bl[ni][1], bl[ni][2], bl[ni][3]);
            }
            // term Ah*Bh and Ah*Bl
#pragma unroll
            for (int mi = 0; mi < 4; mi++)
#pragma unroll
                for (int ni = 0; ni < 2; ni++) {
                    mma16816(acc[mi][ni * 2],     a[mi], bh[ni][0], bh[ni][2]);
                    mma16816(acc[mi][ni * 2 + 1], a[mi], bh[ni][1], bh[ni][3]);
                    mma16816(acc[mi][ni * 2],     a[mi], bl[ni][0], bl[ni][2]);
                    mma16816(acc[mi][ni * 2 + 1], a[mi], bl[ni][1], bl[ni][3]);
                }
            // term Al*Bh (reuse a regs)
#pragma unroll
            for (int mi = 0; mi < 4; mi++)
                ldsm4(st + MATB + aOff + mi * (16 * ROWB) + ko,
                      a[mi][0], a[mi][1], a[mi][2], a[mi][3]);
#pragma unroll
            for (int mi = 0; mi < 4; mi++)
#pragma unroll
                for (int ni = 0; ni < 2; ni++) {
                    mma16816(acc[mi][ni * 2],     a[mi], bh[ni][0], bh[ni][2]);
                    mma16816(acc[mi][ni * 2 + 1], a[mi], bh[ni][1], bh[ni][3]);
                }
        }
        __syncthreads();
        if (kt + 3 < KT) fill(s, kt + 3);
    }

    // ---- epilogue ----
#pragma unroll
    for (int mi = 0; mi < 4; mi++) {
        const int row = m0 + warp_m * 64 + mi * 16 + (lane >> 2);
#pragma unroll
        for (int nj = 0; nj < 4; nj++) {
            const int col = n0 + warp_n * 32 + (nj >> 1) * 16 + (nj & 1) * 8 + (lane & 3) * 2;
            float* cp0 = C + (size_t)row * N + col;
            float* cp1 = C + (size_t)(row + 8) * N + col;
            *(float2*)cp0 = make_float2(acc[mi][nj][0], acc[mi][nj][1]);
            *(float2*)cp1 = make_float2(acc[mi][nj][2], acc[mi][nj][3]);
        }
    }
}

// ============================================================================
// Per-head RMSNorm + RoPE + transpose (unchanged)
// ============================================================================
__global__ void __launch_bounds__(128) qkv_post(
    const float* __restrict__ cosb, const float* __restrict__ sinb,
    const float* __restrict__ qw,   const float* __restrict__ kw)
{
    const int bs = blockIdx.x;
    const int hh = blockIdx.y;
    const int d  = threadIdx.x;
    const int b  = bs / S;
    const int s  = bs - b * S;

    __shared__ float xs[D];
    __shared__ float red[4];

    float x = g_qkv[(size_t)bs * NQKV + hh * D + d];

    if (hh < NH + NKV) {
        float ss = x * x;
#pragma unroll
        for (int o = 16; o; o >>= 1) ss += __shfl_xor_sync(0xffffffffu, ss, o);
        if ((d & 31) == 0) red[d >> 5] = ss;
        __syncthreads();
        const float var = (red[0] + red[1] + red[2] + red[3]) * (1.0f / D);
        const float w = (hh < NH) ? qw[d] : kw[d];
        x = x * rsqrtf(var + EPS) * w;
        xs[d] = x;
        __syncthreads();
        const float c  = cosb[(size_t)bs * D + d];
        const float sn = sinb[(size_t)bs * D + d];
        const float part = (d < 64) ? -xs[d + 64] : xs[d - 64];
        x = x * c + part * sn;
    }

    if (hh < NH) {
        g_qt[(((size_t)b * NH + hh) * S + s) * D + d] = x * QSCALE;
    } else if (hh < NH + NKV) {
        g_kt[(((size_t)b * NKV + (hh - NH)) * S + s) * D + d] = x;
    } else {
        g_vt[(((size_t)b * NKV + (hh - NH - NKV)) * S + s) * D + d] = x;
    }
}

// ============================================================================
// Causal flash attention, fp32 (unchanged from R1 pass)
// ============================================================================
#define BM 64
#define BN 64

__global__ void __launch_bounds__(256) flash_attn()
{
    extern __shared__ float sm[];
    float* sQ   = sm;
    float* sK   = sQ + BM * D;
    float* sV   = sK + BN * D;
    float* sP   = sV + BN * D;
    float* mrow = sP + BM * BN;
    float* lrow = mrow + BM;
    float* srow = lrow + BM;

    const int bh  = blockIdx.y;
    const int b   = bh / NH;
    const int h   = bh - b * NH;
    const int kvh = h / GROUPS;
    const int qt  = blockIdx.x;

    const float* Qb = g_qt + (((size_t)b * NH  + h)   * S + (size_t)qt * BM) * D;
    const float* Kb = g_kt + (((size_t)b * NKV + kvh) * S) * D;
    const float* Vb = g_vt + (((size_t)b * NKV + kvh) * S) * D;

    const int tid = threadIdx.x;
    const int ty = tid >> 4;
    const int tx = tid & 15;

#pragma unroll
    for (int i = tid; i < BM * D / 4; i += 256)
        ((float4*)sQ)[i] = ((const float4*)Qb)[i];
    if (tid < BM) { mrow[tid] = -1e30f; lrow[tid] = 0.f; }

    float o[4][8];
#pragma unroll
    for (int i = 0; i < 4; i++)
#pragma unroll
        for (int j = 0; j < 8; j++) o[i][j] = 0.f;

    for (int kt = 0; kt <= qt; kt++) {
        __syncthreads();
        const float* kp = Kb + (size_t)kt * BN * D;
        const float* vp = Vb + (size_t)kt * BN * D;
#pragma unroll
        for (int i = tid; i < BN * D / 4; i += 256) {
            ((float4*)sK)[i] = ((const float4*)kp)[i];
            ((float4*)sV)[i] = ((const float4*)vp)[i];
        }
        __syncthreads();

        float sc[4][4];
#pragma unroll
        for (int i = 0; i < 4; i++)
#pragma unroll
            for (int j = 0; j < 4; j++) sc[i][j] = 0.f;

#pragma unroll 4
        for (int dd = 0; dd < D; dd += 4) {
            float4 qv[4], kv[4];
#pragma unroll
            for (int i = 0; i < 4; i++) qv[i] = *(const float4*)&sQ[(ty * 4 + i) * D + dd];
#pragma unroll
            for (int j = 0; j < 4; j++) kv[j] = *(const float4*)&sK[(tx * 4 + j) * D + dd];
#pragma unroll
            for (int i = 0; i < 4; i++)
#pragma unroll
                for (int j = 0; j < 4; j++) {
                    sc[i][j] += qv[i].x * kv[j].x;
                    sc[i][j] += qv[i].y * kv[j].y;
                    sc[i][j] += qv[i].z * kv[j].z;
                    sc[i][j] += qv[i].w * kv[j].w;
                }
        }

        if (kt == qt) {
#pragma unroll
            for (int i = 0; i < 4; i++)
#pragma unroll
                for (int j = 0; j < 4; j++)
                    if (tx * 4 + j > ty * 4 + i) sc[i][j] = -1e30f;
        }

        float mloc[4], mold[4], mnew[4], scl[4], rsum[4];
#pragma unroll
        for (int i = 0; i < 4; i++) {
            float v = fmaxf(fmaxf(sc[i][0], sc[i][1]), fmaxf(sc[i][2], sc[i][3]));
#pragma unroll
            for (int off = 8; off; off >>= 1)
                v = fmaxf(v, __shfl_xor_sync(0xffffffffu, v, off));
            mloc[i] = v;
            mold[i] = mrow[ty * 4 + i];
            mnew[i] = fmaxf(mold[i], mloc[i]);
            scl[i]  = __expf(mold[i] - mnew[i]);
            float rs = 0.f;
#pragma unroll
            for (int j = 0; j < 4; j++) {
                sc[i][j] = __expf(sc[i][j] - mnew[i]);
                rs += sc[i][j];
            }
#pragma unroll
            for (int off = 8; off; off >>= 1)
                rs += __shfl_xor_sync(0xffffffffu, rs, off);
            rsum[i] = rs;
        }

#pragma unroll
        for (int i = 0; i < 4; i++) {
            float* pp = &sP[(ty * 4 + i) * BN + tx * 4];
            pp[0] = sc[i][0]; pp[1] = sc[i][1]; pp[2] = sc[i][2]; pp[3] = sc[i][3];
        }
        if (tx == 0) {
#pragma unroll
            for (int i = 0; i < 4; i++) {
                const int r = ty * 4 + i;
                mrow[r] = mnew[i];
                lrow[r] = lrow[r] * scl[i] + rsum[i];
                srow[r] = scl[i];
            }
        }
        __syncthreads();

#pragma unroll
        for (int i = 0; i < 4; i++) {
            const float scale = srow[ty * 4 + i];
#pragma unroll
            for (int j = 0; j < 8; j++) o[i][j] *= scale;
        }

        for (int c = 0; c < BN; c += 4) {
            float4 p4[4];
#pragma unroll
            for (int i = 0; i < 4; i++) p4[i] = *(const float4*)&sP[(ty * 4 + i) * BN + c];
#pragma unroll
            for (int cc = 0; cc < 4; cc++) {
                const float4 v0 = *(const float4*)&sV[(c + cc) * D + tx * 8];
                const float4 v1 = *(const float4*)&sV[(c + cc) * D + tx * 8 + 4];
#pragma unroll
                for (int i = 0; i < 4; i++) {
                    const float* pf = (const float*)&p4[i];
                    const float p = pf[cc];
                    o[i][0] += p * v0.x; o[i][1] += p * v0.y;
                    o[i][2] += p * v0.z; o[i][3] += p * v0.w;
                    o[i][4] += p * v1.x; o[i][5] += p * v1.y;
                    o[i][6] += p * v1.z; o[i][7] += p * v1.w;
                }
            }
        }
    }

#pragma unroll
    for (int i = 0; i < 4; i++) {
        const int r = ty * 4 + i;
        const float inv = 1.f / lrow[r];
        const int grow = qt * BM + r;
        float* op = g_ao + ((size_t)(b * S + grow) * NH + h) * D + tx * 8;
        *(float4*)op       = make_float4(o[i][0] * inv, o[i][1] * inv, o[i][2] * inv, o[i][3] * inv);
        *(float4*)(op + 4) = make_float4(o[i][4] * inv, o[i][5] * inv, o[i][6] * inv, o[i][7] * inv);
    }
}

#define FLASH_SMEM ((3 * BM * D + BM * BN + 3 * BM) * (int)sizeof(float))

// ============================================================================
// host launcher
// ============================================================================
extern "C" void kernel_launch(void* const* d_in, const int* in_sizes, int n_in,
                              void* d_out, int out_size)
{
    const float* hidden = (const float*)d_in[0];
    const float* cosb   = (const float*)d_in[1];
    const float* sinb   = (const float*)d_in[2];
    const float* Wq     = (const float*)d_in[3];
    const float* Wk     = (const float*)d_in[4];
    const float* Wv     = (const float*)d_in[5];
    const float* Wo     = (const float*)d_in[6];
    const float* qw     = (const float*)d_in[7];
    const float* kw     = (const float*)d_in[8];
    float* out = (float*)d_out;

    __nv_bfloat16 *xh, *xl, *wh, *wl, *woh, *wol, *aoh, *aol;
    float *qkv, *ao;
    cudaGetSymbolAddress((void**)&xh,  g_xh);
    cudaGetSymbolAddress((void**)&xl,  g_xl);
    cudaGetSymbolAddress((void**)&wh,  g_wh);
    cudaGetSymbolAddress((void**)&wl,  g_wl);
    cudaGetSymbolAddress((void**)&woh, g_woh);
    cudaGetSymbolAddress((void**)&wol, g_wol);
    cudaGetSymbolAddress((void**)&aoh, g_aoh);
    cudaGetSymbolAddress((void**)&aol, g_aol);
    cudaGetSymbolAddress((void**)&qkv, g_qkv);
    cudaGetSymbolAddress((void**)&ao,  g_ao);

    cudaFuncSetAttribute(gemm_mma, cudaFuncAttributeMaxDynamicSharedMemorySize, GSMEM);
    cudaFuncSetAttribute(flash_attn, cudaFuncAttributeMaxDynamicSharedMemorySize, FLASH_SMEM);

    // fp32 -> bf16 hi/lo conversions
    {
        int n4;
        n4 = MSEQ * H / 4;
        split_fp32<<<(n4 + 255) / 256, 256>>>(hidden, xh, xl, n4);
        n4 = NH * D * H / 4;
        split_fp32<<<(n4 + 255) / 256, 256>>>(Wq, wh, wl, n4);
        n4 = NKV * D * H / 4;
        split_fp32<<<(n4 + 255) / 256, 256>>>(Wk, wh + (size_t)NH * D * H, wl + (size_t)NH * D * H, n4);
        split_fp32<<<(n4 + 255) / 256, 256>>>(Wv, wh + (size_t)(NH + NKV) * D * H, wl + (size_t)(NH + NKV) * D * H, n4);
        n4 = H * NH * D / 4;
        split_fp32<<<(n4 + 255) / 256, 256>>>(Wo, woh, wol, n4);
    }

    // fused QKV projection: [2048, 6144] = X[2048,4096] * Wqkv[6144,4096]^T
    gemm_mma<<<dim3(NQKV / 128, MSEQ / 128), 256, GSMEM>>>(
        xh, xl, wh, wl, qkv, MSEQ, NQKV, H);

    // norm + rope + transpose
    qkv_post<<<dim3(MSEQ, NH + 2 * NKV), 128>>>(cosb, sinb, qw, kw);

    // causal flash attention
    flash_attn<<<dim3(S / BM, B * NH), 256, FLASH_SMEM>>>();

    // attention out -> bf16 hi/lo
    {
        int n4 = MSEQ * NH * D / 4;
        split_fp32<<<(n4 + 255) / 256, 256>>>(ao, aoh, aol, n4);
    }

    // output projection: [2048, 4096] = AO[2048,4096] * Wo[4096,4096]^T
    gemm_mma<<<dim3(H / 128, MSEQ / 128), 256, GSMEM>>>(
        aoh, aol, woh, wol, out, MSEQ, H, NH * D);
}

// round 4
// speedup vs baseline: 2.5833x; 1.5820x over previous
#include <cuda_runtime.h>
#include <cuda_bf16.h>
#include <math.h>
#include <stdint.h>

// ---------------- problem constants ----------------
#define B   2
#define S   1024
#define H   4096
#define NH  32
#define NKV 8
#define D   128
#define GROUPS (NH / NKV)   // 4
#define EPS 1e-6f
#define QSCALE 0.08838834764831845f   // 1/sqrt(128)
#define MSEQ (B * S)        // 2048 rows
#define NQKV ((NH + 2 * NKV) * D)   // 6144
#define LOG2E 1.4426950408889634f

// ---------------- scratch (device globals) ----------------
__device__ __align__(16) __nv_bfloat16 g_xh [MSEQ * H];
__device__ __align__(16) __nv_bfloat16 g_xl [MSEQ * H];
__device__ __align__(16) __nv_bfloat16 g_wh [NQKV * H];
__device__ __align__(16) __nv_bfloat16 g_wl [NQKV * H];
__device__ __align__(16) __nv_bfloat16 g_woh[H * NH * D];
__device__ __align__(16) __nv_bfloat16 g_wol[H * NH * D];
__device__ __align__(16) __nv_bfloat16 g_aoh[MSEQ * NH * D];
__device__ __align__(16) __nv_bfloat16 g_aol[MSEQ * NH * D];
__device__ float g_qkv[MSEQ * NQKV];
// flash inputs, bf16 hi/lo. q,k row-major [B,heads,S,D]; v transposed [B,NKV,D,S]
__device__ __align__(16) __nv_bfloat16 g_qh [B * NH  * S * D];
__device__ __align__(16) __nv_bfloat16 g_ql [B * NH  * S * D];
__device__ __align__(16) __nv_bfloat16 g_kh [B * NKV * S * D];
__device__ __align__(16) __nv_bfloat16 g_kl [B * NKV * S * D];
__device__ __align__(16) __nv_bfloat16 g_vth[B * NKV * D * S];
__device__ __align__(16) __nv_bfloat16 g_vtl[B * NKV * D * S];

// ---------------- small helpers ----------------
__device__ __forceinline__ void cp16(uint32_t dst, const void* src) {
    asm volatile("cp.async.cg.shared.global [%0], [%1], 16;" :: "r"(dst), "l"(src) : "memory");
}
__device__ __forceinline__ void ldsm4(uint32_t addr, uint32_t& r0, uint32_t& r1,
                                      uint32_t& r2, uint32_t& r3) {
    asm volatile("ldmatrix.sync.aligned.m8n8.x4.shared.b16 {%0,%1,%2,%3}, [%4];"
        : "=r"(r0), "=r"(r1), "=r"(r2), "=r"(r3) : "r"(addr));
}
__device__ __forceinline__ void mma16816(float* c, const uint32_t* a,
                                         uint32_t b0, uint32_t b1) {
    asm volatile("mma.sync.aligned.m16n8k16.row.col.f32.bf16.bf16.f32 "
        "{%0,%1,%2,%3}, {%4,%5,%6,%7}, {%8,%9}, {%0,%1,%2,%3};"
        : "+f"(c[0]), "+f"(c[1]), "+f"(c[2]), "+f"(c[3])
        : "r"(a[0]), "r"(a[1]), "r"(a[2]), "r"(a[3]), "r"(b0), "r"(b1));
}
__device__ __forceinline__ void split1(float v, __nv_bfloat16& h, __nv_bfloat16& l) {
    h = __float2bfloat16(v);
    l = __float2bfloat16(v - __bfloat162float(h));
}
__device__ __forceinline__ void split2(float a, float b, uint32_t& hi, uint32_t& lo) {
    __nv_bfloat162 hv, lv;
    split1(a, hv.x, lv.x);
    split1(b, hv.y, lv.y);
    hi = *(uint32_t*)&hv;
    lo = *(uint32_t*)&lv;
}

// ============================================================================
// fp32 -> bf16 hi/lo split
// ============================================================================
__global__ void __launch_bounds__(256) split_fp32(
    const float* __restrict__ src, __nv_bfloat16* __restrict__ hi,
    __nv_bfloat16* __restrict__ lo, int n4)
{
    int i = blockIdx.x * 256 + threadIdx.x;
    if (i >= n4) return;
    float4 x = ((const float4*)src)[i];
    __nv_bfloat162 hv0, hv1, lv0, lv1;
    split1(x.x, hv0.x, lv0.x);
    split1(x.y, hv0.y, lv0.y);
    split1(x.z, hv1.x, lv1.x);
    split1(x.w, hv1.y, lv1.y);
    ((__nv_bfloat162*)hi)[2 * i]     = hv0;
    ((__nv_bfloat162*)hi)[2 * i + 1] = hv1;
    ((__nv_bfloat162*)lo)[2 * i]     = lv0;
    ((__nv_bfloat162*)lo)[2 * i + 1] = lv1;
}

// ============================================================================
// mma.sync split-bf16 NT GEMM: C[M,N] = (Ah+Al)(Bh+Bl)^T  (hh+hl+lh terms)
// Block tile 128x128x32, 8 warps (2x4), warp tile 64x32.
// 4-stage cp.async ring, ONE __syncthreads per K-tile.
// ============================================================================
#define ROWB 80                        // bytes per 32-bf16 row (padded)
#define MATB (128 * ROWB)              // 10240 per matrix tile
#define STGB (4 * MATB)                // Ah|Al|Bh|Bl = 40960 per stage
#define GSMEM (4 * STGB)               // 163840

__global__ void __launch_bounds__(256) gemm_mma(
    const __nv_bfloat16* __restrict__ Ah, const __nv_bfloat16* __restrict__ Al,
    const __nv_bfloat16* __restrict__ Bh, const __nv_bfloat16* __restrict__ Bl,
    float* __restrict__ C, int M, int N, int K)
{
    extern __shared__ __align__(128) char smem[];
    const uint32_t sbase = (uint32_t)__cvta_generic_to_shared(smem);
    const int tid  = threadIdx.x;
    const int lane = tid & 31;
    const int wid  = tid >> 5;
    const int warp_m = wid >> 2;   // 0..1
    const int warp_n = wid & 3;    // 0..3
    const int m0 = blockIdx.y * 128;
    const int n0 = blockIdx.x * 128;
    const int KT = K >> 5;         // K / 32

    float acc[4][4][4];
#pragma unroll
    for (int i = 0; i < 4; i++)
#pragma unroll
        for (int j = 0; j < 4; j++)
#pragma unroll
            for (int q = 0; q < 4; q++) acc[i][j][q] = 0.f;

    auto fill = [&](int s, int kt) {
        const uint32_t st = sbase + s * STGB;
#pragma unroll
        for (int i = 0; i < 8; i++) {
            const int v = ((i & 1) << 8) + tid;    // 0..511 within matrix
            const int r = v >> 2, c = v & 3;
            const __nv_bfloat16* gb =
                (i < 2) ? Ah : (i < 4) ? Al : (i < 6) ? Bh : Bl;
            const int grow = ((i < 4) ? m0 : n0) + r;
            cp16(st + (i >> 1) * MATB + r * ROWB + c * 16,
                 gb + (size_t)grow * K + (size_t)kt * 32 + c * 8);
        }
        asm volatile("cp.async.commit_group;" ::: "memory");
    };

    fill(0, 0); fill(1, 1); fill(2, 2); fill(3, 3);

    const uint32_t aOff = (uint32_t)((warp_m * 64 + (lane & 15)) * ROWB + ((lane >> 4) << 4));
    const uint32_t bOff = (uint32_t)(2 * MATB + (warp_n * 32 + (lane & 15)) * ROWB + ((lane >> 4) << 4));

    for (int kt = 0; kt < KT; kt++) {
        asm volatile("cp.async.wait_group 2;" ::: "memory");
        __syncthreads();     // all warps done with iter kt-1 -> slot (kt-1)&3 free
        if (kt >= 1) {
            if (kt + 3 < KT) fill((kt + 3) & 3, kt + 3);
            else asm volatile("cp.async.commit_group;" ::: "memory");  // keep group count
        }

        const uint32_t st = sbase + (kt & 3) * STGB;
#pragma unroll
        for (int k16 = 0; k16 < 2; k16++) {
            const uint32_t ko = k16 * 32;
            uint32_t a[4][4], bh[2][4], bl[2][4];
#pragma unroll
            for (int mi = 0; mi < 4; mi++)
                ldsm4(st + aOff + mi * (16 * ROWB) + ko,
                      a[mi][0], a[mi][1], a[mi][2], a[mi][3]);
#pragma unroll
            for (int ni = 0; ni < 2; ni++) {
                ldsm4(st + bOff + ni * (16 * ROWB) + ko,
                      bh[ni][0], bh[ni][1], bh[ni][2], bh[ni][3]);
                ldsm4(st + bOff + MATB + ni * (16 * ROWB) + ko,
                      bl[ni][0], bl[ni][1], bl[ni][2], bl[ni][3]);
            }
#pragma unroll
            for (int mi = 0; mi < 4; mi++)
#pragma unroll
                for (int ni = 0; ni < 2; ni++) {
                    mma16816(acc[mi][ni * 2],     a[mi], bh[ni][0], bh[ni][2]);
                    mma16816(acc[mi][ni * 2 + 1], a[mi], bh[ni][1], bh[ni][3]);
                    mma16816(acc[mi][ni * 2],     a[mi], bl[ni][0], bl[ni][2]);
                    mma16816(acc[mi][ni * 2 + 1], a[mi], bl[ni][1], bl[ni][3]);
                }
#pragma unroll
            for (int mi = 0; mi < 4; mi++)
                ldsm4(st + MATB + aOff + mi * (16 * ROWB) + ko,
                      a[mi][0], a[mi][1], a[mi][2], a[mi][3]);
#pragma unroll
            for (int mi = 0; mi < 4; mi++)
#pragma unroll
                for (int ni = 0; ni < 2; ni++) {
                    mma16816(acc[mi][ni * 2],     a[mi], bh[ni][0], bh[ni][2]);
                    mma16816(acc[mi][ni * 2 + 1], a[mi], bh[ni][1], bh[ni][3]);
                }
        }
    }

#pragma unroll
    for (int mi = 0; mi < 4; mi++) {
        const int row = m0 + warp_m * 64 + mi * 16 + (lane >> 2);
#pragma unroll
        for (int nj = 0; nj < 4; nj++) {
            const int col = n0 + warp_n * 32 + (nj >> 1) * 16 + (nj & 1) * 8 + (lane & 3) * 2;
            float* cp0 = C + (size_t)row * N + col;
            float* cp1 = C + (size_t)(row + 8) * N + col;
            *(float2*)cp0 = make_float2(acc[mi][nj][0], acc[mi][nj][1]);
            *(float2*)cp1 = make_float2(acc[mi][nj][2], acc[mi][nj][3]);
        }
    }
}

// ============================================================================
// Per-head RMSNorm + RoPE; writes bf16 hi/lo. q,k row-major; v transposed.
// grid: (B*S, 48), block 128.
// ============================================================================
__global__ void __launch_bounds__(128) qkv_post(
    const float* __restrict__ cosb, const float* __restrict__ sinb,
    const float* __restrict__ qw,   const float* __restrict__ kw)
{
    const int bs = blockIdx.x;
    const int hh = blockIdx.y;
    const int d  = threadIdx.x;
    const int b  = bs / S;
    const int s  = bs - b * S;

    __shared__ float xs[D];
    __shared__ float red[4];

    float x = g_qkv[(size_t)bs * NQKV + hh * D + d];

    if (hh < NH + NKV) {
        float ss = x * x;
#pragma unroll
        for (int o = 16; o; o >>= 1) ss += __shfl_xor_sync(0xffffffffu, ss, o);
        if ((d & 31) == 0) red[d >> 5] = ss;
        __syncthreads();
        const float var = (red[0] + red[1] + red[2] + red[3]) * (1.0f / D);
        const float w = (hh < NH) ? qw[d] : kw[d];
        x = x * rsqrtf(var + EPS) * w;
        xs[d] = x;
        __syncthreads();
        const float c  = cosb[(size_t)bs * D + d];
        const float sn = sinb[(size_t)bs * D + d];
        const float part = (d < 64) ? -xs[d + 64] : xs[d - 64];
        x = x * c + part * sn;
    }

    __nv_bfloat16 hi, lo;
    if (hh < NH) {
        split1(x * QSCALE, hi, lo);
        const size_t idx = (((size_t)b * NH + hh) * S + s) * D + d;
        g_qh[idx] = hi; g_ql[idx] = lo;
    } else if (hh < NH + NKV) {
        split1(x, hi, lo);
        const size_t idx = (((size_t)b * NKV + (hh - NH)) * S + s) * D + d;
        g_kh[idx] = hi; g_kl[idx] = lo;
    } else {
        split1(x, hi, lo);
        const size_t idx = (((size_t)b * NKV + (hh - NH - NKV)) * D + d) * S + s;
        g_vth[idx] = hi; g_vtl[idx] = lo;
    }
}

// ============================================================================
// Causal flash attention on mma.sync, split-bf16 3-term for QK^T and PV.
// BM=BN=64, 4 warps (128 threads), warp owns 16 rows. 2-stage KV pipeline.
// ============================================================================
#define QROW 272                       // 128 bf16 + 8 pad
#define VROW 144                       // 64 bf16 + 8 pad
#define SQH_OFF 0
#define SQL_OFF (64 * QROW)            // 17408
#define SK0_OFF (2 * 64 * QROW)        // 34816
#define KHL_OFF (64 * QROW)            // Kl within stage
#define VH_OFF  (2 * 64 * QROW)        // Vth within stage: 34816
#define VL_OFF  (VH_OFF + 128 * VROW)  // 53248
#define KSTG    (VL_OFF + 128 * VROW)  // 71680
#define FSMEM   (SK0_OFF + 2 * KSTG)   // 178176

__global__ void __launch_bounds__(128) flash_mma()
{
    extern __shared__ __align__(128) char fsm[];
    const uint32_t sb = (uint32_t)__cvta_generic_to_shared(fsm);
    const int tid = threadIdx.x, lane = tid & 31, wid = tid >> 5;
    const int qt = blockIdx.x, bh = blockIdx.y;
    const int b = bh / NH, h = bh - b * NH;
    const int kvh = h / GROUPS;

    const __nv_bfloat16* Qhp = g_qh + (((size_t)b * NH + h) * S + (size_t)qt * 64) * D;
    const __nv_bfloat16* Qlp = g_ql + (((size_t)b * NH + h) * S + (size_t)qt * 64) * D;
    const __nv_bfloat16* Khp = g_kh + ((size_t)b * NKV + kvh) * S * D;
    const __nv_bfloat16* Klp = g_kl + ((size_t)b * NKV + kvh) * S * D;
    const __nv_bfloat16* Vhp = g_vth + ((size_t)b * NKV + kvh) * D * S;
    const __nv_bfloat16* Vlp = g_vtl + ((size_t)b * NKV + kvh) * D * S;

    // Q tiles (loaded once): 64 rows x 128 bf16, hi+lo
#pragma unroll
    for (int i = tid; i < 1024; i += 128) {
        const int r = i >> 4, c = i & 15;
        cp16(sb + SQH_OFF + r * QROW + c * 16, Qhp + r * D + c * 8);
        cp16(sb + SQL_OFF + r * QROW + c * 16, Qlp + r * D + c * 8);
    }

    auto fillkv = [&](int slot, int kt) {
        const uint32_t st = sb + SK0_OFF + slot * KSTG;
        const __nv_bfloat16* kh_ = Khp + (size_t)kt * 64 * D;
        const __nv_bfloat16* kl_ = Klp + (size_t)kt * 64 * D;
#pragma unroll
        for (int i = tid; i < 1024; i += 128) {
            const int r = i >> 4, c = i & 15;
            cp16(st + r * QROW + c * 16,           kh_ + r * D + c * 8);
            cp16(st + KHL_OFF + r * QROW + c * 16, kl_ + r * D + c * 8);
        }
        const __nv_bfloat16* vh_ = Vhp + (size_t)kt * 64;
        const __nv_bfloat16* vl_ = Vlp + (size_t)kt * 64;
#pragma unroll
        for (int i = tid; i < 1024; i += 128) {
            const int r = i >> 3, c = i & 7;
            cp16(st + VH_OFF + r * VROW + c * 16, vh_ + (size_t)r * S + c * 8);
            cp16(st + VL_OFF + r * VROW + c * 16, vl_ + (size_t)r * S + c * 8);
        }
        asm volatile("cp.async.commit_group;" ::: "memory");
    };
    fillkv(0, 0);   // Q cp.asyncs ride this group

    float m0 = -INFINITY, m1 = -INFINITY, l0 = 0.f, l1 = 0.f;
    float o[16][4];
#pragma unroll
    for (int f = 0; f < 16; f++)
#pragma unroll
        for (int e = 0; e < 4; e++) o[f][e] = 0.f;

    const uint32_t aQ = (uint32_t)((wid * 16 + (lane & 15)) * QROW + ((lane >> 4) << 4));
    const uint32_t bK = (uint32_t)((lane & 15) * QROW + ((lane >> 4) << 4));
    const uint32_t bV = (uint32_t)((lane & 15) * VROW + ((lane >> 4) << 4));

    for (int kt = 0; kt <= qt; kt++) {
        asm volatile("cp.async.wait_group 0;" ::: "memory");
        __syncthreads();
        if (kt < qt) fillkv((kt + 1) & 1, kt + 1);
        const uint32_t st = sb + SK0_OFF + (kt & 1) * KSTG;

        // ---- scores: 3-term split (QhKh + QhKl + QlKh) ----
        float s[8][4];
#pragma unroll
        for (int f = 0; f < 8; f++)
#pragma unroll
            for (int e = 0; e < 4; e++) s[f][e] = 0.f;

#pragma unroll
        for (int ks = 0; ks < 8; ks++) {
            const uint32_t ko = ks * 32;
            uint32_t qh4[4], ql4[4];
            ldsm4(sb + SQH_OFF + aQ + ko, qh4[0], qh4[1], qh4[2], qh4[3]);
            ldsm4(sb + SQL_OFF + aQ + ko, ql4[0], ql4[1], ql4[2], ql4[3]);
#pragma unroll
            for (int nb = 0; nb < 4; nb++) {
                uint32_t k4[4], k4l[4];
                ldsm4(st + bK + nb * (16 * QROW) + ko, k4[0], k4[1], k4[2], k4[3]);
                ldsm4(st + KHL_OFF + bK + nb * (16 * QROW) + ko, k4l[0], k4l[1], k4l[2], k4l[3]);
                mma16816(s[nb * 2],     qh4, k4[0],  k4[2]);
                mma16816(s[nb * 2 + 1], qh4, k4[1],  k4[3]);
                mma16816(s[nb * 2],     qh4, k4l[0], k4l[2]);
                mma16816(s[nb * 2 + 1], qh4, k4l[1], k4l[3]);
                mma16816(s[nb * 2],     ql4, k4[0],  k4[2]);
                mma16816(s[nb * 2 + 1], ql4, k4[1],  k4[3]);
            }
        }

        // ---- causal mask on diagonal tile ----
        if (kt == qt) {
            const int r0 = wid * 16 + (lane >> 2);
            const int r1 = r0 + 8;
#pragma unroll
            for (int f = 0; f < 8; f++) {
                const int c0 = f * 8 + (lane & 3) * 2;
                if (c0     > r0) s[f][0] = -INFINITY;
                if (c0 + 1 > r0) s[f][1] = -INFINITY;
                if (c0     > r1) s[f][2] = -INFINITY;
                if (c0 + 1 > r1) s[f][3] = -INFINITY;
            }
        }

        // ---- online softmax (rows r0 = c[0],c[1]; r1 = c[2],c[3]) ----
        float a0 = -INFINITY, a1 = -INFINITY;
#pragma unroll
        for (int f = 0; f < 8; f++) {
            a0 = fmaxf(a0, fmaxf(s[f][0], s[f][1]));
            a1 = fmaxf(a1, fmaxf(s[f][2], s[f][3]));
        }
        a0 = fmaxf(a0, __shfl_xor_sync(0xffffffffu, a0, 1));
        a0 = fmaxf(a0, __shfl_xor_sync(0xffffffffu, a0, 2));
        a1 = fmaxf(a1, __shfl_xor_sync(0xffffffffu, a1, 1));
        a1 = fmaxf(a1, __shfl_xor_sync(0xffffffffu, a1, 2));
        const float mn0 = fmaxf(m0, a0), mn1 = fmaxf(m1, a1);
        const float sc0 = exp2f((m0 - mn0) * LOG2E);
        const float sc1 = exp2f((m1 - mn1) * LOG2E);
        float rs0 = 0.f, rs1 = 0.f;
#pragma unroll
        for (int f = 0; f < 8; f++) {
            s[f][0] = exp2f((s[f][0] - mn0) * LOG2E);
            s[f][1] = exp2f((s[f][1] - mn0) * LOG2E);
            s[f][2] = exp2f((s[f][2] - mn1) * LOG2E);
            s[f][3] = exp2f((s[f][3] - mn1) * LOG2E);
            rs0 += s[f][0] + s[f][1];
            rs1 += s[f][2] + s[f][3];
        }
        rs0 += __shfl_xor_sync(0xffffffffu, rs0, 1);
        rs0 += __shfl_xor_sync(0xffffffffu, rs0, 2);
        rs1 += __shfl_xor_sync(0xffffffffu, rs1, 1);
        rs1 += __shfl_xor_sync(0xffffffffu, rs1, 2);
        m0 = mn0; m1 = mn1;
        l0 = l0 * sc0 + rs0;
        l1 = l1 * sc1 + rs1;
#pragma unroll
        for (int f = 0; f < 16; f++) {
            o[f][0] *= sc0; o[f][1] *= sc0;
            o[f][2] *= sc1; o[f][3] *= sc1;
        }

        // ---- pack P into hi/lo A-frags (C-layout == A-layout trick) ----
        uint32_t ph[4][4], pl[4][4];
#pragma unroll
        for (int kb = 0; kb < 4; kb++) {
            split2(s[2 * kb][0],     s[2 * kb][1],     ph[kb][0], pl[kb][0]);
            split2(s[2 * kb][2],     s[2 * kb][3],     ph[kb][1], pl[kb][1]);
            split2(s[2 * kb + 1][0], s[2 * kb + 1][1], ph[kb][2], pl[kb][2]);
            split2(s[2 * kb + 1][2], s[2 * kb + 1][3], ph[kb][3], pl[kb][3]);
        }

        // ---- PV: 3-term split (PhVh + PhVl + PlVh) ----
#pragma unroll
        for (int kb = 0; kb < 4; kb++) {
            const uint32_t ko = kb * 32;
#pragma unroll
            for (int nb = 0; nb < 8; nb++) {
                uint32_t v4[4], v4l[4];
                ldsm4(st + VH_OFF + bV + nb * (16 * VROW) + ko, v4[0], v4[1], v4[2], v4[3]);
                ldsm4(st + VL_OFF + bV + nb * (16 * VROW) + ko, v4l[0], v4l[1], v4l[2], v4l[3]);
                mma16816(o[nb * 2],     ph[kb], v4[0],  v4[2]);
                mma16816(o[nb * 2 + 1], ph[kb], v4[1],  v4[3]);
                mma16816(o[nb * 2],     ph[kb], v4l[0], v4l[2]);
                mma16816(o[nb * 2 + 1], ph[kb], v4l[1], v4l[3]);
                mma16816(o[nb * 2],     pl[kb], v4[0],  v4[2]);
                mma16816(o[nb * 2 + 1], pl[kb], v4[1],  v4[3]);
            }
        }
    }

    // ---- epilogue: O/l, write bf16 hi/lo directly ----
    const float i0 = 1.f / l0, i1 = 1.f / l1;
    const int gr0 = qt * 64 + wid * 16 + (lane >> 2);
#pragma unroll
    for (int f = 0; f < 16; f++) {
        const int d0 = f * 8 + (lane & 3) * 2;
        const size_t ix0 = ((size_t)(b * S + gr0) * NH + h) * D + d0;
        const size_t ix1 = ((size_t)(b * S + gr0 + 8) * NH + h) * D + d0;
        uint32_t hi, lo;
        split2(o[f][0] * i0, o[f][1] * i0, hi, lo);
        *(uint32_t*)(g_aoh + ix0) = hi; *(uint32_t*)(g_aol + ix0) = lo;
        split2(o[f][2] * i1, o[f][3] * i1, hi, lo);
        *(uint32_t*)(g_aoh + ix1) = hi; *(uint32_t*)(g_aol + ix1) = lo;
    }
}

// ============================================================================
// host launcher
// ============================================================================
extern "C" void kernel_launch(void* const* d_in, const int* in_sizes, int n_in,
                              void* d_out, int out_size)
{
    const float* hidden = (const float*)d_in[0];
    const float* cosb   = (const float*)d_in[1];
    const float* sinb   = (const float*)d_in[2];
    const float* Wq     = (const float*)d_in[3];
    const float* Wk     = (const float*)d_in[4];
    const float* Wv     = (const float*)d_in[5];
    const float* Wo     = (const float*)d_in[6];
    const float* qw     = (const float*)d_in[7];
    const float* kw     = (const float*)d_in[8];
    float* out = (float*)d_out;

    __nv_bfloat16 *xh, *xl, *wh, *wl, *woh, *wol, *aoh, *aol;
    float* qkv;
    cudaGetSymbolAddress((void**)&xh,  g_xh);
    cudaGetSymbolAddress((void**)&xl,  g_xl);
    cudaGetSymbolAddress((void**)&wh,  g_wh);
    cudaGetSymbolAddress((void**)&wl,  g_wl);
    cudaGetSymbolAddress((void**)&woh, g_woh);
    cudaGetSymbolAddress((void**)&wol, g_wol);
    cudaGetSymbolAddress((void**)&aoh, g_aoh);
    cudaGetSymbolAddress((void**)&aol, g_aol);
    cudaGetSymbolAddress((void**)&qkv, g_qkv);

    cudaFuncSetAttribute(gemm_mma, cudaFuncAttributeMaxDynamicSharedMemorySize, GSMEM);
    cudaFuncSetAttribute(flash_mma, cudaFuncAttributeMaxDynamicSharedMemorySize, FSMEM);

    // fp32 -> bf16 hi/lo conversions
    {
        int n4;
        n4 = MSEQ * H / 4;
        split_fp32<<<(n4 + 255) / 256, 256>>>(hidden, xh, xl, n4);
        n4 = NH * D * H / 4;
        split_fp32<<<(n4 + 255) / 256, 256>>>(Wq, wh, wl, n4);
        n4 = NKV * D * H / 4;
        split_fp32<<<(n4 + 255) / 256, 256>>>(Wk, wh + (size_t)NH * D * H, wl + (size_t)NH * D * H, n4);
        split_fp32<<<(n4 + 255) / 256, 256>>>(Wv, wh + (size_t)(NH + NKV) * D * H, wl + (size_t)(NH + NKV) * D * H, n4);
        n4 = H * NH * D / 4;
        split_fp32<<<(n4 + 255) / 256, 256>>>(Wo, woh, wol, n4);
    }

    // fused QKV projection: [2048, 6144] = X[2048,4096] * Wqkv[6144,4096]^T
    gemm_mma<<<dim3(NQKV / 128, MSEQ / 128), 256, GSMEM>>>(
        xh, xl, wh, wl, qkv, MSEQ, NQKV, H);

    // norm + rope + split to bf16 (v transposed)
    qkv_post<<<dim3(MSEQ, NH + 2 * NKV), 128>>>(cosb, sinb, qw, kw);

    // causal flash attention on tensor cores
    flash_mma<<<dim3(S / 64, B * NH), 128, FSMEM>>>();

    // output projection: [2048, 4096] = AO[2048,4096] * Wo[4096,4096]^T
    gemm_mma<<<dim3(H / 128, MSEQ / 128), 256, GSMEM>>>(
        aoh, aol, woh, wol, out, MSEQ, H, NH * D);
}

// round 5
// speedup vs baseline: 2.6313x; 1.0186x over previous
#include <cuda_runtime.h>
#include <cuda_bf16.h>
#include <math.h>
#include <stdint.h>

// ---------------- problem constants ----------------
#define B   2
#define S   1024
#define H   4096
#define NH  32
#define NKV 8
#define D   128
#define GROUPS (NH / NKV)   // 4
#define EPS 1e-6f
#define QSCALE 0.08838834764831845f   // 1/sqrt(128)
#define MSEQ (B * S)        // 2048 rows
#define NQKV ((NH + 2 * NKV) * D)   // 6144
#define LOG2E 1.4426950408889634f

// ---------------- scratch (device globals) ----------------
__device__ __align__(16) __nv_bfloat16 g_xh [MSEQ * H];
__device__ __align__(16) __nv_bfloat16 g_xl [MSEQ * H];
__device__ __align__(16) __nv_bfloat16 g_wh [NQKV * H];
__device__ __align__(16) __nv_bfloat16 g_wl [NQKV * H];
__device__ __align__(16) __nv_bfloat16 g_woh[H * NH * D];
__device__ __align__(16) __nv_bfloat16 g_wol[H * NH * D];
__device__ __align__(16) __nv_bfloat16 g_aoh[MSEQ * NH * D];
__device__ __align__(16) __nv_bfloat16 g_aol[MSEQ * NH * D];
__device__ float g_qkv[MSEQ * NQKV];
// flash inputs, bf16 hi/lo. q,k row-major [B,heads,S,D]; v transposed [B,NKV,D,S]
__device__ __align__(16) __nv_bfloat16 g_qh [B * NH  * S * D];
__device__ __align__(16) __nv_bfloat16 g_ql [B * NH  * S * D];
__device__ __align__(16) __nv_bfloat16 g_kh [B * NKV * S * D];
__device__ __align__(16) __nv_bfloat16 g_kl [B * NKV * S * D];
__device__ __align__(16) __nv_bfloat16 g_vth[B * NKV * D * S];
__device__ __align__(16) __nv_bfloat16 g_vtl[B * NKV * D * S];

// ---------------- small helpers ----------------
__device__ __forceinline__ void cp16(uint32_t dst, const void* src) {
    asm volatile("cp.async.cg.shared.global [%0], [%1], 16;" :: "r"(dst), "l"(src) : "memory");
}
__device__ __forceinline__ void ldsm4(uint32_t addr, uint32_t& r0, uint32_t& r1,
                                      uint32_t& r2, uint32_t& r3) {
    asm volatile("ldmatrix.sync.aligned.m8n8.x4.shared.b16 {%0,%1,%2,%3}, [%4];"
        : "=r"(r0), "=r"(r1), "=r"(r2), "=r"(r3) : "r"(addr));
}
__device__ __forceinline__ void mma16816(float* c, const uint32_t* a,
                                         uint32_t b0, uint32_t b1) {
    asm volatile("mma.sync.aligned.m16n8k16.row.col.f32.bf16.bf16.f32 "
        "{%0,%1,%2,%3}, {%4,%5,%6,%7}, {%8,%9}, {%0,%1,%2,%3};"
        : "+f"(c[0]), "+f"(c[1]), "+f"(c[2]), "+f"(c[3])
        : "r"(a[0]), "r"(a[1]), "r"(a[2]), "r"(a[3]), "r"(b0), "r"(b1));
}
__device__ __forceinline__ void split1(float v, __nv_bfloat16& h, __nv_bfloat16& l) {
    h = __float2bfloat16(v);
    l = __float2bfloat16(v - __bfloat162float(h));
}
__device__ __forceinline__ void split2(float a, float b, uint32_t& hi, uint32_t& lo) {
    __nv_bfloat162 hv, lv;
    split1(a, hv.x, lv.x);
    split1(b, hv.y, lv.y);
    hi = *(uint32_t*)&hv;
    lo = *(uint32_t*)&lv;
}

// ============================================================================
// fp32 -> bf16 hi/lo split
// ============================================================================
__global__ void __launch_bounds__(256) split_fp32(
    const float* __restrict__ src, __nv_bfloat16* __restrict__ hi,
    __nv_bfloat16* __restrict__ lo, int n4)
{
    int i = blockIdx.x * 256 + threadIdx.x;
    if (i >= n4) return;
    float4 x = ((const float4*)src)[i];
    __nv_bfloat162 hv0, hv1, lv0, lv1;
    split1(x.x, hv0.x, lv0.x);
    split1(x.y, hv0.y, lv0.y);
    split1(x.z, hv1.x, lv1.x);
    split1(x.w, hv1.y, lv1.y);
    ((__nv_bfloat162*)hi)[2 * i]     = hv0;
    ((__nv_bfloat162*)hi)[2 * i + 1] = hv1;
    ((__nv_bfloat162*)lo)[2 * i]     = lv0;
    ((__nv_bfloat162*)lo)[2 * i + 1] = lv1;
}

// ============================================================================
// mma.sync split-bf16 NT GEMM: C[M,N] = (Ah+Al)(Bh+Bl)^T  (hh+hl+lh terms)
// Block tile 128x128x32, 8 warps (4m x 2n), warp tile 32x64.
// 4-stage cp.async ring, ONE __syncthreads per K-tile.
// Inner k16: 12 ldsm, 48 MMA in 3 independent passes (hh, lh, hl).
// ============================================================================
#define ROWB 80                        // bytes per 32-bf16 row (padded)
#define MATB (128 * ROWB)              // 10240 per matrix tile
#define STGB (4 * MATB)                // Ah|Al|Bh|Bl = 40960 per stage
#define GSMEM (4 * STGB)               // 163840

__global__ void __launch_bounds__(256) gemm_mma(
    const __nv_bfloat16* __restrict__ Ah, const __nv_bfloat16* __restrict__ Al,
    const __nv_bfloat16* __restrict__ Bh, const __nv_bfloat16* __restrict__ Bl,
    float* __restrict__ C, int M, int N, int K)
{
    extern __shared__ __align__(128) char smem[];
    const uint32_t sbase = (uint32_t)__cvta_generic_to_shared(smem);
    const int tid  = threadIdx.x;
    const int lane = tid & 31;
    const int wid  = tid >> 5;
    const int warp_m = wid >> 1;   // 0..3 (32 rows each)
    const int warp_n = wid & 1;    // 0..1 (64 cols each)
    const int m0 = blockIdx.y * 128;
    const int n0 = blockIdx.x * 128;
    const int KT = K >> 5;         // K / 32

    float acc[2][8][4];
#pragma unroll
    for (int i = 0; i < 2; i++)
#pragma unroll
        for (int j = 0; j < 8; j++)
#pragma unroll
            for (int q = 0; q < 4; q++) acc[i][j][q] = 0.f;

    auto fill = [&](int s, int kt) {
        const uint32_t st = sbase + s * STGB;
#pragma unroll
        for (int i = 0; i < 8; i++) {
            const int v = ((i & 1) << 8) + tid;    // 0..511 within matrix
            const int r = v >> 2, c = v & 3;
            const __nv_bfloat16* gb =
                (i < 2) ? Ah : (i < 4) ? Al : (i < 6) ? Bh : Bl;
            const int grow = ((i < 4) ? m0 : n0) + r;
            cp16(st + (i >> 1) * MATB + r * ROWB + c * 16,
                 gb + (size_t)grow * K + (size_t)kt * 32 + c * 8);
        }
        asm volatile("cp.async.commit_group;" ::: "memory");
    };

    fill(0, 0); fill(1, 1); fill(2, 2); fill(3, 3);

    const uint32_t aOff = (uint32_t)((warp_m * 32 + (lane & 15)) * ROWB + ((lane >> 4) << 4));
    const uint32_t bOff = (uint32_t)(2 * MATB + (warp_n * 64 + (lane & 15)) * ROWB + ((lane >> 4) << 4));

    for (int kt = 0; kt < KT; kt++) {
        asm volatile("cp.async.wait_group 2;" ::: "memory");
        __syncthreads();     // all warps done with iter kt-1 -> slot (kt-1)&3 free
        if (kt >= 1) {
            if (kt + 3 < KT) fill((kt + 3) & 3, kt + 3);
            else asm volatile("cp.async.commit_group;" ::: "memory");  // keep group count
        }

        const uint32_t st = sbase + (kt & 3) * STGB;
#pragma unroll
        for (int k16 = 0; k16 < 2; k16++) {
            const uint32_t ko = k16 * 32;
            uint32_t a[2][4], al[2][4], bh[4][4], bl[4][4];
#pragma unroll
            for (int mi = 0; mi < 2; mi++) {
                ldsm4(st + aOff + mi * (16 * ROWB) + ko,
                      a[mi][0], a[mi][1], a[mi][2], a[mi][3]);
                ldsm4(st + MATB + aOff + mi * (16 * ROWB) + ko,
                      al[mi][0], al[mi][1], al[mi][2], al[mi][3]);
            }
#pragma unroll
            for (int ni = 0; ni < 4; ni++) {
                ldsm4(st + bOff + ni * (16 * ROWB) + ko,
                      bh[ni][0], bh[ni][1], bh[ni][2], bh[ni][3]);
                ldsm4(st + bOff + MATB + ni * (16 * ROWB) + ko,
                      bl[ni][0], bl[ni][1], bl[ni][2], bl[ni][3]);
            }
            // pass 1: Ah*Bh (16 independent MMAs)
#pragma unroll
            for (int mi = 0; mi < 2; mi++)
#pragma unroll
                for (int ni = 0; ni < 4; ni++) {
                    mma16816(acc[mi][ni * 2],     a[mi], bh[ni][0], bh[ni][2]);
                    mma16816(acc[mi][ni * 2 + 1], a[mi], bh[ni][1], bh[ni][3]);
                }
            // pass 2: Al*Bh
#pragma unroll
            for (int mi = 0; mi < 2; mi++)
#pragma unroll
                for (int ni = 0; ni < 4; ni++) {
                    mma16816(acc[mi][ni * 2],     al[mi], bh[ni][0], bh[ni][2]);
                    mma16816(acc[mi][ni * 2 + 1], al[mi], bh[ni][1], bh[ni][3]);
                }
            // pass 3: Ah*Bl
#pragma unroll
            for (int mi = 0; mi < 2; mi++)
#pragma unroll
                for (int ni = 0; ni < 4; ni++) {
                    mma16816(acc[mi][ni * 2],     a[mi], bl[ni][0], bl[ni][2]);
                    mma16816(acc[mi][ni * 2 + 1], a[mi], bl[ni][1], bl[ni][3]);
                }
        }
    }

#pragma unroll
    for (int mi = 0; mi < 2; mi++) {
        const int row = m0 + warp_m * 32 + mi * 16 + (lane >> 2);
#pragma unroll
        for (int nj = 0; nj < 8; nj++) {
            const int col = n0 + warp_n * 64 + nj * 8 + (lane & 3) * 2;
            float* cp0 = C + (size_t)row * N + col;
            float* cp1 = C + (size_t)(row + 8) * N + col;
            *(float2*)cp0 = make_float2(acc[mi][nj][0], acc[mi][nj][1]);
            *(float2*)cp1 = make_float2(acc[mi][nj][2], acc[mi][nj][3]);
        }
    }
}

// ============================================================================
// Per-head RMSNorm + RoPE; writes bf16 hi/lo. q,k row-major; v transposed.
// grid: (B*S, 48), block 128.
// ============================================================================
__global__ void __launch_bounds__(128) qkv_post(
    const float* __restrict__ cosb, const float* __restrict__ sinb,
    const float* __restrict__ qw,   const float* __restrict__ kw)
{
    const int bs = blockIdx.x;
    const int hh = blockIdx.y;
    const int d  = threadIdx.x;
    const int b  = bs / S;
    const int s  = bs - b * S;

    __shared__ float xs[D];
    __shared__ float red[4];

    float x = g_qkv[(size_t)bs * NQKV + hh * D + d];

    if (hh < NH + NKV) {
        float ss = x * x;
#pragma unroll
        for (int o = 16; o; o >>= 1) ss += __shfl_xor_sync(0xffffffffu, ss, o);
        if ((d & 31) == 0) red[d >> 5] = ss;
        __syncthreads();
        const float var = (red[0] + red[1] + red[2] + red[3]) * (1.0f / D);
        const float w = (hh < NH) ? qw[d] : kw[d];
        x = x * rsqrtf(var + EPS) * w;
        xs[d] = x;
        __syncthreads();
        const float c  = cosb[(size_t)bs * D + d];
        const float sn = sinb[(size_t)bs * D + d];
        const float part = (d < 64) ? -xs[d + 64] : xs[d - 64];
        x = x * c + part * sn;
    }

    __nv_bfloat16 hi, lo;
    if (hh < NH) {
        split1(x * QSCALE, hi, lo);
        const size_t idx = (((size_t)b * NH + hh) * S + s) * D + d;
        g_qh[idx] = hi; g_ql[idx] = lo;
    } else if (hh < NH + NKV) {
        split1(x, hi, lo);
        const size_t idx = (((size_t)b * NKV + (hh - NH)) * S + s) * D + d;
        g_kh[idx] = hi; g_kl[idx] = lo;
    } else {
        split1(x, hi, lo);
        const size_t idx = (((size_t)b * NKV + (hh - NH - NKV)) * D + d) * S + s;
        g_vth[idx] = hi; g_vtl[idx] = lo;
    }
}

// ============================================================================
// Causal flash attention on mma.sync, split-bf16 3-term for QK^T and PV.
// BM=128, BN=64, 8 warps (256 threads), warp owns 16 q-rows.
// 2-stage KV pipeline. 3-term MMAs organized in independent passes.
// ============================================================================
#define QROW 272                       // 128 bf16 + 8 pad
#define VROW 144                       // 64 bf16 + 8 pad
#define SQH_OFF 0
#define SQL_OFF (128 * QROW)           // 34816
#define SK0_OFF (2 * 128 * QROW)       // 69632
#define KHL_OFF (64 * QROW)            // Kl within stage (17408)
#define VH_OFF  (2 * 64 * QROW)        // Vth within stage: 34816
#define VL_OFF  (VH_OFF + 128 * VROW)  // 53248
#define KSTG    (VL_OFF + 128 * VROW)  // 71680
#define FSMEM   (SK0_OFF + 2 * KSTG)   // 212992

__global__ void __launch_bounds__(256) flash_mma()
{
    extern __shared__ __align__(128) char fsm[];
    const uint32_t sb = (uint32_t)__cvta_generic_to_shared(fsm);
    const int tid = threadIdx.x, lane = tid & 31, wid = tid >> 5;
    const int qt = (int)gridDim.x - 1 - (int)blockIdx.x;   // heavy CTAs first
    const int bh = blockIdx.y;
    const int b = bh / NH, h = bh - b * NH;
    const int kvh = h / GROUPS;

    const __nv_bfloat16* Qhp = g_qh + (((size_t)b * NH + h) * S + (size_t)qt * 128) * D;
    const __nv_bfloat16* Qlp = g_ql + (((size_t)b * NH + h) * S + (size_t)qt * 128) * D;
    const __nv_bfloat16* Khp = g_kh + ((size_t)b * NKV + kvh) * S * D;
    const __nv_bfloat16* Klp = g_kl + ((size_t)b * NKV + kvh) * S * D;
    const __nv_bfloat16* Vhp = g_vth + ((size_t)b * NKV + kvh) * D * S;
    const __nv_bfloat16* Vlp = g_vtl + ((size_t)b * NKV + kvh) * D * S;

    // Q tiles (loaded once): 128 rows x 128 bf16, hi+lo
#pragma unroll
    for (int i = tid; i < 2048; i += 256) {
        const int r = i >> 4, c = i & 15;
        cp16(sb + SQH_OFF + r * QROW + c * 16, Qhp + r * D + c * 8);
        cp16(sb + SQL_OFF + r * QROW + c * 16, Qlp + r * D + c * 8);
    }

    auto fillkv = [&](int slot, int kt) {
        const uint32_t st = sb + SK0_OFF + slot * KSTG;
        const __nv_bfloat16* kh_ = Khp + (size_t)kt * 64 * D;
        const __nv_bfloat16* kl_ = Klp + (size_t)kt * 64 * D;
#pragma unroll
        for (int i = tid; i < 1024; i += 256) {
            const int r = i >> 4, c = i & 15;
            cp16(st + r * QROW + c * 16,           kh_ + r * D + c * 8);
            cp16(st + KHL_OFF + r * QROW + c * 16, kl_ + r * D + c * 8);
        }
        const __nv_bfloat16* vh_ = Vhp + (size_t)kt * 64;
        const __nv_bfloat16* vl_ = Vlp + (size_t)kt * 64;
#pragma unroll
        for (int i = tid; i < 1024; i += 256) {
            const int r = i >> 3, c = i & 7;
            cp16(st + VH_OFF + r * VROW + c * 16, vh_ + (size_t)r * S + c * 8);
            cp16(st + VL_OFF + r * VROW + c * 16, vl_ + (size_t)r * S + c * 8);
        }
        asm volatile("cp.async.commit_group;" ::: "memory");
    };
    fillkv(0, 0);   // Q cp.asyncs ride this group

    float m0 = -INFINITY, m1 = -INFINITY, l0 = 0.f, l1 = 0.f;
    float o[16][4];
#pragma unroll
    for (int f = 0; f < 16; f++)
#pragma unroll
        for (int e = 0; e < 4; e++) o[f][e] = 0.f;

    const uint32_t aQ = (uint32_t)((wid * 16 + (lane & 15)) * QROW + ((lane >> 4) << 4));
    const uint32_t bK = (uint32_t)((lane & 15) * QROW + ((lane >> 4) << 4));
    const uint32_t bV = (uint32_t)((lane & 15) * VROW + ((lane >> 4) << 4));

    const int ktmax = 2 * qt + 1;

    for (int kt = 0; kt <= ktmax; kt++) {
        asm volatile("cp.async.wait_group 0;" ::: "memory");
        __syncthreads();
        if (kt < ktmax) fillkv((kt + 1) & 1, kt + 1);
        const uint32_t st = sb + SK0_OFF + (kt & 1) * KSTG;

        // ---- scores: 3-term split in independent passes ----
        float s[8][4];
#pragma unroll
        for (int f = 0; f < 8; f++)
#pragma unroll
            for (int e = 0; e < 4; e++) s[f][e] = 0.f;

#pragma unroll
        for (int ks = 0; ks < 8; ks++) {
            const uint32_t ko = ks * 32;
            uint32_t qh4[4], ql4[4], kh4[4][4], kl4[4][4];
            ldsm4(sb + SQH_OFF + aQ + ko, qh4[0], qh4[1], qh4[2], qh4[3]);
            ldsm4(sb + SQL_OFF + aQ + ko, ql4[0], ql4[1], ql4[2], ql4[3]);
#pragma unroll
            for (int nb = 0; nb < 4; nb++) {
                ldsm4(st + bK + nb * (16 * QROW) + ko,
                      kh4[nb][0], kh4[nb][1], kh4[nb][2], kh4[nb][3]);
                ldsm4(st + KHL_OFF + bK + nb * (16 * QROW) + ko,
                      kl4[nb][0], kl4[nb][1], kl4[nb][2], kl4[nb][3]);
            }
            // pass Qh*Kh
#pragma unroll
            for (int nb = 0; nb < 4; nb++) {
                mma16816(s[nb * 2],     qh4, kh4[nb][0], kh4[nb][2]);
                mma16816(s[nb * 2 + 1], qh4, kh4[nb][1], kh4[nb][3]);
            }
            // pass Ql*Kh
#pragma unroll
            for (int nb = 0; nb < 4; nb++) {
                mma16816(s[nb * 2],     ql4, kh4[nb][0], kh4[nb][2]);
                mma16816(s[nb * 2 + 1], ql4, kh4[nb][1], kh4[nb][3]);
            }
            // pass Qh*Kl
#pragma unroll
            for (int nb = 0; nb < 4; nb++) {
                mma16816(s[nb * 2],     qh4, kl4[nb][0], kl4[nb][2]);
                mma16816(s[nb * 2 + 1], qh4, kl4[nb][1], kl4[nb][3]);
            }
        }

        // ---- causal mask (needed only on the last two tiles) ----
        if (kt >= 2 * qt) {
            const int r0 = qt * 128 + wid * 16 + (lane >> 2);
            const int r1 = r0 + 8;
#pragma unroll
            for (int f = 0; f < 8; f++) {
                const int c0 = kt * 64 + f * 8 + (lane & 3) * 2;
                if (c0     > r0) s[f][0] = -INFINITY;
                if (c0 + 1 > r0) s[f][1] = -INFINITY;
                if (c0     > r1) s[f][2] = -INFINITY;
                if (c0 + 1 > r1) s[f][3] = -INFINITY;
            }
        }

        // ---- online softmax ----
        float a0 = -INFINITY, a1 = -INFINITY;
#pragma unroll
        for (int f = 0; f < 8; f++) {
            a0 = fmaxf(a0, fmaxf(s[f][0], s[f][1]));
            a1 = fmaxf(a1, fmaxf(s[f][2], s[f][3]));
        }
        a0 = fmaxf(a0, __shfl_xor_sync(0xffffffffu, a0, 1));
        a0 = fmaxf(a0, __shfl_xor_sync(0xffffffffu, a0, 2));
        a1 = fmaxf(a1, __shfl_xor_sync(0xffffffffu, a1, 1));
        a1 = fmaxf(a1, __shfl_xor_sync(0xffffffffu, a1, 2));
        const float mn0 = fmaxf(m0, a0), mn1 = fmaxf(m1, a1);
        const float sc0 = exp2f((m0 - mn0) * LOG2E);
        const float sc1 = exp2f((m1 - mn1) * LOG2E);
        float rs0 = 0.f, rs1 = 0.f;
#pragma unroll
        for (int f = 0; f < 8; f++) {
            s[f][0] = exp2f((s[f][0] - mn0) * LOG2E);
            s[f][1] = exp2f((s[f][1] - mn0) * LOG2E);
            s[f][2] = exp2f((s[f][2] - mn1) * LOG2E);
            s[f][3] = exp2f((s[f][3] - mn1) * LOG2E);
            rs0 += s[f][0] + s[f][1];
            rs1 += s[f][2] + s[f][3];
        }
        rs0 += __shfl_xor_sync(0xffffffffu, rs0, 1);
        rs0 += __shfl_xor_sync(0xffffffffu, rs0, 2);
        rs1 += __shfl_xor_sync(0xffffffffu, rs1, 1);
        rs1 += __shfl_xor_sync(0xffffffffu, rs1, 2);
        m0 = mn0; m1 = mn1;
        l0 = l0 * sc0 + rs0;
        l1 = l1 * sc1 + rs1;
#pragma unroll
        for (int f = 0; f < 16; f++) {
            o[f][0] *= sc0; o[f][1] *= sc0;
            o[f][2] *= sc1; o[f][3] *= sc1;
        }

        // ---- pack P into hi/lo A-frags ----
        uint32_t ph[4][4], pl[4][4];
#pragma unroll
        for (int kb = 0; kb < 4; kb++) {
            split2(s[2 * kb][0],     s[2 * kb][1],     ph[kb][0], pl[kb][0]);
            split2(s[2 * kb][2],     s[2 * kb][3],     ph[kb][1], pl[kb][1]);
            split2(s[2 * kb + 1][0], s[2 * kb + 1][1], ph[kb][2], pl[kb][2]);
            split2(s[2 * kb + 1][2], s[2 * kb + 1][3], ph[kb][3], pl[kb][3]);
        }

        // ---- PV: 3-term in passes (PhVh, PlVh share Vh; then PhVl) ----
#pragma unroll
        for (int kb = 0; kb < 4; kb++) {
            const uint32_t ko = kb * 32;
            uint32_t vh4[8][4];
#pragma unroll
            for (int nb = 0; nb < 8; nb++)
                ldsm4(st + VH_OFF + bV + nb * (16 * VROW) + ko,
                      vh4[nb][0], vh4[nb][1], vh4[nb][2], vh4[nb][3]);
#pragma unroll
            for (int nb = 0; nb < 8; nb++) {
                mma16816(o[nb * 2],     ph[kb], vh4[nb][0], vh4[nb][2]);
                mma16816(o[nb * 2 + 1], ph[kb], vh4[nb][1], vh4[nb][3]);
            }
#pragma unroll
            for (int nb = 0; nb < 8; nb++) {
                mma16816(o[nb * 2],     pl[kb], vh4[nb][0], vh4[nb][2]);
                mma16816(o[nb * 2 + 1], pl[kb], vh4[nb][1], vh4[nb][3]);
            }
#pragma unroll
            for (int nb = 0; nb < 8; nb++) {
                uint32_t v0, v1, v2, v3;
                ldsm4(st + VL_OFF + bV + nb * (16 * VROW) + ko, v0, v1, v2, v3);
                mma16816(o[nb * 2],     ph[kb], v0, v2);
                mma16816(o[nb * 2 + 1], ph[kb], v1, v3);
            }
        }
    }

    // ---- epilogue: O/l, write bf16 hi/lo directly ----
    const float i0 = 1.f / l0, i1 = 1.f / l1;
    const int gr0 = qt * 128 + wid * 16 + (lane >> 2);
#pragma unroll
    for (int f = 0; f < 16; f++) {
        const int d0 = f * 8 + (lane & 3) * 2;
        const size_t ix0 = ((size_t)(b * S + gr0) * NH + h) * D + d0;
        const size_t ix1 = ((size_t)(b * S + gr0 + 8) * NH + h) * D + d0;
        uint32_t hi, lo;
        split2(o[f][0] * i0, o[f][1] * i0, hi, lo);
        *(uint32_t*)(g_aoh + ix0) = hi; *(uint32_t*)(g_aol + ix0) = lo;
        split2(o[f][2] * i1, o[f][3] * i1, hi, lo);
        *(uint32_t*)(g_aoh + ix1) = hi; *(uint32_t*)(g_aol + ix1) = lo;
    }
}

// ============================================================================
// host launcher
// ============================================================================
extern "C" void kernel_launch(void* const* d_in, const int* in_sizes, int n_in,
                              void* d_out, int out_size)
{
    const float* hidden = (const float*)d_in[0];
    const float* cosb   = (const float*)d_in[1];
    const float* sinb   = (const float*)d_in[2];
    const float* Wq     = (const float*)d_in[3];
    const float* Wk     = (const float*)d_in[4];
    const float* Wv     = (const float*)d_in[5];
    const float* Wo     = (const float*)d_in[6];
    const float* qw     = (const float*)d_in[7];
    const float* kw     = (const float*)d_in[8];
    float* out = (float*)d_out;

    __nv_bfloat16 *xh, *xl, *wh, *wl, *woh, *wol, *aoh, *aol;
    float* qkv;
    cudaGetSymbolAddress((void**)&xh,  g_xh);
    cudaGetSymbolAddress((void**)&xl,  g_xl);
    cudaGetSymbolAddress((void**)&wh,  g_wh);
    cudaGetSymbolAddress((void**)&wl,  g_wl);
    cudaGetSymbolAddress((void**)&woh, g_woh);
    cudaGetSymbolAddress((void**)&wol, g_wol);
    cudaGetSymbolAddress((void**)&aoh, g_aoh);
    cudaGetSymbolAddress((void**)&aol, g_aol);
    cudaGetSymbolAddress((void**)&qkv, g_qkv);

    cudaFuncSetAttribute(gemm_mma, cudaFuncAttributeMaxDynamicSharedMemorySize, GSMEM);
    cudaFuncSetAttribute(flash_mma, cudaFuncAttributeMaxDynamicSharedMemorySize, FSMEM);

    // fp32 -> bf16 hi/lo conversions
    {
        int n4;
        n4 = MSEQ * H / 4;
        split_fp32<<<(n4 + 255) / 256, 256>>>(hidden, xh, xl, n4);
        n4 = NH * D * H / 4;
        split_fp32<<<(n4 + 255) / 256, 256>>>(Wq, wh, wl, n4);
        n4 = NKV * D * H / 4;
        split_fp32<<<(n4 + 255) / 256, 256>>>(Wk, wh + (size_t)NH * D * H, wl + (size_t)NH * D * H, n4);
        split_fp32<<<(n4 + 255) / 256, 256>>>(Wv, wh + (size_t)(NH + NKV) * D * H, wl + (size_t)(NH + NKV) * D * H, n4);
        n4 = H * NH * D / 4;
        split_fp32<<<(n4 + 255) / 256, 256>>>(Wo, woh, wol, n4);
    }

    // fused QKV projection: [2048, 6144] = X[2048,4096] * Wqkv[6144,4096]^T
    gemm_mma<<<dim3(NQKV / 128, MSEQ / 128), 256, GSMEM>>>(
        xh, xl, wh, wl, qkv, MSEQ, NQKV, H);

    // norm + rope + split to bf16 (v transposed)
    qkv_post<<<dim3(MSEQ, NH + 2 * NKV), 128>>>(cosb, sinb, qw, kw);

    // causal flash attention on tensor cores
    flash_mma<<<dim3(S / 128, B * NH), 256, FSMEM>>>();

    // output projection: [2048, 4096] = AO[2048,4096] * Wo[4096,4096]^T
    gemm_mma<<<dim3(H / 128, MSEQ / 128), 256, GSMEM>>>(
        aoh, aol, woh, wol, out, MSEQ, H, NH * D);
}

// round 6
// speedup vs baseline: 3.6117x; 1.3726x over previous
#include <cuda_runtime.h>
#include <cuda_fp16.h>
#include <math.h>
#include <stdint.h>

// ---------------- problem constants ----------------
#define B   2
#define S   1024
#define H   4096
#define NH  32
#define NKV 8
#define D   128
#define GROUPS (NH / NKV)   // 4
#define EPS 1e-6f
#define QSCALE 0.08838834764831845f   // 1/sqrt(128)
#define MSEQ (B * S)        // 2048 rows
#define NQKV ((NH + 2 * NKV) * D)   // 6144
#define LOG2E 1.4426950408889634f
#define ASCALE 256.0f
#define AINV   (1.0f / 256.0f)
#define QSC    32.0f
#define SFIX   (QSCALE / 32.0f)
#define PBIAS  12.0f                 // P scaled by 2^12 (cancels in O/l)

// ---------------- scratch (device globals, fp16) ----------------
__device__ __align__(16) __half g_xh [MSEQ * H];       // hidden*256 hi
__device__ __align__(16) __half g_xl [MSEQ * H];       // hidden*256 lo
__device__ __align__(16) __half g_wh [NQKV * H];       // stacked Wq|Wk|Wv (hi only)
__device__ __align__(16) __half g_woh[H * NH * D];     // Wo (hi only)
__device__ __align__(16) __half g_aoh[MSEQ * NH * D];  // attn out *256 hi
__device__ __align__(16) __half g_aol[MSEQ * NH * D];  // attn out *256 lo
__device__ float g_qkv[MSEQ * NQKV];
// flash inputs: q*32 hi/lo row-major, k hi row-major, v hi transposed [B,NKV,D,S]
__device__ __align__(16) __half g_qh [B * NH  * S * D];
__device__ __align__(16) __half g_ql [B * NH  * S * D];
__device__ __align__(16) __half g_kh [B * NKV * S * D];
__device__ __align__(16) __half g_vth[B * NKV * D * S];

// ---------------- small helpers ----------------
__device__ __forceinline__ void cp16(uint32_t dst, const void* src) {
    asm volatile("cp.async.cg.shared.global [%0], [%1], 16;" :: "r"(dst), "l"(src) : "memory");
}
__device__ __forceinline__ void ldsm4(uint32_t addr, uint32_t& r0, uint32_t& r1,
                                      uint32_t& r2, uint32_t& r3) {
    asm volatile("ldmatrix.sync.aligned.m8n8.x4.shared.b16 {%0,%1,%2,%3}, [%4];"
        : "=r"(r0), "=r"(r1), "=r"(r2), "=r"(r3) : "r"(addr));
}
__device__ __forceinline__ void mma16816(float* c, const uint32_t* a,
                                         uint32_t b0, uint32_t b1) {
    asm volatile("mma.sync.aligned.m16n8k16.row.col.f32.f16.f16.f32 "
        "{%0,%1,%2,%3}, {%4,%5,%6,%7}, {%8,%9}, {%0,%1,%2,%3};"
        : "+f"(c[0]), "+f"(c[1]), "+f"(c[2]), "+f"(c[3])
        : "r"(a[0]), "r"(a[1]), "r"(a[2]), "r"(a[3]), "r"(b0), "r"(b1));
}
__device__ __forceinline__ void split1h(float v, __half& h, __half& l) {
    h = __float2half(v);
    l = __float2half(v - __half2float(h));
}
__device__ __forceinline__ void split2h(float a, float b, uint32_t& hi, uint32_t& lo) {
    __half2 hv, lv;
    split1h(a, hv.x, lv.x);
    split1h(b, hv.y, lv.y);
    hi = *(uint32_t*)&hv;
    lo = *(uint32_t*)&lv;
}

// ============================================================================
// fp32 -> fp16 hi/lo split with scale
// ============================================================================
__global__ void __launch_bounds__(256) split_fp32(
    const float* __restrict__ src, __half* __restrict__ hi,
    __half* __restrict__ lo, float scale, int n4)
{
    int i = blockIdx.x * 256 + threadIdx.x;
    if (i >= n4) return;
    float4 x = ((const float4*)src)[i];
    __half2 hv0, hv1, lv0, lv1;
    split1h(x.x * scale, hv0.x, lv0.x);
    split1h(x.y * scale, hv0.y, lv0.y);
    split1h(x.z * scale, hv1.x, lv1.x);
    split1h(x.w * scale, hv1.y, lv1.y);
    ((__half2*)hi)[2 * i]     = hv0;
    ((__half2*)hi)[2 * i + 1] = hv1;
    ((__half2*)lo)[2 * i]     = lv0;
    ((__half2*)lo)[2 * i + 1] = lv1;
}

// fp32 -> fp16 round (hi only, no scale)
__global__ void __launch_bounds__(256) cvt_fp32(
    const float* __restrict__ src, __half* __restrict__ dst, int n4)
{
    int i = blockIdx.x * 256 + threadIdx.x;
    if (i >= n4) return;
    float4 x = ((const float4*)src)[i];
    ((__half2*)dst)[2 * i]     = __floats2half2_rn(x.x, x.y);
    ((__half2*)dst)[2 * i + 1] = __floats2half2_rn(x.z, x.w);
}

// ============================================================================
// mma.sync split-fp16 NT GEMM: C[M,N] = alpha*(Ah+Al)[M,K]*Bh[N,K]^T (2 terms)
// Block tile 128x128x32, 8 warps (4m x 2n), warp tile 32x64.
// 4-stage cp.async ring, ONE __syncthreads per K-tile.
// ============================================================================
#define ROWB 80                        // bytes per 32-fp16 row (padded)
#define MATB (128 * ROWB)              // 10240 per matrix tile
#define STGB (3 * MATB)                // Ah|Al|Bh = 30720 per stage
#define GSMEM (4 * STGB)               // 122880

__global__ void __launch_bounds__(256) gemm_mma(
    const __half* __restrict__ Ah, const __half* __restrict__ Al,
    const __half* __restrict__ Bh, float* __restrict__ C,
    float alpha, int M, int N, int K)
{
    extern __shared__ __align__(128) char smem[];
    const uint32_t sbase = (uint32_t)__cvta_generic_to_shared(smem);
    const int tid  = threadIdx.x;
    const int lane = tid & 31;
    const int wid  = tid >> 5;
    const int warp_m = wid >> 1;   // 0..3 (32 rows each)
    const int warp_n = wid & 1;    // 0..1 (64 cols each)
    const int m0 = blockIdx.y * 128;
    const int n0 = blockIdx.x * 128;
    const int KT = K >> 5;         // K / 32

    float acc[2][8][4];
#pragma unroll
    for (int i = 0; i < 2; i++)
#pragma unroll
        for (int j = 0; j < 8; j++)
#pragma unroll
            for (int q = 0; q < 4; q++) acc[i][j][q] = 0.f;

    auto fill = [&](int s, int kt) {
        const uint32_t st = sbase + s * STGB;
#pragma unroll
        for (int i = 0; i < 6; i++) {
            const int v = ((i & 1) << 8) + tid;    // 0..511 within matrix
            const int r = v >> 2, c = v & 3;
            const __half* gb = (i < 2) ? Ah : (i < 4) ? Al : Bh;
            const int grow = ((i < 4) ? m0 : n0) + r;
            cp16(st + (i >> 1) * MATB + r * ROWB + c * 16,
                 gb + (size_t)grow * K + (size_t)kt * 32 + c * 8);
        }
        asm volatile("cp.async.commit_group;" ::: "memory");
    };

    fill(0, 0); fill(1, 1); fill(2, 2); fill(3, 3);

    const uint32_t aOff = (uint32_t)((warp_m * 32 + (lane & 15)) * ROWB + ((lane >> 4) << 4));
    const uint32_t bOff = (uint32_t)(2 * MATB + (warp_n * 64 + (lane & 15)) * ROWB + ((lane >> 4) << 4));

    for (int kt = 0; kt < KT; kt++) {
        asm volatile("cp.async.wait_group 2;" ::: "memory");
        __syncthreads();     // all warps done with iter kt-1 -> slot (kt-1)&3 free
        if (kt >= 1) {
            if (kt + 3 < KT) fill((kt + 3) & 3, kt + 3);
            else asm volatile("cp.async.commit_group;" ::: "memory");  // keep group count
        }

        const uint32_t st = sbase + (kt & 3) * STGB;
#pragma unroll
        for (int k16 = 0; k16 < 2; k16++) {
            const uint32_t ko = k16 * 32;
            uint32_t a[2][4], al[2][4], bh[4][4];
#pragma unroll
            for (int mi = 0; mi < 2; mi++) {
                ldsm4(st + aOff + mi * (16 * ROWB) + ko,
                      a[mi][0], a[mi][1], a[mi][2], a[mi][3]);
                ldsm4(st + MATB + aOff + mi * (16 * ROWB) + ko,
                      al[mi][0], al[mi][1], al[mi][2], al[mi][3]);
            }
#pragma unroll
            for (int ni = 0; ni < 4; ni++)
                ldsm4(st + bOff + ni * (16 * ROWB) + ko,
                      bh[ni][0], bh[ni][1], bh[ni][2], bh[ni][3]);
            // pass 1: Ah*Bh (16 independent MMAs)
#pragma unroll
            for (int mi = 0; mi < 2; mi++)
#pragma unroll
                for (int ni = 0; ni < 4; ni++) {
                    mma16816(acc[mi][ni * 2],     a[mi], bh[ni][0], bh[ni][2]);
                    mma16816(acc[mi][ni * 2 + 1], a[mi], bh[ni][1], bh[ni][3]);
                }
            // pass 2: Al*Bh
#pragma unroll
            for (int mi = 0; mi < 2; mi++)
#pragma unroll
                for (int ni = 0; ni < 4; ni++) {
                    mma16816(acc[mi][ni * 2],     al[mi], bh[ni][0], bh[ni][2]);
                    mma16816(acc[mi][ni * 2 + 1], al[mi], bh[ni][1], bh[ni][3]);
                }
        }
    }

#pragma unroll
    for (int mi = 0; mi < 2; mi++) {
        const int row = m0 + warp_m * 32 + mi * 16 + (lane >> 2);
#pragma unroll
        for (int nj = 0; nj < 8; nj++) {
            const int col = n0 + warp_n * 64 + nj * 8 + (lane & 3) * 2;
            float* cp0 = C + (size_t)row * N + col;
            float* cp1 = C + (size_t)(row + 8) * N + col;
            *(float2*)cp0 = make_float2(acc[mi][nj][0] * alpha, acc[mi][nj][1] * alpha);
            *(float2*)cp1 = make_float2(acc[mi][nj][2] * alpha, acc[mi][nj][3] * alpha);
        }
    }
}

// ============================================================================
// Per-head RMSNorm + RoPE; q -> fp16 hi/lo (*32), k -> fp16 hi, v -> fp16 hi ^T
// grid: (B*S, 48), block 128.
// ============================================================================
__global__ void __launch_bounds__(128) qkv_post(
    const float* __restrict__ cosb, const float* __restrict__ sinb,
    const float* __restrict__ qw,   const float* __restrict__ kw)
{
    const int bs = blockIdx.x;
    const int hh = blockIdx.y;
    const int d  = threadIdx.x;
    const int b  = bs / S;
    const int s  = bs - b * S;

    __shared__ float xs[D];
    __shared__ float red[4];

    float x = g_qkv[(size_t)bs * NQKV + hh * D + d];

    if (hh < NH + NKV) {
        float ss = x * x;
#pragma unroll
        for (int o = 16; o; o >>= 1) ss += __shfl_xor_sync(0xffffffffu, ss, o);
        if ((d & 31) == 0) red[d >> 5] = ss;
        __syncthreads();
        const float var = (red[0] + red[1] + red[2] + red[3]) * (1.0f / D);
        const float w = (hh < NH) ? qw[d] : kw[d];
        x = x * rsqrtf(var + EPS) * w;
        xs[d] = x;
        __syncthreads();
        const float c  = cosb[(size_t)bs * D + d];
        const float sn = sinb[(size_t)bs * D + d];
        const float part = (d < 64) ? -xs[d + 64] : xs[d - 64];
        x = x * c + part * sn;
    }

    if (hh < NH) {
        __half hi, lo;
        split1h(x * QSC, hi, lo);
        const size_t idx = (((size_t)b * NH + hh) * S + s) * D + d;
        g_qh[idx] = hi; g_ql[idx] = lo;
    } else if (hh < NH + NKV) {
        const size_t idx = (((size_t)b * NKV + (hh - NH)) * S + s) * D + d;
        g_kh[idx] = __float2half(x);
    } else {
        const size_t idx = (((size_t)b * NKV + (hh - NH - NKV)) * D + d) * S + s;
        g_vth[idx] = __float2half(x);
    }
}

// ============================================================================
// Causal flash attention, fp16 2-term (QhKh+QlKh; PhVh+PlVh).
// BM=128, BN=64, 8 warps (256 threads), warp owns 16 q-rows.
// 2-stage KV pipeline.
// ============================================================================
#define QROW 272                       // 128 fp16 + 8 pad
#define VROW 144                       // 64 fp16 + 8 pad
#define SQH_OFF 0
#define SQL_OFF (128 * QROW)           // 34816
#define SK0_OFF (2 * 128 * QROW)       // 69632
#define VH_SOFF (64 * QROW)            // Vh within stage (17408)
#define KSTG    (VH_SOFF + 128 * VROW) // 35840
#define FSMEM   (SK0_OFF + 2 * KSTG)   // 141312

__global__ void __launch_bounds__(256) flash_mma()
{
    extern __shared__ __align__(128) char fsm[];
    const uint32_t sb = (uint32_t)__cvta_generic_to_shared(fsm);
    const int tid = threadIdx.x, lane = tid & 31, wid = tid >> 5;
    const int qt = (int)gridDim.x - 1 - (int)blockIdx.x;   // heavy CTAs first
    const int bh = blockIdx.y;
    const int b = bh / NH, h = bh - b * NH;
    const int kvh = h / GROUPS;

    const __half* Qhp = g_qh + (((size_t)b * NH + h) * S + (size_t)qt * 128) * D;
    const __half* Qlp = g_ql + (((size_t)b * NH + h) * S + (size_t)qt * 128) * D;
    const __half* Khp = g_kh + ((size_t)b * NKV + kvh) * S * D;
    const __half* Vhp = g_vth + ((size_t)b * NKV + kvh) * D * S;

    // Q tiles (loaded once): 128 rows x 128 fp16, hi+lo
#pragma unroll
    for (int i = tid; i < 2048; i += 256) {
        const int r = i >> 4, c = i & 15;
        cp16(sb + SQH_OFF + r * QROW + c * 16, Qhp + r * D + c * 8);
        cp16(sb + SQL_OFF + r * QROW + c * 16, Qlp + r * D + c * 8);
    }

    auto fillkv = [&](int slot, int kt) {
        const uint32_t st = sb + SK0_OFF + slot * KSTG;
        const __half* kh_ = Khp + (size_t)kt * 64 * D;
#pragma unroll
        for (int i = tid; i < 1024; i += 256) {
            const int r = i >> 4, c = i & 15;
            cp16(st + r * QROW + c * 16, kh_ + r * D + c * 8);
        }
        const __half* vh_ = Vhp + (size_t)kt * 64;
#pragma unroll
        for (int i = tid; i < 1024; i += 256) {
            const int r = i >> 3, c = i & 7;
            cp16(st + VH_SOFF + r * VROW + c * 16, vh_ + (size_t)r * S + c * 8);
        }
        asm volatile("cp.async.commit_group;" ::: "memory");
    };
    fillkv(0, 0);   // Q cp.asyncs ride this group

    float m0 = -INFINITY, m1 = -INFINITY, l0 = 0.f, l1 = 0.f;
    float o[16][4];
#pragma unroll
    for (int f = 0; f < 16; f++)
#pragma unroll
        for (int e = 0; e < 4; e++) o[f][e] = 0.f;

    const uint32_t aQ = (uint32_t)((wid * 16 + (lane & 15)) * QROW + ((lane >> 4) << 4));
    const uint32_t bK = (uint32_t)((lane & 15) * QROW + ((lane >> 4) << 4));
    const uint32_t bV = (uint32_t)((lane & 15) * VROW + ((lane >> 4) << 4));

    const int ktmax = 2 * qt + 1;

    for (int kt = 0; kt <= ktmax; kt++) {
        asm volatile("cp.async.wait_group 0;" ::: "memory");
        __syncthreads();
        if (kt < ktmax) fillkv((kt + 1) & 1, kt + 1);
        const uint32_t st = sb + SK0_OFF + (kt & 1) * KSTG;

        // ---- scores: 2-term split (QhKh + QlKh) ----
        float s[8][4];
#pragma unroll
        for (int f = 0; f < 8; f++)
#pragma unroll
            for (int e = 0; e < 4; e++) s[f][e] = 0.f;

#pragma unroll
        for (int ks = 0; ks < 8; ks++) {
            const uint32_t ko = ks * 32;
            uint32_t qh4[4], ql4[4], kh4[4][4];
            ldsm4(sb + SQH_OFF + aQ + ko, qh4[0], qh4[1], qh4[2], qh4[3]);
            ldsm4(sb + SQL_OFF + aQ + ko, ql4[0], ql4[1], ql4[2], ql4[3]);
#pragma unroll
            for (int nb = 0; nb < 4; nb++)
                ldsm4(st + bK + nb * (16 * QROW) + ko,
                      kh4[nb][0], kh4[nb][1], kh4[nb][2], kh4[nb][3]);
#pragma unroll
            for (int nb = 0; nb < 4; nb++) {
                mma16816(s[nb * 2],     qh4, kh4[nb][0], kh4[nb][2]);
                mma16816(s[nb * 2 + 1], qh4, kh4[nb][1], kh4[nb][3]);
            }
#pragma unroll
            for (int nb = 0; nb < 4; nb++) {
                mma16816(s[nb * 2],     ql4, kh4[nb][0], kh4[nb][2]);
                mma16816(s[nb * 2 + 1], ql4, kh4[nb][1], kh4[nb][3]);
            }
        }

        // restore true scale (Q was *32, 1/sqrt(D) not yet applied)
#pragma unroll
        for (int f = 0; f < 8; f++)
#pragma unroll
            for (int e = 0; e < 4; e++) s[f][e] *= SFIX;

        // ---- causal mask (needed only on the last two tiles) ----
        if (kt >= 2 * qt) {
            const int r0 = qt * 128 + wid * 16 + (lane >> 2);
            const int r1 = r0 + 8;
#pragma unroll
            for (int f = 0; f < 8; f++) {
                const int c0 = kt * 64 + f * 8 + (lane & 3) * 2;
                if (c0     > r0) s[f][0] = -INFINITY;
                if (c0 + 1 > r0) s[f][1] = -INFINITY;
                if (c0     > r1) s[f][2] = -INFINITY;
                if (c0 + 1 > r1) s[f][3] = -INFINITY;
            }
        }

        // ---- online softmax (P scaled by 2^PBIAS; cancels in O/l) ----
        float a0 = -INFINITY, a1 = -INFINITY;
#pragma unroll
        for (int f = 0; f < 8; f++) {
            a0 = fmaxf(a0, fmaxf(s[f][0], s[f][1]));
            a1 = fmaxf(a1, fmaxf(s[f][2], s[f][3]));
        }
        a0 = fmaxf(a0, __shfl_xor_sync(0xffffffffu, a0, 1));
        a0 = fmaxf(a0, __shfl_xor_sync(0xffffffffu, a0, 2));
        a1 = fmaxf(a1, __shfl_xor_sync(0xffffffffu, a1, 1));
        a1 = fmaxf(a1, __shfl_xor_sync(0xffffffffu, a1, 2));
        const float mn0 = fmaxf(m0, a0), mn1 = fmaxf(m1, a1);
        const float sc0 = exp2f((m0 - mn0) * LOG2E);
        const float sc1 = exp2f((m1 - mn1) * LOG2E);
        float rs0 = 0.f, rs1 = 0.f;
#pragma unroll
        for (int f = 0; f < 8; f++) {
            s[f][0] = exp2f((s[f][0] - mn0) * LOG2E + PBIAS);
            s[f][1] = exp2f((s[f][1] - mn0) * LOG2E + PBIAS);
            s[f][2] = exp2f((s[f][2] - mn1) * LOG2E + PBIAS);
            s[f][3] = exp2f((s[f][3] - mn1) * LOG2E + PBIAS);
            rs0 += s[f][0] + s[f][1];
            rs1 += s[f][2] + s[f][3];
        }
        rs0 += __shfl_xor_sync(0xffffffffu, rs0, 1);
        rs0 += __shfl_xor_sync(0xffffffffu, rs0, 2);
        rs1 += __shfl_xor_sync(0xffffffffu, rs1, 1);
        rs1 += __shfl_xor_sync(0xffffffffu, rs1, 2);
        m0 = mn0; m1 = mn1;
        l0 = l0 * sc0 + rs0;
        l1 = l1 * sc1 + rs1;
#pragma unroll
        for (int f = 0; f < 16; f++) {
            o[f][0] *= sc0; o[f][1] *= sc0;
            o[f][2] *= sc1; o[f][3] *= sc1;
        }

        // ---- pack P into hi/lo A-frags ----
        uint32_t ph[4][4], pl[4][4];
#pragma unroll
        for (int kb = 0; kb < 4; kb++) {
            split2h(s[2 * kb][0],     s[2 * kb][1],     ph[kb][0], pl[kb][0]);
            split2h(s[2 * kb][2],     s[2 * kb][3],     ph[kb][1], pl[kb][1]);
            split2h(s[2 * kb + 1][0], s[2 * kb + 1][1], ph[kb][2], pl[kb][2]);
            split2h(s[2 * kb + 1][2], s[2 * kb + 1][3], ph[kb][3], pl[kb][3]);
        }

        // ---- PV: 2-term (PhVh + PlVh) ----
#pragma unroll
        for (int kb = 0; kb < 4; kb++) {
            const uint32_t ko = kb * 32;
            uint32_t vh4[8][4];
#pragma unroll
            for (int nb = 0; nb < 8; nb++)
                ldsm4(st + VH_SOFF + bV + nb * (16 * VROW) + ko,
                      vh4[nb][0], vh4[nb][1], vh4[nb][2], vh4[nb][3]);
#pragma unroll
            for (int nb = 0; nb < 8; nb++) {
                mma16816(o[nb * 2],     ph[kb], vh4[nb][0], vh4[nb][2]);
                mma16816(o[nb * 2 + 1], ph[kb], vh4[nb][1], vh4[nb][3]);
            }
#pragma unroll
            for (int nb = 0; nb < 8; nb++) {
                mma16816(o[nb * 2],     pl[kb], vh4[nb][0], vh4[nb][2]);
                mma16816(o[nb * 2 + 1], pl[kb], vh4[nb][1], vh4[nb][3]);
            }
        }
    }

    // ---- epilogue: O*256/l (pre-scaled for O-proj), write fp16 hi/lo ----
    const float i0 = ASCALE / l0, i1 = ASCALE / l1;
    const int gr0 = qt * 128 + wid * 16 + (lane >> 2);
#pragma unroll
    for (int f = 0; f < 16; f++) {
        const int d0 = f * 8 + (lane & 3) * 2;
        const size_t ix0 = ((size_t)(b * S + gr0) * NH + h) * D + d0;
        const size_t ix1 = ((size_t)(b * S + gr0 + 8) * NH + h) * D + d0;
        uint32_t hi, lo;
        split2h(o[f][0] * i0, o[f][1] * i0, hi, lo);
        *(uint32_t*)(g_aoh + ix0) = hi; *(uint32_t*)(g_aol + ix0) = lo;
        split2h(o[f][2] * i1, o[f][3] * i1, hi, lo);
        *(uint32_t*)(g_aoh + ix1) = hi; *(uint32_t*)(g_aol + ix1) = lo;
    }
}

// ============================================================================
// host launcher
// ============================================================================
extern "C" void kernel_launch(void* const* d_in, const int* in_sizes, int n_in,
                              void* d_out, int out_size)
{
    const float* hidden = (const float*)d_in[0];
    const float* cosb   = (const float*)d_in[1];
    const float* sinb   = (const float*)d_in[2];
    const float* Wq     = (const float*)d_in[3];
    const float* Wk     = (const float*)d_in[4];
    const float* Wv     = (const float*)d_in[5];
    const float* Wo     = (const float*)d_in[6];
    const float* qw     = (const float*)d_in[7];
    const float* kw     = (const float*)d_in[8];
    float* out = (float*)d_out;

    __half *xh, *xl, *wh, *woh, *aoh, *aol;
    float* qkv;
    cudaGetSymbolAddress((void**)&xh,  g_xh);
    cudaGetSymbolAddress((void**)&xl,  g_xl);
    cudaGetSymbolAddress((void**)&wh,  g_wh);
    cudaGetSymbolAddress((void**)&woh, g_woh);
    cudaGetSymbolAddress((void**)&aoh, g_aoh);
    cudaGetSymbolAddress((void**)&aol, g_aol);
    cudaGetSymbolAddress((void**)&qkv, g_qkv);

    cudaFuncSetAttribute(gemm_mma, cudaFuncAttributeMaxDynamicSharedMemorySize, GSMEM);
    cudaFuncSetAttribute(flash_mma, cudaFuncAttributeMaxDynamicSharedMemorySize, FSMEM);

    // conversions
    {
        int n4;
        n4 = MSEQ * H / 4;
        split_fp32<<<(n4 + 255) / 256, 256>>>(hidden, xh, xl, ASCALE, n4);
        n4 = NH * D * H / 4;
        cvt_fp32<<<(n4 + 255) / 256, 256>>>(Wq, wh, n4);
        n4 = NKV * D * H / 4;
        cvt_fp32<<<(n4 + 255) / 256, 256>>>(Wk, wh + (size_t)NH * D * H, n4);
        cvt_fp32<<<(n4 + 255) / 256, 256>>>(Wv, wh + (size_t)(NH + NKV) * D * H, n4);
        n4 = H * NH * D / 4;
        cvt_fp32<<<(n4 + 255) / 256, 256>>>(Wo, woh, n4);
    }

    // fused QKV projection: [2048, 6144] = (X*256)[2048,4096] * Wqkv^T / 256
    gemm_mma<<<dim3(NQKV / 128, MSEQ / 128), 256, GSMEM>>>(
        xh, xl, wh, qkv, AINV, MSEQ, NQKV, H);

    // norm + rope + fp16 pack (v transposed)
    qkv_post<<<dim3(MSEQ, NH + 2 * NKV), 128>>>(cosb, sinb, qw, kw);

    // causal flash attention on tensor cores
    flash_mma<<<dim3(S / 128, B * NH), 256, FSMEM>>>();

    // output projection: [2048, 4096] = (AO*256)[2048,4096] * Wo^T / 256
    gemm_mma<<<dim3(H / 128, MSEQ / 128), 256, GSMEM>>>(
        aoh, aol, woh, out, AINV, MSEQ, H, NH * D);
}

// round 7
// speedup vs baseline: 4.1023x; 1.1358x over previous
#include <cuda_runtime.h>
#include <cuda_fp16.h>
#include <math.h>
#include <stdint.h>

// ---------------- problem constants ----------------
#define B   2
#define S   1024
#define H   4096
#define NH  32
#define NKV 8
#define D   128
#define GROUPS (NH / NKV)   // 4
#define EPS 1e-6f
#define QSCALE 0.08838834764831845f   // 1/sqrt(128)
#define MSEQ (B * S)        // 2048 rows
#define NQKV ((NH + 2 * NKV) * D)   // 6144
#define LOG2E 1.4426950408889634f
#define ASCALE 256.0f
#define AINV   (1.0f / 256.0f)
#define QSC    32.0f
#define SFIX   (QSCALE / 32.0f)
#define PBIAS  12.0f                 // P scaled by 2^12 (cancels in O/l)

// ---------------- scratch (device globals, fp16) ----------------
__device__ __align__(16) __half g_xh [MSEQ * H];       // hidden*256 hi
__device__ __align__(16) __half g_xl [MSEQ * H];       // hidden*256 lo
__device__ __align__(16) __half g_wh [NQKV * H];       // stacked Wq|Wk|Wv (hi only)
__device__ __align__(16) __half g_woh[H * NH * D];     // Wo (hi only)
__device__ __align__(16) __half g_aoh[MSEQ * NH * D];  // attn out *256 hi
__device__ __align__(16) __half g_aol[MSEQ * NH * D];  // attn out *256 lo
__device__ float g_qkv[MSEQ * NQKV];
// flash inputs: q*32 hi/lo row-major, k hi row-major, v row-major + transposed
__device__ __align__(16) __half g_qh [B * NH  * S * D];
__device__ __align__(16) __half g_ql [B * NH  * S * D];
__device__ __align__(16) __half g_kh [B * NKV * S * D];
__device__ __align__(16) __half g_vrow[B * NKV * S * D];   // [B,NKV,S,D]
__device__ __align__(16) __half g_vth [B * NKV * D * S];   // [B,NKV,D,S]

// ---------------- small helpers ----------------
__device__ __forceinline__ void cp16(uint32_t dst, const void* src) {
    asm volatile("cp.async.cg.shared.global [%0], [%1], 16;" :: "r"(dst), "l"(src) : "memory");
}
__device__ __forceinline__ void ldsm4(uint32_t addr, uint32_t& r0, uint32_t& r1,
                                      uint32_t& r2, uint32_t& r3) {
    asm volatile("ldmatrix.sync.aligned.m8n8.x4.shared.b16 {%0,%1,%2,%3}, [%4];"
        : "=r"(r0), "=r"(r1), "=r"(r2), "=r"(r3) : "r"(addr));
}
__device__ __forceinline__ void mma16816(float* c, const uint32_t* a,
                                         uint32_t b0, uint32_t b1) {
    asm volatile("mma.sync.aligned.m16n8k16.row.col.f32.f16.f16.f32 "
        "{%0,%1,%2,%3}, {%4,%5,%6,%7}, {%8,%9}, {%0,%1,%2,%3};"
        : "+f"(c[0]), "+f"(c[1]), "+f"(c[2]), "+f"(c[3])
        : "r"(a[0]), "r"(a[1]), "r"(a[2]), "r"(a[3]), "r"(b0), "r"(b1));
}
__device__ __forceinline__ void split1h(float v, __half& h, __half& l) {
    h = __float2half(v);
    l = __float2half(v - __half2float(h));
}
__device__ __forceinline__ void split2h(float a, float b, uint32_t& hi, uint32_t& lo) {
    __half2 hv, lv;
    split1h(a, hv.x, lv.x);
    split1h(b, hv.y, lv.y);
    hi = *(uint32_t*)&hv;
    lo = *(uint32_t*)&lv;
}

// ============================================================================
// fp32 -> fp16 hi/lo split with scale
// ============================================================================
__global__ void __launch_bounds__(256) split_fp32(
    const float* __restrict__ src, __half* __restrict__ hi,
    __half* __restrict__ lo, float scale, int n4)
{
    int i = blockIdx.x * 256 + threadIdx.x;
    if (i >= n4) return;
    float4 x = ((const float4*)src)[i];
    __half2 hv0, hv1, lv0, lv1;
    split1h(x.x * scale, hv0.x, lv0.x);
    split1h(x.y * scale, hv0.y, lv0.y);
    split1h(x.z * scale, hv1.x, lv1.x);
    split1h(x.w * scale, hv1.y, lv1.y);
    ((__half2*)hi)[2 * i]     = hv0;
    ((__half2*)hi)[2 * i + 1] = hv1;
    ((__half2*)lo)[2 * i]     = lv0;
    ((__half2*)lo)[2 * i + 1] = lv1;
}

// all four weight matrices -> fp16 in one launch
#define N4Q (NH * D * H / 4)           // 4194304
#define N4K (NKV * D * H / 4)          // 1048576
#define N4ALL (N4Q + 2 * N4K + N4Q)    // Wq,Wk,Wv,Wo

__global__ void __launch_bounds__(256) cvt_weights(
    const float* __restrict__ Wq, const float* __restrict__ Wk,
    const float* __restrict__ Wv, const float* __restrict__ Wo)
{
    int i = blockIdx.x * 256 + threadIdx.x;
    if (i >= N4ALL) return;
    const float* src;
    __half* dst;
    int j = i;
    if (j < N4Q)                { src = Wq; dst = g_wh; }
    else if ((j -= N4Q) < N4K)  { src = Wk; dst = g_wh + (size_t)NH * D * H; }
    else if ((j -= N4K) < N4K)  { src = Wv; dst = g_wh + (size_t)(NH + NKV) * D * H; }
    else { j -= N4K;              src = Wo; dst = g_woh; }
    float4 x = ((const float4*)src)[j];
    ((__half2*)dst)[2 * j]     = __floats2half2_rn(x.x, x.y);
    ((__half2*)dst)[2 * j + 1] = __floats2half2_rn(x.z, x.w);
}

// ============================================================================
// mma.sync split-fp16 NT GEMM: C[M,N] = alpha*(Ah+Al)[M,K]*Bh[N,K]^T (2 terms)
// Block tile 128x128x32, 8 warps (4m x 2n), warp tile 32x64.
// 3-stage cp.async ring, ONE __syncthreads per K-tile, 2 CTAs/SM.
// ============================================================================
#define ROWB 80                        // bytes per 32-fp16 row (padded)
#define MATB (128 * ROWB)              // 10240 per matrix tile
#define STGB (3 * MATB)                // Ah|Al|Bh = 30720 per stage
#define GSMEM (3 * STGB)               // 92160

__global__ void __launch_bounds__(256, 2) gemm_mma(
    const __half* __restrict__ Ah, const __half* __restrict__ Al,
    const __half* __restrict__ Bh, float* __restrict__ C,
    float alpha, int M, int N, int K)
{
    extern __shared__ __align__(128) char smem[];
    const uint32_t sbase = (uint32_t)__cvta_generic_to_shared(smem);
    const int tid  = threadIdx.x;
    const int lane = tid & 31;
    const int wid  = tid >> 5;
    const int warp_m = wid >> 1;   // 0..3 (32 rows each)
    const int warp_n = wid & 1;    // 0..1 (64 cols each)
    const int m0 = blockIdx.y * 128;
    const int n0 = blockIdx.x * 128;
    const int KT = K >> 5;         // K / 32

    float acc[2][8][4];
#pragma unroll
    for (int i = 0; i < 2; i++)
#pragma unroll
        for (int j = 0; j < 8; j++)
#pragma unroll
            for (int q = 0; q < 4; q++) acc[i][j][q] = 0.f;

    auto fill = [&](int s, int kt) {
        const uint32_t st = sbase + s * STGB;
#pragma unroll
        for (int i = 0; i < 6; i++) {
            const int v = ((i & 1) << 8) + tid;    // 0..511 within matrix
            const int r = v >> 2, c = v & 3;
            const __half* gb = (i < 2) ? Ah : (i < 4) ? Al : Bh;
            const int grow = ((i < 4) ? m0 : n0) + r;
            cp16(st + (i >> 1) * MATB + r * ROWB + c * 16,
                 gb + (size_t)grow * K + (size_t)kt * 32 + c * 8);
        }
        asm volatile("cp.async.commit_group;" ::: "memory");
    };

    fill(0, 0); fill(1, 1); fill(2, 2);

    const uint32_t aOff = (uint32_t)((warp_m * 32 + (lane & 15)) * ROWB + ((lane >> 4) << 4));
    const uint32_t bOff = (uint32_t)(2 * MATB + (warp_n * 64 + (lane & 15)) * ROWB + ((lane >> 4) << 4));

    for (int kt = 0; kt < KT; kt++) {
        asm volatile("cp.async.wait_group 1;" ::: "memory");
        __syncthreads();     // all warps done with iter kt-1 -> slot (kt-1)%3 free
        if (kt >= 1) {
            const int t = kt + 2;
            if (t < KT) fill(t % 3, t);
            else asm volatile("cp.async.commit_group;" ::: "memory");  // keep group count
        }

        const uint32_t st = sbase + (kt % 3) * STGB;
#pragma unroll
        for (int k16 = 0; k16 < 2; k16++) {
            const uint32_t ko = k16 * 32;
            uint32_t a[2][4], al[2][4], bh[4][4];
#pragma unroll
            for (int mi = 0; mi < 2; mi++) {
                ldsm4(st + aOff + mi * (16 * ROWB) + ko,
                      a[mi][0], a[mi][1], a[mi][2], a[mi][3]);
                ldsm4(st + MATB + aOff + mi * (16 * ROWB) + ko,
                      al[mi][0], al[mi][1], al[mi][2], al[mi][3]);
            }
#pragma unroll
            for (int ni = 0; ni < 4; ni++)
                ldsm4(st + bOff + ni * (16 * ROWB) + ko,
                      bh[ni][0], bh[ni][1], bh[ni][2], bh[ni][3]);
            // pass 1: Ah*Bh (16 independent MMAs)
#pragma unroll
            for (int mi = 0; mi < 2; mi++)
#pragma unroll
                for (int ni = 0; ni < 4; ni++) {
                    mma16816(acc[mi][ni * 2],     a[mi], bh[ni][0], bh[ni][2]);
                    mma16816(acc[mi][ni * 2 + 1], a[mi], bh[ni][1], bh[ni][3]);
                }
            // pass 2: Al*Bh
#pragma unroll
            for (int mi = 0; mi < 2; mi++)
#pragma unroll
                for (int ni = 0; ni < 4; ni++) {
                    mma16816(acc[mi][ni * 2],     al[mi], bh[ni][0], bh[ni][2]);
                    mma16816(acc[mi][ni * 2 + 1], al[mi], bh[ni][1], bh[ni][3]);
                }
        }
    }

#pragma unroll
    for (int mi = 0; mi < 2; mi++) {
        const int row = m0 + warp_m * 32 + mi * 16 + (lane >> 2);
#pragma unroll
        for (int nj = 0; nj < 8; nj++) {
            const int col = n0 + warp_n * 64 + nj * 8 + (lane & 3) * 2;
            float* cp0 = C + (size_t)row * N + col;
            float* cp1 = C + (size_t)(row + 8) * N + col;
            *(float2*)cp0 = make_float2(acc[mi][nj][0] * alpha, acc[mi][nj][1] * alpha);
            *(float2*)cp1 = make_float2(acc[mi][nj][2] * alpha, acc[mi][nj][3] * alpha);
        }
    }
}

// ============================================================================
// Per-head RMSNorm + RoPE; q -> fp16 hi/lo (*32), k -> fp16, v -> fp16 row-major
// grid: (B*S, 48), block 128.
// ============================================================================
__global__ void __launch_bounds__(128) qkv_post(
    const float* __restrict__ cosb, const float* __restrict__ sinb,
    const float* __restrict__ qw,   const float* __restrict__ kw)
{
    const int bs = blockIdx.x;
    const int hh = blockIdx.y;
    const int d  = threadIdx.x;
    const int b  = bs / S;
    const int s  = bs - b * S;

    __shared__ float xs[D];
    __shared__ float red[4];

    float x = g_qkv[(size_t)bs * NQKV + hh * D + d];

    if (hh < NH + NKV) {
        float ss = x * x;
#pragma unroll
        for (int o = 16; o; o >>= 1) ss += __shfl_xor_sync(0xffffffffu, ss, o);
        if ((d & 31) == 0) red[d >> 5] = ss;
        __syncthreads();
        const float var = (red[0] + red[1] + red[2] + red[3]) * (1.0f / D);
        const float w = (hh < NH) ? qw[d] : kw[d];
        x = x * rsqrtf(var + EPS) * w;
        xs[d] = x;
        __syncthreads();
        const float c  = cosb[(size_t)bs * D + d];
        const float sn = sinb[(size_t)bs * D + d];
        const float part = (d < 64) ? -xs[d + 64] : xs[d - 64];
        x = x * c + part * sn;
    }

    if (hh < NH) {
        __half hi, lo;
        split1h(x * QSC, hi, lo);
        const size_t idx = (((size_t)b * NH + hh) * S + s) * D + d;
        g_qh[idx] = hi; g_ql[idx] = lo;
    } else if (hh < NH + NKV) {
        const size_t idx = (((size_t)b * NKV + (hh - NH)) * S + s) * D + d;
        g_kh[idx] = __float2half(x);
    } else {
        const size_t idx = (((size_t)b * NKV + (hh - NH - NKV)) * S + s) * D + d;
        g_vrow[idx] = __float2half(x);
    }
}

// ============================================================================
// Tiled transpose: g_vrow [B,NKV,S,D] -> g_vth [B,NKV,D,S]. 64x64 fp16 tiles.
// grid (S/64, D/64, B*NKV), block 256.
// ============================================================================
__global__ void __launch_bounds__(256) v_transpose()
{
    __shared__ __half tile[64][72];
    const int s0 = blockIdx.x * 64;
    const int d0 = blockIdx.y * 64;
    const size_t base = (size_t)blockIdx.z;
    const int tid = threadIdx.x;
    const __half* src = g_vrow + base * S * D;
    __half* dst = g_vth + base * D * S;

    // load: 64 rows (s) x 64 cols (d); 16 chunks of 4 fp16 per row
#pragma unroll
    for (int i = tid; i < 1024; i += 256) {
        const int r = i >> 4, c4 = (i & 15) << 2;
        *(uint64_t*)&tile[r][c4] = *(const uint64_t*)(src + (size_t)(s0 + r) * D + d0 + c4);
    }
    __syncthreads();
    // store: 64 rows (d) x 64 cols (s), coalesced in s
#pragma unroll
    for (int i = tid; i < 1024; i += 256) {
        const int r = i >> 4, c4 = (i & 15) << 2;
        __half2 p0, p1;
        p0.x = tile[c4 + 0][r]; p0.y = tile[c4 + 1][r];
        p1.x = tile[c4 + 2][r]; p1.y = tile[c4 + 3][r];
        *(__half2*)(dst + (size_t)(d0 + r) * S + s0 + c4)     = p0;
        *(__half2*)(dst + (size_t)(d0 + r) * S + s0 + c4 + 2) = p1;
    }
}

// ============================================================================
// Causal flash attention, fp16 2-term (QhKh+QlKh; PhVh+PlVh).
// BM=128, BN=64, 8 warps (256 threads), warp owns 16 q-rows.
// 2-stage KV pipeline.
// ============================================================================
#define QROW 272                       // 128 fp16 + 8 pad
#define VROW 144                       // 64 fp16 + 8 pad
#define SQH_OFF 0
#define SQL_OFF (128 * QROW)           // 34816
#define SK0_OFF (2 * 128 * QROW)       // 69632
#define VH_SOFF (64 * QROW)            // Vh within stage (17408)
#define KSTG    (VH_SOFF + 128 * VROW) // 35840
#define FSMEM   (SK0_OFF + 2 * KSTG)   // 141312

__global__ void __launch_bounds__(256) flash_mma()
{
    extern __shared__ __align__(128) char fsm[];
    const uint32_t sb = (uint32_t)__cvta_generic_to_shared(fsm);
    const int tid = threadIdx.x, lane = tid & 31, wid = tid >> 5;
    const int qt = (int)gridDim.x - 1 - (int)blockIdx.x;   // heavy CTAs first
    const int bh = blockIdx.y;
    const int b = bh / NH, h = bh - b * NH;
    const int kvh = h / GROUPS;

    const __half* Qhp = g_qh + (((size_t)b * NH + h) * S + (size_t)qt * 128) * D;
    const __half* Qlp = g_ql + (((size_t)b * NH + h) * S + (size_t)qt * 128) * D;
    const __half* Khp = g_kh + ((size_t)b * NKV + kvh) * S * D;
    const __half* Vhp = g_vth + ((size_t)b * NKV + kvh) * D * S;

    // Q tiles (loaded once): 128 rows x 128 fp16, hi+lo
#pragma unroll
    for (int i = tid; i < 2048; i += 256) {
        const int r = i >> 4, c = i & 15;
        cp16(sb + SQH_OFF + r * QROW + c * 16, Qhp + r * D + c * 8);
        cp16(sb + SQL_OFF + r * QROW + c * 16, Qlp + r * D + c * 8);
    }

    auto fillkv = [&](int slot, int kt) {
        const uint32_t st = sb + SK0_OFF + slot * KSTG;
        const __half* kh_ = Khp + (size_t)kt * 64 * D;
#pragma unroll
        for (int i = tid; i < 1024; i += 256) {
            const int r = i >> 4, c = i & 15;
            cp16(st + r * QROW + c * 16, kh_ + r * D + c * 8);
        }
        const __half* vh_ = Vhp + (size_t)kt * 64;
#pragma unroll
        for (int i = tid; i < 1024; i += 256) {
            const int r = i >> 3, c = i & 7;
            cp16(st + VH_SOFF + r * VROW + c * 16, vh_ + (size_t)r * S + c * 8);
        }
        asm volatile("cp.async.commit_group;" ::: "memory");
    };
    fillkv(0, 0);   // Q cp.asyncs ride this group

    float m0 = -INFINITY, m1 = -INFINITY, l0 = 0.f, l1 = 0.f;
    float o[16][4];
#pragma unroll
    for (int f = 0; f < 16; f++)
#pragma unroll
        for (int e = 0; e < 4; e++) o[f][e] = 0.f;

    const uint32_t aQ = (uint32_t)((wid * 16 + (lane & 15)) * QROW + ((lane >> 4) << 4));
    const uint32_t bK = (uint32_t)((lane & 15) * QROW + ((lane >> 4) << 4));
    const uint32_t bV = (uint32_t)((lane & 15) * VROW + ((lane >> 4) << 4));

    const int ktmax = 2 * qt + 1;

    for (int kt = 0; kt <= ktmax; kt++) {
        asm volatile("cp.async.wait_group 0;" ::: "memory");
        __syncthreads();
        if (kt < ktmax) fillkv((kt + 1) & 1, kt + 1);
        const uint32_t st = sb + SK0_OFF + (kt & 1) * KSTG;

        // ---- scores: 2-term split (QhKh + QlKh) ----
        float s[8][4];
#pragma unroll
        for (int f = 0; f < 8; f++)
#pragma unroll
            for (int e = 0; e < 4; e++) s[f][e] = 0.f;

#pragma unroll
        for (int ks = 0; ks < 8; ks++) {
            const uint32_t ko = ks * 32;
            uint32_t qh4[4], ql4[4], kh4[4][4];
            ldsm4(sb + SQH_OFF + aQ + ko, qh4[0], qh4[1], qh4[2], qh4[3]);
            ldsm4(sb + SQL_OFF + aQ + ko, ql4[0], ql4[1], ql4[2], ql4[3]);
#pragma unroll
            for (int nb = 0; nb < 4; nb++)
                ldsm4(st + bK + nb * (16 * QROW) + ko,
                      kh4[nb][0], kh4[nb][1], kh4[nb][2], kh4[nb][3]);
#pragma unroll
            for (int nb = 0; nb < 4; nb++) {
                mma16816(s[nb * 2],     qh4, kh4[nb][0], kh4[nb][2]);
                mma16816(s[nb * 2 + 1], qh4, kh4[nb][1], kh4[nb][3]);
            }
#pragma unroll
            for (int nb = 0; nb < 4; nb++) {
                mma16816(s[nb * 2],     ql4, kh4[nb][0], kh4[nb][2]);
                mma16816(s[nb * 2 + 1], ql4, kh4[nb][1], kh4[nb][3]);
            }
        }

        // restore true scale (Q was *32, 1/sqrt(D) not yet applied)
#pragma unroll
        for (int f = 0; f < 8; f++)
#pragma unroll
            for (int e = 0; e < 4; e++) s[f][e] *= SFIX;

        // ---- causal mask (needed only on the last two tiles) ----
        if (kt >= 2 * qt) {
            const int r0 = qt * 128 + wid * 16 + (lane >> 2);
            const int r1 = r0 + 8;
#pragma unroll
            for (int f = 0; f < 8; f++) {
                const int c0 = kt * 64 + f * 8 + (lane & 3) * 2;
                if (c0     > r0) s[f][0] = -INFINITY;
                if (c0 + 1 > r0) s[f][1] = -INFINITY;
                if (c0     > r1) s[f][2] = -INFINITY;
                if (c0 + 1 > r1) s[f][3] = -INFINITY;
            }
        }

        // ---- online softmax (P scaled by 2^PBIAS; cancels in O/l) ----
        float a0 = -INFINITY, a1 = -INFINITY;
#pragma unroll
        for (int f = 0; f < 8; f++) {
            a0 = fmaxf(a0, fmaxf(s[f][0], s[f][1]));
            a1 = fmaxf(a1, fmaxf(s[f][2], s[f][3]));
        }
        a0 = fmaxf(a0, __shfl_xor_sync(0xffffffffu, a0, 1));
        a0 = fmaxf(a0, __shfl_xor_sync(0xffffffffu, a0, 2));
        a1 = fmaxf(a1, __shfl_xor_sync(0xffffffffu, a1, 1));
        a1 = fmaxf(a1, __shfl_xor_sync(0xffffffffu, a1, 2));
        const float mn0 = fmaxf(m0, a0), mn1 = fmaxf(m1, a1);
        const float sc0 = exp2f((m0 - mn0) * LOG2E);
        const float sc1 = exp2f((m1 - mn1) * LOG2E);
        float rs0 = 0.f, rs1 = 0.f;
#pragma unroll
        for (int f = 0; f < 8; f++) {
            s[f][0] = exp2f((s[f][0] - mn0) * LOG2E + PBIAS);
            s[f][1] = exp2f((s[f][1] - mn0) * LOG2E + PBIAS);
            s[f][2] = exp2f((s[f][2] - mn1) * LOG2E + PBIAS);
            s[f][3] = exp2f((s[f][3] - mn1) * LOG2E + PBIAS);
            rs0 += s[f][0] + s[f][1];
            rs1 += s[f][2] + s[f][3];
        }
        rs0 += __shfl_xor_sync(0xffffffffu, rs0, 1);
        rs0 += __shfl_xor_sync(0xffffffffu, rs0, 2);
        rs1 += __shfl_xor_sync(0xffffffffu, rs1, 1);
        rs1 += __shfl_xor_sync(0xffffffffu, rs1, 2);
        m0 = mn0; m1 = mn1;
        l0 = l0 * sc0 + rs0;
        l1 = l1 * sc1 + rs1;
#pragma unroll
        for (int f = 0; f < 16; f++) {
            o[f][0] *= sc0; o[f][1] *= sc0;
            o[f][2] *= sc1; o[f][3] *= sc1;
        }

        // ---- pack P into hi/lo A-frags ----
        uint32_t ph[4][4], pl[4][4];
#pragma unroll
        for (int kb = 0; kb < 4; kb++) {
            split2h(s[2 * kb][0],     s[2 * kb][1],     ph[kb][0], pl[kb][0]);
            split2h(s[2 * kb][2],     s[2 * kb][3],     ph[kb][1], pl[kb][1]);
            split2h(s[2 * kb + 1][0], s[2 * kb + 1][1], ph[kb][2], pl[kb][2]);
            split2h(s[2 * kb + 1][2], s[2 * kb + 1][3], ph[kb][3], pl[kb][3]);
        }

        // ---- PV: 2-term (PhVh + PlVh) ----
#pragma unroll
        for (int kb = 0; kb < 4; kb++) {
            const uint32_t ko = kb * 32;
            uint32_t vh4[8][4];
#pragma unroll
            for (int nb = 0; nb < 8; nb++)
                ldsm4(st + VH_SOFF + bV + nb * (16 * VROW) + ko,
                      vh4[nb][0], vh4[nb][1], vh4[nb][2], vh4[nb][3]);
#pragma unroll
            for (int nb = 0; nb < 8; nb++) {
                mma16816(o[nb * 2],     ph[kb], vh4[nb][0], vh4[nb][2]);
                mma16816(o[nb * 2 + 1], ph[kb], vh4[nb][1], vh4[nb][3]);
            }
#pragma unroll
            for (int nb = 0; nb < 8; nb++) {
                mma16816(o[nb * 2],     pl[kb], vh4[nb][0], vh4[nb][2]);
                mma16816(o[nb * 2 + 1], pl[kb], vh4[nb][1], vh4[nb][3]);
            }
        }
    }

    // ---- epilogue: O*256/l (pre-scaled for O-proj), write fp16 hi/lo ----
    const float i0 = ASCALE / l0, i1 = ASCALE / l1;
    const int gr0 = qt * 128 + wid * 16 + (lane >> 2);
#pragma unroll
    for (int f = 0; f < 16; f++) {
        const int d0 = f * 8 + (lane & 3) * 2;
        const size_t ix0 = ((size_t)(b * S + gr0) * NH + h) * D + d0;
        const size_t ix1 = ((size_t)(b * S + gr0 + 8) * NH + h) * D + d0;
        uint32_t hi, lo;
        split2h(o[f][0] * i0, o[f][1] * i0, hi, lo);
        *(uint32_t*)(g_aoh + ix0) = hi; *(uint32_t*)(g_aol + ix0) = lo;
        split2h(o[f][2] * i1, o[f][3] * i1, hi, lo);
        *(uint32_t*)(g_aoh + ix1) = hi; *(uint32_t*)(g_aol + ix1) = lo;
    }
}

// ============================================================================
// host launcher
// ============================================================================
extern "C" void kernel_launch(void* const* d_in, const int* in_sizes, int n_in,
                              void* d_out, int out_size)
{
    const float* hidden = (const float*)d_in[0];
    const float* cosb   = (const float*)d_in[1];
    const float* sinb   = (const float*)d_in[2];
    const float* Wq     = (const float*)d_in[3];
    const float* Wk     = (const float*)d_in[4];
    const float* Wv     = (const float*)d_in[5];
    const float* Wo     = (const float*)d_in[6];
    const float* qw     = (const float*)d_in[7];
    const float* kw     = (const float*)d_in[8];
    float* out = (float*)d_out;

    __half *xh, *xl, *wh, *woh, *aoh, *aol;
    float* qkv;
    cudaGetSymbolAddress((void**)&xh,  g_xh);
    cudaGetSymbolAddress((void**)&xl,  g_xl);
    cudaGetSymbolAddress((void**)&wh,  g_wh);
    cudaGetSymbolAddress((void**)&woh, g_woh);
    cudaGetSymbolAddress((void**)&aoh, g_aoh);
    cudaGetSymbolAddress((void**)&aol, g_aol);
    cudaGetSymbolAddress((void**)&qkv, g_qkv);

    cudaFuncSetAttribute(gemm_mma, cudaFuncAttributeMaxDynamicSharedMemorySize, GSMEM);
    cudaFuncSetAttribute(flash_mma, cudaFuncAttributeMaxDynamicSharedMemorySize, FSMEM);

    // conversions (2 launches)
    {
        int n4 = MSEQ * H / 4;
        split_fp32<<<(n4 + 255) / 256, 256>>>(hidden, xh, xl, ASCALE, n4);
        cvt_weights<<<(N4ALL + 255) / 256, 256>>>(Wq, Wk, Wv, Wo);
    }

    // fused QKV projection: [2048, 6144] = (X*256)[2048,4096] * Wqkv^T / 256
    gemm_mma<<<dim3(NQKV / 128, MSEQ / 128), 256, GSMEM>>>(
        xh, xl, wh, qkv, AINV, MSEQ, NQKV, H);

    // norm + rope + fp16 pack (v row-major)
    qkv_post<<<dim3(MSEQ, NH + 2 * NKV), 128>>>(cosb, sinb, qw, kw);

    // v transpose [B,NKV,S,D] -> [B,NKV,D,S]
    v_transpose<<<dim3(S / 64, D / 64, B * NKV), 256>>>();

    // causal flash attention on tensor cores
    flash_mma<<<dim3(S / 128, B * NH), 256, FSMEM>>>();

    // output projection: [2048, 4096] = (AO*256)[2048,4096] * Wo^T / 256
    gemm_mma<<<dim3(H / 128, MSEQ / 128), 256, GSMEM>>>(
        aoh, aol, woh, out, AINV, MSEQ, H, NH * D);
}

// round 9
// speedup vs baseline: 4.8417x; 1.1802x over previous
#include <cuda_runtime.h>
#include <cuda_fp16.h>
#include <math.h>
#include <stdint.h>

// ---------------- problem constants ----------------
#define B   2
#define S   1024
#define H   4096
#define NH  32
#define NKV 8
#define D   128
#define GROUPS (NH / NKV)   // 4
#define EPS 1e-6f
#define QSCALE 0.08838834764831845f   // 1/sqrt(128)
#define MSEQ (B * S)        // 2048 rows
#define NQKV ((NH + 2 * NKV) * D)   // 6144
#define LOG2E 1.4426950408889634f
#define ASCALE 256.0f
#define AINV   (1.0f / 256.0f)
#define QSC    32.0f
#define SFIX   (QSCALE / 32.0f)
#define PBIAS  12.0f                 // P scaled by 2^12 (cancels in O/l)

// ---------------- scratch (device globals, fp16) ----------------
__device__ __align__(16) __half g_xh [MSEQ * H];       // hidden*256 hi
__device__ __align__(16) __half g_xl [MSEQ * H];       // hidden*256 lo
__device__ __align__(16) __half g_wh [NQKV * H];       // stacked Wq|Wk|Wv
__device__ __align__(16) __half g_woh[H * NH * D];     // Wo
__device__ __align__(16) __half g_aoh[MSEQ * NH * D];  // attn out *256 (1 term)
__device__ float g_qkv[MSEQ * NQKV];
// flash inputs: q*32 hi/lo row-major, k hi row-major, v row-major + transposed
__device__ __align__(16) __half g_qh [B * NH  * S * D];
__device__ __align__(16) __half g_ql [B * NH  * S * D];
__device__ __align__(16) __half g_kh [B * NKV * S * D];
__device__ __align__(16) __half g_vrow[B * NKV * S * D];   // [B,NKV,S,D]
__device__ __align__(16) __half g_vth [B * NKV * D * S];   // [B,NKV,D,S]

// ---------------- small helpers ----------------
__device__ __forceinline__ void cp16(uint32_t dst, const void* src) {
    asm volatile("cp.async.cg.shared.global [%0], [%1], 16;" :: "r"(dst), "l"(src) : "memory");
}
__device__ __forceinline__ void ldsm4(uint32_t addr, uint32_t& r0, uint32_t& r1,
                                      uint32_t& r2, uint32_t& r3) {
    asm volatile("ldmatrix.sync.aligned.m8n8.x4.shared.b16 {%0,%1,%2,%3}, [%4];"
        : "=r"(r0), "=r"(r1), "=r"(r2), "=r"(r3) : "r"(addr));
}
__device__ __forceinline__ void mma16816(float* c, const uint32_t* a,
                                         uint32_t b0, uint32_t b1) {
    asm volatile("mma.sync.aligned.m16n8k16.row.col.f32.f16.f16.f32 "
        "{%0,%1,%2,%3}, {%4,%5,%6,%7}, {%8,%9}, {%0,%1,%2,%3};"
        : "+f"(c[0]), "+f"(c[1]), "+f"(c[2]), "+f"(c[3])
        : "r"(a[0]), "r"(a[1]), "r"(a[2]), "r"(a[3]), "r"(b0), "r"(b1));
}
__device__ __forceinline__ void split1h(float v, __half& h, __half& l) {
    h = __float2half(v);
    l = __float2half(v - __half2float(h));
}
__device__ __forceinline__ void split2h(float a, float b, uint32_t& hi, uint32_t& lo) {
    __half2 hv, lv;
    split1h(a, hv.x, lv.x);
    split1h(b, hv.y, lv.y);
    hi = *(uint32_t*)&hv;
    lo = *(uint32_t*)&lv;
}

// ============================================================================
// fp32 -> fp16 hi/lo split with scale
// ============================================================================
__global__ void __launch_bounds__(256) split_fp32(
    const float* __restrict__ src, __half* __restrict__ hi,
    __half* __restrict__ lo, float scale, int n4)
{
    int i = blockIdx.x * 256 + threadIdx.x;
    if (i >= n4) return;
    float4 x = ((const float4*)src)[i];
    __half2 hv0, hv1, lv0, lv1;
    split1h(x.x * scale, hv0.x, lv0.x);
    split1h(x.y * scale, hv0.y, lv0.y);
    split1h(x.z * scale, hv1.x, lv1.x);
    split1h(x.w * scale, hv1.y, lv1.y);
    ((__half2*)hi)[2 * i]     = hv0;
    ((__half2*)hi)[2 * i + 1] = hv1;
    ((__half2*)lo)[2 * i]     = lv0;
    ((__half2*)lo)[2 * i + 1] = lv1;
}

// all four weight matrices -> fp16 in one launch
#define N4Q (NH * D * H / 4)           // 4194304
#define N4K (NKV * D * H / 4)          // 1048576
#define N4ALL (N4Q + 2 * N4K + N4Q)

__global__ void __launch_bounds__(256) cvt_weights(
    const float* __restrict__ Wq, const float* __restrict__ Wk,
    const float* __restrict__ Wv, const float* __restrict__ Wo)
{
    int i = blockIdx.x * 256 + threadIdx.x;
    if (i >= N4ALL) return;
    const float* src;
    __half* dst;
    int j = i;
    if (j < N4Q)                { src = Wq; dst = g_wh; }
    else if ((j -= N4Q) < N4K)  { src = Wk; dst = g_wh + (size_t)NH * D * H; }
    else if ((j -= N4K) < N4K)  { src = Wv; dst = g_wh + (size_t)(NH + NKV) * D * H; }
    else { j -= N4K;              src = Wo; dst = g_woh; }
    float4 x = ((const float4*)src)[j];
    ((__half2*)dst)[2 * j]     = __floats2half2_rn(x.x, x.y);
    ((__half2*)dst)[2 * j + 1] = __floats2half2_rn(x.z, x.w);
}

// ============================================================================
// mma.sync fp16 NT GEMM, TERMS in {1,2}:
//   TERMS=2: C = alpha*(Ah+Al)[M,K]*Bh[N,K]^T
//   TERMS=1: C = alpha* Ah    [M,K]*Bh[N,K]^T
// Block tile 128x128x32, 8 warps (4m x 2n), warp tile 32x64.
// 3-stage cp.async ring, ONE __syncthreads per K-tile, 2 CTAs/SM.
// ============================================================================
#define ROWB 80                        // bytes per 32-fp16 row (padded)
#define MATB (128 * ROWB)              // 10240 per matrix tile
#define GSMEM2 (3 * 3 * MATB)          // 92160 (Ah|Al|Bh per stage)
#define GSMEM1 (3 * 2 * MATB)          // 61440 (Ah|Bh per stage)

template<int TERMS>
__global__ void __launch_bounds__(256, 2) gemm_mma(
    const __half* __restrict__ Ah, const __half* __restrict__ Al,
    const __half* __restrict__ Bh, float* __restrict__ C,
    float alpha, int M, int N, int K)
{
    constexpr int NMAT = TERMS + 1;
    constexpr int STGB = NMAT * MATB;
    extern __shared__ __align__(128) char smem[];
    const uint32_t sbase = (uint32_t)__cvta_generic_to_shared(smem);
    const int tid  = threadIdx.x;
    const int lane = tid & 31;
    const int wid  = tid >> 5;
    const int warp_m = wid >> 1;   // 0..3 (32 rows each)
    const int warp_n = wid & 1;    // 0..1 (64 cols each)
    const int m0 = blockIdx.y * 128;
    const int n0 = blockIdx.x * 128;
    const int KT = K >> 5;         // K / 32

    float acc[2][8][4];
#pragma unroll
    for (int i = 0; i < 2; i++)
#pragma unroll
        for (int j = 0; j < 8; j++)
#pragma unroll
            for (int q = 0; q < 4; q++) acc[i][j][q] = 0.f;

    auto fill = [&](int s, int kt) {
        const uint32_t st = sbase + s * STGB;
#pragma unroll
        for (int i = 0; i < 2 * NMAT; i++) {
            const int v = ((i & 1) << 8) + tid;    // 0..511 within matrix
            const int r = v >> 2, c = v & 3;
            const __half* gb = (i < 2) ? Ah : (i < 2 * TERMS) ? Al : Bh;
            const int grow = ((i < 2 * TERMS) ? m0 : n0) + r;
            cp16(st + (i >> 1) * MATB + r * ROWB + c * 16,
                 gb + (size_t)grow * K + (size_t)kt * 32 + c * 8);
        }
        asm volatile("cp.async.commit_group;" ::: "memory");
    };

    fill(0, 0); fill(1, 1); fill(2, 2);

    const uint32_t aOff = (uint32_t)((warp_m * 32 + (lane & 15)) * ROWB + ((lane >> 4) << 4));
    const uint32_t bOff = (uint32_t)(TERMS * MATB + (warp_n * 64 + (lane & 15)) * ROWB + ((lane >> 4) << 4));

    for (int kt = 0; kt < KT; kt++) {
        asm volatile("cp.async.wait_group 1;" ::: "memory");
        __syncthreads();     // all warps done with iter kt-1 -> slot (kt-1)%3 free
        if (kt >= 1) {
            const int t = kt + 2;
            if (t < KT) fill(t % 3, t);
            else asm volatile("cp.async.commit_group;" ::: "memory");  // keep group count
        }

        const uint32_t st = sbase + (kt % 3) * STGB;
#pragma unroll
        for (int k16 = 0; k16 < 2; k16++) {
            const uint32_t ko = k16 * 32;
            uint32_t a[2][4], al[2][4], bh[4][4];
#pragma unroll
            for (int mi = 0; mi < 2; mi++) {
                ldsm4(st + aOff + mi * (16 * ROWB) + ko,
                      a[mi][0], a[mi][1], a[mi][2], a[mi][3]);
                if (TERMS == 2)
                    ldsm4(st + MATB + aOff + mi * (16 * ROWB) + ko,
                          al[mi][0], al[mi][1], al[mi][2], al[mi][3]);
            }
#pragma unroll
            for (int ni = 0; ni < 4; ni++)
                ldsm4(st + bOff + ni * (16 * ROWB) + ko,
                      bh[ni][0], bh[ni][1], bh[ni][2], bh[ni][3]);
            // pass 1: Ah*Bh (16 independent MMAs)
#pragma unroll
            for (int mi = 0; mi < 2; mi++)
#pragma unroll
                for (int ni = 0; ni < 4; ni++) {
                    mma16816(acc[mi][ni * 2],     a[mi], bh[ni][0], bh[ni][2]);
                    mma16816(acc[mi][ni * 2 + 1], a[mi], bh[ni][1], bh[ni][3]);
                }
            // pass 2: Al*Bh
            if (TERMS == 2) {
#pragma unroll
                for (int mi = 0; mi < 2; mi++)
#pragma unroll
                    for (int ni = 0; ni < 4; ni++) {
                        mma16816(acc[mi][ni * 2],     al[mi], bh[ni][0], bh[ni][2]);
                        mma16816(acc[mi][ni * 2 + 1], al[mi], bh[ni][1], bh[ni][3]);
                    }
            }
        }
    }

#pragma unroll
    for (int mi = 0; mi < 2; mi++) {
        const int row = m0 + warp_m * 32 + mi * 16 + (lane >> 2);
#pragma unroll
        for (int nj = 0; nj < 8; nj++) {
            const int col = n0 + warp_n * 64 + nj * 8 + (lane & 3) * 2;
            float* cp0 = C + (size_t)row * N + col;
            float* cp1 = C + (size_t)(row + 8) * N + col;
            *(float2*)cp0 = make_float2(acc[mi][nj][0] * alpha, acc[mi][nj][1] * alpha);
            *(float2*)cp1 = make_float2(acc[mi][nj][2] * alpha, acc[mi][nj][3] * alpha);
        }
    }
}

// ============================================================================
// Per-head RMSNorm + RoPE; q -> fp16 hi/lo (*32), k -> fp16, v -> fp16 row-major
// grid: (B*S, 48), block 128.
// ============================================================================
__global__ void __launch_bounds__(128) qkv_post(
    const float* __restrict__ cosb, const float* __restrict__ sinb,
    const float* __restrict__ qw,   const float* __restrict__ kw)
{
    const int bs = blockIdx.x;
    const int hh = blockIdx.y;
    const int d  = threadIdx.x;
    const int b  = bs / S;
    const int s  = bs - b * S;

    __shared__ float xs[D];
    __shared__ float red[4];

    float x = g_qkv[(size_t)bs * NQKV + hh * D + d];

    if (hh < NH + NKV) {
        float ss = x * x;
#pragma unroll
        for (int o = 16; o; o >>= 1) ss += __shfl_xor_sync(0xffffffffu, ss, o);
        if ((d & 31) == 0) red[d >> 5] = ss;
        __syncthreads();
        const float var = (red[0] + red[1] + red[2] + red[3]) * (1.0f / D);
        const float w = (hh < NH) ? qw[d] : kw[d];
        x = x * rsqrtf(var + EPS) * w;
        xs[d] = x;
        __syncthreads();
        const float c  = cosb[(size_t)bs * D + d];
        const float sn = sinb[(size_t)bs * D + d];
        const float part = (d < 64) ? -xs[d + 64] : xs[d - 64];
        x = x * c + part * sn;
    }

    if (hh < NH) {
        __half hi, lo;
        split1h(x * QSC, hi, lo);
        const size_t idx = (((size_t)b * NH + hh) * S + s) * D + d;
        g_qh[idx] = hi; g_ql[idx] = lo;
    } else if (hh < NH + NKV) {
        const size_t idx = (((size_t)b * NKV + (hh - NH)) * S + s) * D + d;
        g_kh[idx] = __float2half(x);
    } else {
        const size_t idx = (((size_t)b * NKV + (hh - NH - NKV)) * S + s) * D + d;
        g_vrow[idx] = __float2half(x);
    }
}

// ============================================================================
// Tiled transpose: g_vrow [B,NKV,S,D] -> g_vth [B,NKV,D,S]. 64x64 fp16 tiles.
// ============================================================================
__global__ void __launch_bounds__(256) v_transpose()
{
    __shared__ __half tile[64][72];
    const int s0 = blockIdx.x * 64;
    const int d0 = blockIdx.y * 64;
    const size_t base = (size_t)blockIdx.z;
    const int tid = threadIdx.x;
    const __half* src = g_vrow + base * S * D;
    __half* dst = g_vth + base * D * S;

#pragma unroll
    for (int i = tid; i < 1024; i += 256) {
        const int r = i >> 4, c4 = (i & 15) << 2;
        *(uint64_t*)&tile[r][c4] = *(const uint64_t*)(src + (size_t)(s0 + r) * D + d0 + c4);
    }
    __syncthreads();
#pragma unroll
    for (int i = tid; i < 1024; i += 256) {
        const int r = i >> 4, c4 = (i & 15) << 2;
        __half2 p0, p1;
        p0.x = tile[c4 + 0][r]; p0.y = tile[c4 + 1][r];
        p1.x = tile[c4 + 2][r]; p1.y = tile[c4 + 3][r];
        *(__half2*)(dst + (size_t)(d0 + r) * S + s0 + c4)     = p0;
        *(__half2*)(dst + (size_t)(d0 + r) * S + s0 + c4 + 2) = p1;
    }
}

// ============================================================================
// Causal flash attention, fp16 2-term (QhKh+QlKh; PhVh+PlVh).
// BM=128, BN=64, 8 warps (256 threads). 2-stage KV pipeline.
// Epilogue emits single fp16 AO (*256) for the 1-term O-projection.
// ============================================================================
#define QROW 272                       // 128 fp16 + 8 pad
#define VROW 144                       // 64 fp16 + 8 pad
#define SQH_OFF 0
#define SQL_OFF (128 * QROW)           // 34816
#define SK0_OFF (2 * 128 * QROW)       // 69632
#define VH_SOFF (64 * QROW)            // Vh within stage (17408)
#define KSTG    (VH_SOFF + 128 * VROW) // 35840
#define FSMEM   (SK0_OFF + 2 * KSTG)   // 141312

__global__ void __launch_bounds__(256) flash_mma()
{
    extern __shared__ __align__(128) char fsm[];
    const uint32_t sb = (uint32_t)__cvta_generic_to_shared(fsm);
    const int tid = threadIdx.x, lane = tid & 31, wid = tid >> 5;
    const int qt = (int)gridDim.x - 1 - (int)blockIdx.x;   // heavy CTAs first
    const int bh = blockIdx.y;
    const int b = bh / NH, h = bh - b * NH;
    const int kvh = h / GROUPS;

    const __half* Qhp = g_qh + (((size_t)b * NH + h) * S + (size_t)qt * 128) * D;
    const __half* Qlp = g_ql + (((size_t)b * NH + h) * S + (size_t)qt * 128) * D;
    const __half* Khp = g_kh + ((size_t)b * NKV + kvh) * S * D;
    const __half* Vhp = g_vth + ((size_t)b * NKV + kvh) * D * S;

#pragma unroll
    for (int i = tid; i < 2048; i += 256) {
        const int r = i >> 4, c = i & 15;
        cp16(sb + SQH_OFF + r * QROW + c * 16, Qhp + r * D + c * 8);
        cp16(sb + SQL_OFF + r * QROW + c * 16, Qlp + r * D + c * 8);
    }

    auto fillkv = [&](int slot, int kt) {
        const uint32_t st = sb + SK0_OFF + slot * KSTG;
        const __half* kh_ = Khp + (size_t)kt * 64 * D;
#pragma unroll
        for (int i = tid; i < 1024; i += 256) {
            const int r = i >> 4, c = i & 15;
            cp16(st + r * QROW + c * 16, kh_ + r * D + c * 8);
        }
        const __half* vh_ = Vhp + (size_t)kt * 64;
#pragma unroll
        for (int i = tid; i < 1024; i += 256) {
            const int r = i >> 3, c = i & 7;
            cp16(st + VH_SOFF + r * VROW + c * 16, vh_ + (size_t)r * S + c * 8);
        }
        asm volatile("cp.async.commit_group;" ::: "memory");
    };
    fillkv(0, 0);   // Q cp.asyncs ride this group

    float m0 = -INFINITY, m1 = -INFINITY, l0 = 0.f, l1 = 0.f;
    float o[16][4];
#pragma unroll
    for (int f = 0; f < 16; f++)
#pragma unroll
        for (int e = 0; e < 4; e++) o[f][e] = 0.f;

    const uint32_t aQ = (uint32_t)((wid * 16 + (lane & 15)) * QROW + ((lane >> 4) << 4));
    const uint32_t bK = (uint32_t)((lane & 15) * QROW + ((lane >> 4) << 4));
    const uint32_t bV = (uint32_t)((lane & 15) * VROW + ((lane >> 4) << 4));

    const int ktmax = 2 * qt + 1;

    for (int kt = 0; kt <= ktmax; kt++) {
        asm volatile("cp.async.wait_group 0;" ::: "memory");
        __syncthreads();
        if (kt < ktmax) fillkv((kt + 1) & 1, kt + 1);
        const uint32_t st = sb + SK0_OFF + (kt & 1) * KSTG;

        float s[8][4];
#pragma unroll
        for (int f = 0; f < 8; f++)
#pragma unroll
            for (int e = 0; e < 4; e++) s[f][e] = 0.f;

#pragma unroll
        for (int ks = 0; ks < 8; ks++) {
            const uint32_t ko = ks * 32;
            uint32_t qh4[4], ql4[4], kh4[4][4];
            ldsm4(sb + SQH_OFF + aQ + ko, qh4[0], qh4[1], qh4[2], qh4[3]);
            ldsm4(sb + SQL_OFF + aQ + ko, ql4[0], ql4[1], ql4[2], ql4[3]);
#pragma unroll
            for (int nb = 0; nb < 4; nb++)
                ldsm4(st + bK + nb * (16 * QROW) + ko,
                      kh4[nb][0], kh4[nb][1], kh4[nb][2], kh4[nb][3]);
#pragma unroll
            for (int nb = 0; nb < 4; nb++) {
                mma16816(s[nb * 2],     qh4, kh4[nb][0], kh4[nb][2]);
                mma16816(s[nb * 2 + 1], qh4, kh4[nb][1], kh4[nb][3]);
            }
#pragma unroll
            for (int nb = 0; nb < 4; nb++) {
                mma16816(s[nb * 2],     ql4, kh4[nb][0], kh4[nb][2]);
                mma16816(s[nb * 2 + 1], ql4, kh4[nb][1], kh4[nb][3]);
            }
        }

#pragma unroll
        for (int f = 0; f < 8; f++)
#pragma unroll
            for (int e = 0; e < 4; e++) s[f][e] *= SFIX;

        if (kt >= 2 * qt) {
            const int r0 = qt * 128 + wid * 16 + (lane >> 2);
            const int r1 = r0 + 8;
#pragma unroll
            for (int f = 0; f < 8; f++) {
                const int c0 = kt * 64 + f * 8 + (lane & 3) * 2;
                if (c0     > r0) s[f][0] = -INFINITY;
                if (c0 + 1 > r0) s[f][1] = -INFINITY;
                if (c0     > r1) s[f][2] = -INFINITY;
                if (c0 + 1 > r1) s[f][3] = -INFINITY;
            }
        }

        float a0 = -INFINITY, a1 = -INFINITY;
#pragma unroll
        for (int f = 0; f < 8; f++) {
            a0 = fmaxf(a0, fmaxf(s[f][0], s[f][1]));
            a1 = fmaxf(a1, fmaxf(s[f][2], s[f][3]));
        }
        a0 = fmaxf(a0, __shfl_xor_sync(0xffffffffu, a0, 1));
        a0 = fmaxf(a0, __shfl_xor_sync(0xffffffffu, a0, 2));
        a1 = fmaxf(a1, __shfl_xor_sync(0xffffffffu, a1, 1));
        a1 = fmaxf(a1, __shfl_xor_sync(0xffffffffu, a1, 2));
        const float mn0 = fmaxf(m0, a0), mn1 = fmaxf(m1, a1);
        const float sc0 = exp2f((m0 - mn0) * LOG2E);
        const float sc1 = exp2f((m1 - mn1) * LOG2E);
        float rs0 = 0.f, rs1 = 0.f;
#pragma unroll
        for (int f = 0; f < 8; f++) {
            s[f][0] = exp2f((s[f][0] - mn0) * LOG2E + PBIAS);
            s[f][1] = exp2f((s[f][1] - mn0) * LOG2E + PBIAS);
            s[f][2] = exp2f((s[f][2] - mn1) * LOG2E + PBIAS);
            s[f][3] = exp2f((s[f][3] - mn1) * LOG2E + PBIAS);
            rs0 += s[f][0] + s[f][1];
            rs1 += s[f][2] + s[f][3];
        }
        rs0 += __shfl_xor_sync(0xffffffffu, rs0, 1);
        rs0 += __shfl_xor_sync(0xffffffffu, rs0, 2);
        rs1 += __shfl_xor_sync(0xffffffffu, rs1, 1);
        rs1 += __shfl_xor_sync(0xffffffffu, rs1, 2);
        m0 = mn0; m1 = mn1;
        l0 = l0 * sc0 + rs0;
        l1 = l1 * sc1 + rs1;
#pragma unroll
        for (int f = 0; f < 16; f++) {
            o[f][0] *= sc0; o[f][1] *= sc0;
            o[f][2] *= sc1; o[f][3] *= sc1;
        }

        uint32_t ph[4][4], pl[4][4];
#pragma unroll
        for (int kb = 0; kb < 4; kb++) {
            split2h(s[2 * kb][0],     s[2 * kb][1],     ph[kb][0], pl[kb][0]);
            split2h(s[2 * kb][2],     s[2 * kb][3],     ph[kb][1], pl[kb][1]);
            split2h(s[2 * kb + 1][0], s[2 * kb + 1][1], ph[kb][2], pl[kb][2]);
            split2h(s[2 * kb + 1][2], s[2 * kb + 1][3], ph[kb][3], pl[kb][3]);
        }

#pragma unroll
        for (int kb = 0; kb < 4; kb++) {
            const uint32_t ko = kb * 32;
            uint32_t vh4[8][4];
#pragma unroll
            for (int nb = 0; nb < 8; nb++)
                ldsm4(st + VH_SOFF + bV + nb * (16 * VROW) + ko,
                      vh4[nb][0], vh4[nb][1], vh4[nb][2], vh4[nb][3]);
#pragma unroll
            for (int nb = 0; nb < 8; nb++) {
                mma16816(o[nb * 2],     ph[kb], vh4[nb][0], vh4[nb][2]);
                mma16816(o[nb * 2 + 1], ph[kb], vh4[nb][1], vh4[nb][3]);
            }
#pragma unroll
            for (int nb = 0; nb < 8; nb++) {
                mma16816(o[nb * 2],     pl[kb], vh4[nb][0], vh4[nb][2]);
                mma16816(o[nb * 2 + 1], pl[kb], vh4[nb][1], vh4[nb][3]);
            }
        }
    }

    // ---- epilogue: O*256/l, single fp16 term for 1-term O-projection ----
    const float i0 = ASCALE / l0, i1 = ASCALE / l1;
    const int gr0 = qt * 128 + wid * 16 + (lane >> 2);
#pragma unroll
    for (int f = 0; f < 16; f++) {
        const int d0 = f * 8 + (lane & 3) * 2;
        const size_t ix0 = ((size_t)(b * S + gr0) * NH + h) * D + d0;
        const size_t ix1 = ((size_t)(b * S + gr0 + 8) * NH + h) * D + d0;
        __half2 h0 = __floats2half2_rn(o[f][0] * i0, o[f][1] * i0);
        __half2 h1 = __floats2half2_rn(o[f][2] * i1, o[f][3] * i1);
        *(__half2*)(g_aoh + ix0) = h0;
        *(__half2*)(g_aoh + ix1) = h1;
    }
}

// ============================================================================
// host launcher
// ============================================================================
extern "C" void kernel_launch(void* const* d_in, const int* in_sizes, int n_in,
                              void* d_out, int out_size)
{
    const float* hidden = (const float*)d_in[0];
    const float* cosb   = (const float*)d_in[1];
    const float* sinb   = (const float*)d_in[2];
    const float* Wq     = (const float*)d_in[3];
    const float* Wk     = (const float*)d_in[4];
    const float* Wv     = (const float*)d_in[5];
    const float* Wo     = (const float*)d_in[6];
    const float* qw     = (const float*)d_in[7];
    const float* kw     = (const float*)d_in[8];
    float* out = (float*)d_out;

    __half *xh, *xl, *wh, *woh, *aoh;
    float* qkv;
    cudaGetSymbolAddress((void**)&xh,  g_xh);
    cudaGetSymbolAddress((void**)&xl,  g_xl);
    cudaGetSymbolAddress((void**)&wh,  g_wh);
    cudaGetSymbolAddress((void**)&woh, g_woh);
    cudaGetSymbolAddress((void**)&aoh, g_aoh);
    cudaGetSymbolAddress((void**)&qkv, g_qkv);

    cudaFuncSetAttribute(gemm_mma<2>, cudaFuncAttributeMaxDynamicSharedMemorySize, GSMEM2);
    cudaFuncSetAttribute(gemm_mma<1>, cudaFuncAttributeMaxDynamicSharedMemorySize, GSMEM1);
    cudaFuncSetAttribute(flash_mma, cudaFuncAttributeMaxDynamicSharedMemorySize, FSMEM);

    // conversions (2 launches)
    {
        int n4 = MSEQ * H / 4;
        split_fp32<<<(n4 + 255) / 256, 256>>>(hidden, xh, xl, ASCALE, n4);
        cvt_weights<<<(N4ALL + 255) / 256, 256>>>(Wq, Wk, Wv, Wo);
    }

    // fused QKV projection (2-term): [2048, 6144] = (X*256) * Wqkv^T / 256
    gemm_mma<2><<<dim3(NQKV / 128, MSEQ / 128), 256, GSMEM2>>>(
        xh, xl, wh, qkv, AINV, MSEQ, NQKV, H);

    // norm + rope + fp16 pack (v row-major)
    qkv_post<<<dim3(MSEQ, NH + 2 * NKV), 128>>>(cosb, sinb, qw, kw);

    // v transpose [B,NKV,S,D] -> [B,NKV,D,S]
    v_transpose<<<dim3(S / 64, D / 64, B * NKV), 256>>>();

    // causal flash attention on tensor cores
    flash_mma<<<dim3(S / 128, B * NH), 256, FSMEM>>>();

    // output projection (1-term): [2048, 4096] = (AO*256) * Wo^T / 256
    gemm_mma<1><<<dim3(H / 128, MSEQ / 128), 256, GSMEM1>>>(
        aoh, nullptr, woh, out, AINV, MSEQ, H, NH * D);
}

// round 10
// speedup vs baseline: 5.4183x; 1.1191x over previous
#include <cuda_runtime.h>
#include <cuda_fp16.h>
#include <math.h>
#include <stdint.h>

// ---------------- problem constants ----------------
#define B   2
#define S   1024
#define H   4096
#define NH  32
#define NKV 8
#define D   128
#define GROUPS (NH / NKV)   // 4
#define EPS 1e-6f
#define QSCALE 0.08838834764831845f   // 1/sqrt(128)
#define MSEQ (B * S)        // 2048 rows
#define NQKV ((NH + 2 * NKV) * D)   // 6144
#define LOG2E 1.4426950408889634f
#define ASCALE 256.0f
#define AINV   (1.0f / 256.0f)
#define QSC    32.0f
#define SFIX   (QSCALE / 32.0f)
#define PBIAS  12.0f                 // P scaled by 2^12 (cancels in O/l)

// ---------------- scratch (device globals, fp16) ----------------
__device__ __align__(16) __half g_xh [MSEQ * H];       // hidden*256 hi
__device__ __align__(16) __half g_xl [MSEQ * H];       // hidden*256 lo
__device__ __align__(16) __half g_wh [NQKV * H];       // stacked Wq|Wk|Wv
__device__ __align__(16) __half g_woh[H * NH * D];     // Wo
__device__ __align__(16) __half g_aoh[MSEQ * NH * D];  // attn out *256 (1 term)
__device__ float g_qkv[MSEQ * NQKV];
// flash inputs: q*32 hi/lo row-major, k hi row-major, v row-major + transposed
__device__ __align__(16) __half g_qh [B * NH  * S * D];
__device__ __align__(16) __half g_ql [B * NH  * S * D];
__device__ __align__(16) __half g_kh [B * NKV * S * D];
__device__ __align__(16) __half g_vrow[B * NKV * S * D];   // [B,NKV,S,D]
__device__ __align__(16) __half g_vth [B * NKV * D * S];   // [B,NKV,D,S]

// ---------------- small helpers ----------------
__device__ __forceinline__ void cp16(uint32_t dst, const void* src) {
    asm volatile("cp.async.cg.shared.global [%0], [%1], 16;" :: "r"(dst), "l"(src) : "memory");
}
__device__ __forceinline__ void ldsm4(uint32_t addr, uint32_t& r0, uint32_t& r1,
                                      uint32_t& r2, uint32_t& r3) {
    asm volatile("ldmatrix.sync.aligned.m8n8.x4.shared.b16 {%0,%1,%2,%3}, [%4];"
        : "=r"(r0), "=r"(r1), "=r"(r2), "=r"(r3) : "r"(addr));
}
__device__ __forceinline__ void mma16816(float* c, const uint32_t* a,
                                         uint32_t b0, uint32_t b1) {
    asm volatile("mma.sync.aligned.m16n8k16.row.col.f32.f16.f16.f32 "
        "{%0,%1,%2,%3}, {%4,%5,%6,%7}, {%8,%9}, {%0,%1,%2,%3};"
        : "+f"(c[0]), "+f"(c[1]), "+f"(c[2]), "+f"(c[3])
        : "r"(a[0]), "r"(a[1]), "r"(a[2]), "r"(a[3]), "r"(b0), "r"(b1));
}
__device__ __forceinline__ void split1h(float v, __half& h, __half& l) {
    h = __float2half(v);
    l = __float2half(v - __half2float(h));
}
__device__ __forceinline__ void split2h(float a, float b, uint32_t& hi, uint32_t& lo) {
    __half2 hv, lv;
    split1h(a, hv.x, lv.x);
    split1h(b, hv.y, lv.y);
    hi = *(uint32_t*)&hv;
    lo = *(uint32_t*)&lv;
}

// ============================================================================
// fp32 -> fp16 hi/lo split with scale
// ============================================================================
__global__ void __launch_bounds__(256) split_fp32(
    const float* __restrict__ src, __half* __restrict__ hi,
    __half* __restrict__ lo, float scale, int n4)
{
    int i = blockIdx.x * 256 + threadIdx.x;
    if (i >= n4) return;
    float4 x = ((const float4*)src)[i];
    __half2 hv0, hv1, lv0, lv1;
    split1h(x.x * scale, hv0.x, lv0.x);
    split1h(x.y * scale, hv0.y, lv0.y);
    split1h(x.z * scale, hv1.x, lv1.x);
    split1h(x.w * scale, hv1.y, lv1.y);
    ((__half2*)hi)[2 * i]     = hv0;
    ((__half2*)hi)[2 * i + 1] = hv1;
    ((__half2*)lo)[2 * i]     = lv0;
    ((__half2*)lo)[2 * i + 1] = lv1;
}

// all four weight matrices -> fp16 in one launch
#define N4Q (NH * D * H / 4)           // 4194304
#define N4K (NKV * D * H / 4)          // 1048576
#define N4ALL (N4Q + 2 * N4K + N4Q)

__global__ void __launch_bounds__(256) cvt_weights(
    const float* __restrict__ Wq, const float* __restrict__ Wk,
    const float* __restrict__ Wv, const float* __restrict__ Wo)
{
    int i = blockIdx.x * 256 + threadIdx.x;
    if (i >= N4ALL) return;
    const float* src;
    __half* dst;
    int j = i;
    if (j < N4Q)                { src = Wq; dst = g_wh; }
    else if ((j -= N4Q) < N4K)  { src = Wk; dst = g_wh + (size_t)NH * D * H; }
    else if ((j -= N4K) < N4K)  { src = Wv; dst = g_wh + (size_t)(NH + NKV) * D * H; }
    else { j -= N4K;              src = Wo; dst = g_woh; }
    float4 x = ((const float4*)src)[j];
    ((__half2*)dst)[2 * j]     = __floats2half2_rn(x.x, x.y);
    ((__half2*)dst)[2 * j + 1] = __floats2half2_rn(x.z, x.w);
}

// ============================================================================
// mma.sync fp16 NT GEMM with per-block term count:
//   blocks with n0 <  nsplit:  C = alpha*(Ah+Al)*Bh^T   (2 terms)
//   blocks with n0 >= nsplit:  C = alpha* Ah   *Bh^T    (1 term)
// Block tile 128x128x32, 8 warps (4m x 2n), warp tile 32x64.
// 3-stage cp.async ring, ONE __syncthreads per K-tile, 2 CTAs/SM.
// ============================================================================
#define ROWB 80                        // bytes per 32-fp16 row (padded)
#define MATB (128 * ROWB)              // 10240 per matrix tile
#define STGB (3 * MATB)                // Ah|Al|Bh slots per stage
#define GSMEM (3 * STGB)               // 92160

__global__ void __launch_bounds__(256, 2) gemm_mma(
    const __half* __restrict__ Ah, const __half* __restrict__ Al,
    const __half* __restrict__ Bh, float* __restrict__ C,
    float alpha, int M, int N, int K, int nsplit)
{
    extern __shared__ __align__(128) char smem[];
    const uint32_t sbase = (uint32_t)__cvta_generic_to_shared(smem);
    const int tid  = threadIdx.x;
    const int lane = tid & 31;
    const int wid  = tid >> 5;
    const int warp_m = wid >> 1;   // 0..3 (32 rows each)
    const int warp_n = wid & 1;    // 0..1 (64 cols each)
    const int m0 = blockIdx.y * 128;
    const int n0 = blockIdx.x * 128;
    const int KT = K >> 5;         // K / 32
    const bool two = (n0 < nsplit);

    float acc[2][8][4];
#pragma unroll
    for (int i = 0; i < 2; i++)
#pragma unroll
        for (int j = 0; j < 8; j++)
#pragma unroll
            for (int q = 0; q < 4; q++) acc[i][j][q] = 0.f;

    auto fill = [&](int s, int kt) {
        const uint32_t st = sbase + s * STGB;
#pragma unroll
        for (int i = 0; i < 6; i++) {
            if (i >= 2 && i < 4 && !two) continue;   // skip Al for 1-term blocks
            const int v = ((i & 1) << 8) + tid;      // 0..511 within matrix
            const int r = v >> 2, c = v & 3;
            const __half* gb = (i < 2) ? Ah : (i < 4) ? Al : Bh;
            const int grow = ((i < 4) ? m0 : n0) + r;
            cp16(st + (i >> 1) * MATB + r * ROWB + c * 16,
                 gb + (size_t)grow * K + (size_t)kt * 32 + c * 8);
        }
        asm volatile("cp.async.commit_group;" ::: "memory");
    };

    fill(0, 0); fill(1, 1); fill(2, 2);

    const uint32_t aOff = (uint32_t)((warp_m * 32 + (lane & 15)) * ROWB + ((lane >> 4) << 4));
    const uint32_t bOff = (uint32_t)(2 * MATB + (warp_n * 64 + (lane & 15)) * ROWB + ((lane >> 4) << 4));

    for (int kt = 0; kt < KT; kt++) {
        asm volatile("cp.async.wait_group 1;" ::: "memory");
        __syncthreads();     // all warps done with iter kt-1 -> slot (kt-1)%3 free
        if (kt >= 1) {
            const int t = kt + 2;
            if (t < KT) fill(t % 3, t);
            else asm volatile("cp.async.commit_group;" ::: "memory");  // keep group count
        }

        const uint32_t st = sbase + (kt % 3) * STGB;
#pragma unroll
        for (int k16 = 0; k16 < 2; k16++) {
            const uint32_t ko = k16 * 32;
            uint32_t a[2][4], al[2][4], bh[4][4];
#pragma unroll
            for (int mi = 0; mi < 2; mi++)
                ldsm4(st + aOff + mi * (16 * ROWB) + ko,
                      a[mi][0], a[mi][1], a[mi][2], a[mi][3]);
            if (two) {
#pragma unroll
                for (int mi = 0; mi < 2; mi++)
                    ldsm4(st + MATB + aOff + mi * (16 * ROWB) + ko,
                          al[mi][0], al[mi][1], al[mi][2], al[mi][3]);
            }
#pragma unroll
            for (int ni = 0; ni < 4; ni++)
                ldsm4(st + bOff + ni * (16 * ROWB) + ko,
                      bh[ni][0], bh[ni][1], bh[ni][2], bh[ni][3]);
            // pass 1: Ah*Bh (16 independent MMAs)
#pragma unroll
            for (int mi = 0; mi < 2; mi++)
#pragma unroll
                for (int ni = 0; ni < 4; ni++) {
                    mma16816(acc[mi][ni * 2],     a[mi], bh[ni][0], bh[ni][2]);
                    mma16816(acc[mi][ni * 2 + 1], a[mi], bh[ni][1], bh[ni][3]);
                }
            // pass 2: Al*Bh (only 2-term blocks)
            if (two) {
#pragma unroll
                for (int mi = 0; mi < 2; mi++)
#pragma unroll
                    for (int ni = 0; ni < 4; ni++) {
                        mma16816(acc[mi][ni * 2],     al[mi], bh[ni][0], bh[ni][2]);
                        mma16816(acc[mi][ni * 2 + 1], al[mi], bh[ni][1], bh[ni][3]);
                    }
            }
        }
    }

#pragma unroll
    for (int mi = 0; mi < 2; mi++) {
        const int row = m0 + warp_m * 32 + mi * 16 + (lane >> 2);
#pragma unroll
        for (int nj = 0; nj < 8; nj++) {
            const int col = n0 + warp_n * 64 + nj * 8 + (lane & 3) * 2;
            float* cp0 = C + (size_t)row * N + col;
            float* cp1 = C + (size_t)(row + 8) * N + col;
            *(float2*)cp0 = make_float2(acc[mi][nj][0] * alpha, acc[mi][nj][1] * alpha);
            *(float2*)cp1 = make_float2(acc[mi][nj][2] * alpha, acc[mi][nj][3] * alpha);
        }
    }
}

// ============================================================================
// Per-head RMSNorm + RoPE; warp-per-head, no smem/syncthreads.
// block 256 = 8 warps = 8 heads; grid = B*S*48/8 = 12288.
// q -> fp16 hi/lo (*32), k -> fp16, v -> fp16 row-major.
// ============================================================================
__global__ void __launch_bounds__(256) qkv_post(
    const float* __restrict__ cosb, const float* __restrict__ sinb,
    const float* __restrict__ qw,   const float* __restrict__ kw)
{
    const int gid  = blockIdx.x * 8 + (threadIdx.x >> 5);
    const int lane = threadIdx.x & 31;
    const int bs = gid / 48;
    const int hh = gid - bs * 48;
    const int b  = bs >> 10;          // S = 1024
    const int s  = bs & 1023;

    float4 x4 = *(const float4*)(g_qkv + (size_t)bs * NQKV + hh * D + lane * 4);
    float v0 = x4.x, v1 = x4.y, v2 = x4.z, v3 = x4.w;

    if (hh < NH + NKV) {
        float ss = v0 * v0 + v1 * v1 + v2 * v2 + v3 * v3;
#pragma unroll
        for (int o = 16; o; o >>= 1) ss += __shfl_xor_sync(0xffffffffu, ss, o);
        const float inv = rsqrtf(ss * (1.0f / D) + EPS);
        const float* wp = (hh < NH) ? qw : kw;
        float4 w4 = *(const float4*)(wp + lane * 4);
        v0 *= inv * w4.x; v1 *= inv * w4.y; v2 *= inv * w4.z; v3 *= inv * w4.w;
        // rope: partner d +/- 64 lives in lane ^ 16, same sub-index
        float p0 = __shfl_xor_sync(0xffffffffu, v0, 16);
        float p1 = __shfl_xor_sync(0xffffffffu, v1, 16);
        float p2 = __shfl_xor_sync(0xffffffffu, v2, 16);
        float p3 = __shfl_xor_sync(0xffffffffu, v3, 16);
        const float sgn = (lane < 16) ? -1.f : 1.f;
        float4 c4 = *(const float4*)(cosb + (size_t)bs * D + lane * 4);
        float4 s4 = *(const float4*)(sinb + (size_t)bs * D + lane * 4);
        v0 = v0 * c4.x + sgn * p0 * s4.x;
        v1 = v1 * c4.y + sgn * p1 * s4.y;
        v2 = v2 * c4.z + sgn * p2 * s4.z;
        v3 = v3 * c4.w + sgn * p3 * s4.w;
    }

    if (hh < NH) {
        const size_t idx = (((size_t)b * NH + hh) * S + s) * D + lane * 4;
        uint32_t h0, l0, h1, l1;
        split2h(v0 * QSC, v1 * QSC, h0, l0);
        split2h(v2 * QSC, v3 * QSC, h1, l1);
        *(uint2*)(g_qh + idx) = make_uint2(h0, h1);
        *(uint2*)(g_ql + idx) = make_uint2(l0, l1);
    } else if (hh < NH + NKV) {
        const size_t idx = (((size_t)b * NKV + (hh - NH)) * S + s) * D + lane * 4;
        __half2 a = __floats2half2_rn(v0, v1);
        __half2 c = __floats2half2_rn(v2, v3);
        *(uint2*)(g_kh + idx) = make_uint2(*(uint32_t*)&a, *(uint32_t*)&c);
    } else {
        const size_t idx = (((size_t)b * NKV + (hh - NH - NKV)) * S + s) * D + lane * 4;
        __half2 a = __floats2half2_rn(v0, v1);
        __half2 c = __floats2half2_rn(v2, v3);
        *(uint2*)(g_vrow + idx) = make_uint2(*(uint32_t*)&a, *(uint32_t*)&c);
    }
}

// ============================================================================
// Tiled transpose: g_vrow [B,NKV,S,D] -> g_vth [B,NKV,D,S]. 64x64 fp16 tiles.
// ============================================================================
__global__ void __launch_bounds__(256) v_transpose()
{
    __shared__ __half tile[64][72];
    const int s0 = blockIdx.x * 64;
    const int d0 = blockIdx.y * 64;
    const size_t base = (size_t)blockIdx.z;
    const int tid = threadIdx.x;
    const __half* src = g_vrow + base * S * D;
    __half* dst = g_vth + base * D * S;

#pragma unroll
    for (int i = tid; i < 1024; i += 256) {
        const int r = i >> 4, c4 = (i & 15) << 2;
        *(uint64_t*)&tile[r][c4] = *(const uint64_t*)(src + (size_t)(s0 + r) * D + d0 + c4);
    }
    __syncthreads();
#pragma unroll
    for (int i = tid; i < 1024; i += 256) {
        const int r = i >> 4, c4 = (i & 15) << 2;
        __half2 p0, p1;
        p0.x = tile[c4 + 0][r]; p0.y = tile[c4 + 1][r];
        p1.x = tile[c4 + 2][r]; p1.y = tile[c4 + 3][r];
        *(__half2*)(dst + (size_t)(d0 + r) * S + s0 + c4)     = p0;
        *(__half2*)(dst + (size_t)(d0 + r) * S + s0 + c4 + 2) = p1;
    }
}

// ============================================================================
// Causal flash attention, fp16 2-term (QhKh+QlKh; PhVh+PlVh).
// BM=128, BN=64, 8 warps (256 threads). 2-stage KV pipeline.
// Epilogue emits single fp16 AO (*256) for the 1-term O-projection.
// ============================================================================
#define QROW 272                       // 128 fp16 + 8 pad
#define VROW 144                       // 64 fp16 + 8 pad
#define SQH_OFF 0
#define SQL_OFF (128 * QROW)           // 34816
#define SK0_OFF (2 * 128 * QROW)       // 69632
#define VH_SOFF (64 * QROW)            // Vh within stage (17408)
#define KSTG    (VH_SOFF + 128 * VROW) // 35840
#define FSMEM   (SK0_OFF + 2 * KSTG)   // 141312

__global__ void __launch_bounds__(256) flash_mma()
{
    extern __shared__ __align__(128) char fsm[];
    const uint32_t sb = (uint32_t)__cvta_generic_to_shared(fsm);
    const int tid = threadIdx.x, lane = tid & 31, wid = tid >> 5;
    const int qt = (int)gridDim.x - 1 - (int)blockIdx.x;   // heavy CTAs first
    const int bh = blockIdx.y;
    const int b = bh / NH, h = bh - b * NH;
    const int kvh = h / GROUPS;

    const __half* Qhp = g_qh + (((size_t)b * NH + h) * S + (size_t)qt * 128) * D;
    const __half* Qlp = g_ql + (((size_t)b * NH + h) * S + (size_t)qt * 128) * D;
    const __half* Khp = g_kh + ((size_t)b * NKV + kvh) * S * D;
    const __half* Vhp = g_vth + ((size_t)b * NKV + kvh) * D * S;

#pragma unroll
    for (int i = tid; i < 2048; i += 256) {
        const int r = i >> 4, c = i & 15;
        cp16(sb + SQH_OFF + r * QROW + c * 16, Qhp + r * D + c * 8);
        cp16(sb + SQL_OFF + r * QROW + c * 16, Qlp + r * D + c * 8);
    }

    auto fillkv = [&](int slot, int kt) {
        const uint32_t st = sb + SK0_OFF + slot * KSTG;
        const __half* kh_ = Khp + (size_t)kt * 64 * D;
#pragma unroll
        for (int i = tid; i < 1024; i += 256) {
            const int r = i >> 4, c = i & 15;
            cp16(st + r * QROW + c * 16, kh_ + r * D + c * 8);
        }
        const __half* vh_ = Vhp + (size_t)kt * 64;
#pragma unroll
        for (int i = tid; i < 1024; i += 256) {
            const int r = i >> 3, c = i & 7;
            cp16(st + VH_SOFF + r * VROW + c * 16, vh_ + (size_t)r * S + c * 8);
        }
        asm volatile("cp.async.commit_group;" ::: "memory");
    };
    fillkv(0, 0);   // Q cp.asyncs ride this group

    float m0 = -INFINITY, m1 = -INFINITY, l0 = 0.f, l1 = 0.f;
    float o[16][4];
#pragma unroll
    for (int f = 0; f < 16; f++)
#pragma unroll
        for (int e = 0; e < 4; e++) o[f][e] = 0.f;

    const uint32_t aQ = (uint32_t)((wid * 16 + (lane & 15)) * QROW + ((lane >> 4) << 4));
    const uint32_t bK = (uint32_t)((lane & 15) * QROW + ((lane >> 4) << 4));
    const uint32_t bV = (uint32_t)((lane & 15) * VROW + ((lane >> 4) << 4));

    const int ktmax = 2 * qt + 1;

    for (int kt = 0; kt <= ktmax; kt++) {
        asm volatile("cp.async.wait_group 0;" ::: "memory");
        __syncthreads();
        if (kt < ktmax) fillkv((kt + 1) & 1, kt + 1);
        const uint32_t st = sb + SK0_OFF + (kt & 1) * KSTG;

        float s[8][4];
#pragma unroll
        for (int f = 0; f < 8; f++)
#pragma unroll
            for (int e = 0; e < 4; e++) s[f][e] = 0.f;

#pragma unroll
        for (int ks = 0; ks < 8; ks++) {
            const uint32_t ko = ks * 32;
            uint32_t qh4[4], ql4[4], kh4[4][4];
            ldsm4(sb + SQH_OFF + aQ + ko, qh4[0], qh4[1], qh4[2], qh4[3]);
            ldsm4(sb + SQL_OFF + aQ + ko, ql4[0], ql4[1], ql4[2], ql4[3]);
#pragma unroll
            for (int nb = 0; nb < 4; nb++)
                ldsm4(st + bK + nb * (16 * QROW) + ko,
                      kh4[nb][0], kh4[nb][1], kh4[nb][2], kh4[nb][3]);
#pragma unroll
            for (int nb = 0; nb < 4; nb++) {
                mma16816(s[nb * 2],     qh4, kh4[nb][0], kh4[nb][2]);
                mma16816(s[nb * 2 + 1], qh4, kh4[nb][1], kh4[nb][3]);
            }
#pragma unroll
            for (int nb = 0; nb < 4; nb++) {
                mma16816(s[nb * 2],     ql4, kh4[nb][0], kh4[nb][2]);
                mma16816(s[nb * 2 + 1], ql4, kh4[nb][1], kh4[nb][3]);
            }
        }

#pragma unroll
        for (int f = 0; f < 8; f++)
#pragma unroll
            for (int e = 0; e < 4; e++) s[f][e] *= SFIX;

        if (kt >= 2 * qt) {
            const int r0 = qt * 128 + wid * 16 + (lane >> 2);
            const int r1 = r0 + 8;
#pragma unroll
            for (int f = 0; f < 8; f++) {
                const int c0 = kt * 64 + f * 8 + (lane & 3) * 2;
                if (c0     > r0) s[f][0] = -INFINITY;
                if (c0 + 1 > r0) s[f][1] = -INFINITY;
                if (c0     > r1) s[f][2] = -INFINITY;
                if (c0 + 1 > r1) s[f][3] = -INFINITY;
            }
        }

        float a0 = -INFINITY, a1 = -INFINITY;
#pragma unroll
        for (int f = 0; f < 8; f++) {
            a0 = fmaxf(a0, fmaxf(s[f][0], s[f][1]));
            a1 = fmaxf(a1, fmaxf(s[f][2], s[f][3]));
        }
        a0 = fmaxf(a0, __shfl_xor_sync(0xffffffffu, a0, 1));
        a0 = fmaxf(a0, __shfl_xor_sync(0xffffffffu, a0, 2));
        a1 = fmaxf(a1, __shfl_xor_sync(0xffffffffu, a1, 1));
        a1 = fmaxf(a1, __shfl_xor_sync(0xffffffffu, a1, 2));
        const float mn0 = fmaxf(m0, a0), mn1 = fmaxf(m1, a1);
        const float sc0 = exp2f((m0 - mn0) * LOG2E);
        const float sc1 = exp2f((m1 - mn1) * LOG2E);
        float rs0 = 0.f, rs1 = 0.f;
#pragma unroll
        for (int f = 0; f < 8; f++) {
            s[f][0] = exp2f((s[f][0] - mn0) * LOG2E + PBIAS);
            s[f][1] = exp2f((s[f][1] - mn0) * LOG2E + PBIAS);
            s[f][2] = exp2f((s[f][2] - mn1) * LOG2E + PBIAS);
            s[f][3] = exp2f((s[f][3] - mn1) * LOG2E + PBIAS);
            rs0 += s[f][0] + s[f][1];
            rs1 += s[f][2] + s[f][3];
        }
        rs0 += __shfl_xor_sync(0xffffffffu, rs0, 1);
        rs0 += __shfl_xor_sync(0xffffffffu, rs0, 2);
        rs1 += __shfl_xor_sync(0xffffffffu, rs1, 1);
        rs1 += __shfl_xor_sync(0xffffffffu, rs1, 2);
        m0 = mn0; m1 = mn1;
        l0 = l0 * sc0 + rs0;
        l1 = l1 * sc1 + rs1;
#pragma unroll
        for (int f = 0; f < 16; f++) {
            o[f][0] *= sc0; o[f][1] *= sc0;
            o[f][2] *= sc1; o[f][3] *= sc1;
        }

        uint32_t ph[4][4], pl[4][4];
#pragma unroll
        for (int kb = 0; kb < 4; kb++) {
            split2h(s[2 * kb][0],     s[2 * kb][1],     ph[kb][0], pl[kb][0]);
            split2h(s[2 * kb][2],     s[2 * kb][3],     ph[kb][1], pl[kb][1]);
            split2h(s[2 * kb + 1][0], s[2 * kb + 1][1], ph[kb][2], pl[kb][2]);
            split2h(s[2 * kb + 1][2], s[2 * kb + 1][3], ph[kb][3], pl[kb][3]);
        }

#pragma unroll
        for (int kb = 0; kb < 4; kb++) {
            const uint32_t ko = kb * 32;
            uint32_t vh4[8][4];
#pragma unroll
            for (int nb = 0; nb < 8; nb++)
                ldsm4(st + VH_SOFF + bV + nb * (16 * VROW) + ko,
                      vh4[nb][0], vh4[nb][1], vh4[nb][2], vh4[nb][3]);
#pragma unroll
            for (int nb = 0; nb < 8; nb++) {
                mma16816(o[nb * 2],     ph[kb], vh4[nb][0], vh4[nb][2]);
                mma16816(o[nb * 2 + 1], ph[kb], vh4[nb][1], vh4[nb][3]);
            }
#pragma unroll
            for (int nb = 0; nb < 8; nb++) {
                mma16816(o[nb * 2],     pl[kb], vh4[nb][0], vh4[nb][2]);
                mma16816(o[nb * 2 + 1], pl[kb], vh4[nb][1], vh4[nb][3]);
            }
        }
    }

    // ---- epilogue: O*256/l, single fp16 term for 1-term O-projection ----
    const float i0 = ASCALE / l0, i1 = ASCALE / l1;
    const int gr0 = qt * 128 + wid * 16 + (lane >> 2);
#pragma unroll
    for (int f = 0; f < 16; f++) {
        const int d0 = f * 8 + (lane & 3) * 2;
        const size_t ix0 = ((size_t)(b * S + gr0) * NH + h) * D + d0;
        const size_t ix1 = ((size_t)(b * S + gr0 + 8) * NH + h) * D + d0;
        __half2 h0 = __floats2half2_rn(o[f][0] * i0, o[f][1] * i0);
        __half2 h1 = __floats2half2_rn(o[f][2] * i1, o[f][3] * i1);
        *(__half2*)(g_aoh + ix0) = h0;
        *(__half2*)(g_aoh + ix1) = h1;
    }
}

// ============================================================================
// host launcher
// ============================================================================
extern "C" void kernel_launch(void* const* d_in, const int* in_sizes, int n_in,
                              void* d_out, int out_size)
{
    const float* hidden = (const float*)d_in[0];
    const float* cosb   = (const float*)d_in[1];
    const float* sinb   = (const float*)d_in[2];
    const float* Wq     = (const float*)d_in[3];
    const float* Wk     = (const float*)d_in[4];
    const float* Wv     = (const float*)d_in[5];
    const float* Wo     = (const float*)d_in[6];
    const float* qw     = (const float*)d_in[7];
    const float* kw     = (const float*)d_in[8];
    float* out = (float*)d_out;

    __half *xh, *xl, *wh, *woh, *aoh;
    float* qkv;
    cudaGetSymbolAddress((void**)&xh,  g_xh);
    cudaGetSymbolAddress((void**)&xl,  g_xl);
    cudaGetSymbolAddress((void**)&wh,  g_wh);
    cudaGetSymbolAddress((void**)&woh, g_woh);
    cudaGetSymbolAddress((void**)&aoh, g_aoh);
    cudaGetSymbolAddress((void**)&qkv, g_qkv);

    cudaFuncSetAttribute(gemm_mma, cudaFuncAttributeMaxDynamicSharedMemorySize, GSMEM);
    cudaFuncSetAttribute(flash_mma, cudaFuncAttributeMaxDynamicSharedMemorySize, FSMEM);

    // conversions (2 launches)
    {
        int n4 = MSEQ * H / 4;
        split_fp32<<<(n4 + 255) / 256, 256>>>(hidden, xh, xl, ASCALE, n4);
        cvt_weights<<<(N4ALL + 255) / 256, 256>>>(Wq, Wk, Wv, Wo);
    }

    // fused QKV projection: Q cols 2-term, K/V cols 1-term
    gemm_mma<<<dim3(NQKV / 128, MSEQ / 128), 256, GSMEM>>>(
        xh, xl, wh, qkv, AINV, MSEQ, NQKV, H, NH * D);

    // norm + rope + fp16 pack (v row-major), warp-per-head
    qkv_post<<<MSEQ * (NH + 2 * NKV) / 8, 256>>>(cosb, sinb, qw, kw);

    // v transpose [B,NKV,S,D] -> [B,NKV,D,S]
    v_transpose<<<dim3(S / 64, D / 64, B * NKV), 256>>>();

    // causal flash attention on tensor cores
    flash_mma<<<dim3(S / 128, B * NH), 256, FSMEM>>>();

    // output projection (1-term): [2048, 4096] = (AO*256) * Wo^T / 256
    gemm_mma<<<dim3(H / 128, MSEQ / 128), 256, GSMEM>>>(
        aoh, nullptr, woh, out, AINV, MSEQ, H, NH * D, 0);
}

// round 11
// speedup vs baseline: 7.1010x; 1.3106x over previous
#include <cuda_runtime.h>
#include <cuda_fp16.h>
#include <math.h>
#include <stdint.h>

// ---------------- problem constants ----------------
#define B   2
#define S   1024
#define H   4096
#define NH  32
#define NKV 8
#define D   128
#define GROUPS (NH / NKV)   // 4
#define EPS 1e-6f
#define QSCALE 0.08838834764831845f   // 1/sqrt(128)
#define MSEQ (B * S)        // 2048 rows
#define NQKV ((NH + 2 * NKV) * D)   // 6144
#define LOG2E 1.4426950408889634f
#define PBIAS  12.0f                 // P scaled by 2^12 (cancels in O/l)

// ---------------- scratch (device globals, fp16) ----------------
__device__ __align__(16) __half g_xh [MSEQ * H];       // hidden fp16
__device__ __align__(16) __half g_wh [NQKV * H];       // stacked Wq|Wk|Wv
__device__ __align__(16) __half g_woh[H * NH * D];     // Wo
__device__ __align__(16) __half g_aoh[MSEQ * NH * D];  // attn out fp16
__device__ float g_qkv[MSEQ * NQKV];
// flash inputs: q (pre-scaled by QSCALE), k row-major, v row-major + transposed
__device__ __align__(16) __half g_qh [B * NH  * S * D];
__device__ __align__(16) __half g_kh [B * NKV * S * D];
__device__ __align__(16) __half g_vrow[B * NKV * S * D];   // [B,NKV,S,D]
__device__ __align__(16) __half g_vth [B * NKV * D * S];   // [B,NKV,D,S]

// ---------------- small helpers ----------------
__device__ __forceinline__ void cp16(uint32_t dst, const void* src) {
    asm volatile("cp.async.cg.shared.global [%0], [%1], 16;" :: "r"(dst), "l"(src) : "memory");
}
__device__ __forceinline__ void ldsm4(uint32_t addr, uint32_t& r0, uint32_t& r1,
                                      uint32_t& r2, uint32_t& r3) {
    asm volatile("ldmatrix.sync.aligned.m8n8.x4.shared.b16 {%0,%1,%2,%3}, [%4];"
        : "=r"(r0), "=r"(r1), "=r"(r2), "=r"(r3) : "r"(addr));
}
__device__ __forceinline__ void mma16816(float* c, const uint32_t* a,
                                         uint32_t b0, uint32_t b1) {
    asm volatile("mma.sync.aligned.m16n8k16.row.col.f32.f16.f16.f32 "
        "{%0,%1,%2,%3}, {%4,%5,%6,%7}, {%8,%9}, {%0,%1,%2,%3};"
        : "+f"(c[0]), "+f"(c[1]), "+f"(c[2]), "+f"(c[3])
        : "r"(a[0]), "r"(a[1]), "r"(a[2]), "r"(a[3]), "r"(b0), "r"(b1));
}
__device__ __forceinline__ void split1h(float v, __half& h, __half& l) {
    h = __float2half(v);
    l = __float2half(v - __half2float(h));
}
__device__ __forceinline__ void split2h(float a, float b, uint32_t& hi, uint32_t& lo) {
    __half2 hv, lv;
    split1h(a, hv.x, lv.x);
    split1h(b, hv.y, lv.y);
    hi = *(uint32_t*)&hv;
    lo = *(uint32_t*)&lv;
}

// ============================================================================
// fp32 -> fp16 convert (hidden states)
// ============================================================================
__global__ void __launch_bounds__(256) cvt_fp32(
    const float* __restrict__ src, __half* __restrict__ dst, int n4)
{
    int i = blockIdx.x * 256 + threadIdx.x;
    if (i >= n4) return;
    float4 x = ((const float4*)src)[i];
    ((__half2*)dst)[2 * i]     = __floats2half2_rn(x.x, x.y);
    ((__half2*)dst)[2 * i + 1] = __floats2half2_rn(x.z, x.w);
}

// all four weight matrices -> fp16 in one launch
#define N4Q (NH * D * H / 4)           // 4194304
#define N4K (NKV * D * H / 4)          // 1048576
#define N4ALL (N4Q + 2 * N4K + N4Q)

__global__ void __launch_bounds__(256) cvt_weights(
    const float* __restrict__ Wq, const float* __restrict__ Wk,
    const float* __restrict__ Wv, const float* __restrict__ Wo)
{
    int i = blockIdx.x * 256 + threadIdx.x;
    if (i >= N4ALL) return;
    const float* src;
    __half* dst;
    int j = i;
    if (j < N4Q)                { src = Wq; dst = g_wh; }
    else if ((j -= N4Q) < N4K)  { src = Wk; dst = g_wh + (size_t)NH * D * H; }
    else if ((j -= N4K) < N4K)  { src = Wv; dst = g_wh + (size_t)(NH + NKV) * D * H; }
    else { j -= N4K;              src = Wo; dst = g_woh; }
    float4 x = ((const float4*)src)[j];
    ((__half2*)dst)[2 * j]     = __floats2half2_rn(x.x, x.y);
    ((__half2*)dst)[2 * j + 1] = __floats2half2_rn(x.z, x.w);
}

// ============================================================================
// mma.sync fp16 NT GEMM (1 term): C[M,N] = A[M,K]*B[N,K]^T, fp32 out.
// Block tile 128x128x32, 8 warps (4m x 2n), warp tile 32x64.
// 3-stage cp.async ring, ONE __syncthreads per K-tile, 2 CTAs/SM.
// ============================================================================
#define ROWB 80                        // bytes per 32-fp16 row (padded)
#define MATB (128 * ROWB)              // 10240 per matrix tile
#define STGB (2 * MATB)                // A|B per stage = 20480
#define GSMEM (3 * STGB)               // 61440

__global__ void __launch_bounds__(256, 2) gemm_mma(
    const __half* __restrict__ A, const __half* __restrict__ Bm,
    float* __restrict__ C, int M, int N, int K)
{
    extern __shared__ __align__(128) char smem[];
    const uint32_t sbase = (uint32_t)__cvta_generic_to_shared(smem);
    const int tid  = threadIdx.x;
    const int lane = tid & 31;
    const int wid  = tid >> 5;
    const int warp_m = wid >> 1;   // 0..3 (32 rows each)
    const int warp_n = wid & 1;    // 0..1 (64 cols each)
    const int m0 = blockIdx.y * 128;
    const int n0 = blockIdx.x * 128;
    const int KT = K >> 5;         // K / 32

    float acc[2][8][4];
#pragma unroll
    for (int i = 0; i < 2; i++)
#pragma unroll
        for (int j = 0; j < 8; j++)
#pragma unroll
            for (int q = 0; q < 4; q++) acc[i][j][q] = 0.f;

    auto fill = [&](int s, int kt) {
        const uint32_t st = sbase + s * STGB;
#pragma unroll
        for (int i = 0; i < 4; i++) {
            const int v = ((i & 1) << 8) + tid;      // 0..511 within matrix
            const int r = v >> 2, c = v & 3;
            const __half* gb = (i < 2) ? A : Bm;
            const int grow = ((i < 2) ? m0 : n0) + r;
            cp16(st + (i >> 1) * MATB + r * ROWB + c * 16,
                 gb + (size_t)grow * K + (size_t)kt * 32 + c * 8);
        }
        asm volatile("cp.async.commit_group;" ::: "memory");
    };

    fill(0, 0); fill(1, 1); fill(2, 2);

    const uint32_t aOff = (uint32_t)((warp_m * 32 + (lane & 15)) * ROWB + ((lane >> 4) << 4));
    const uint32_t bOff = (uint32_t)(MATB + (warp_n * 64 + (lane & 15)) * ROWB + ((lane >> 4) << 4));

    for (int kt = 0; kt < KT; kt++) {
        asm volatile("cp.async.wait_group 1;" ::: "memory");
        __syncthreads();     // all warps done with iter kt-1 -> slot (kt-1)%3 free
        if (kt >= 1) {
            const int t = kt + 2;
            if (t < KT) fill(t % 3, t);
            else asm volatile("cp.async.commit_group;" ::: "memory");  // keep group count
        }

        const uint32_t st = sbase + (kt % 3) * STGB;
#pragma unroll
        for (int k16 = 0; k16 < 2; k16++) {
            const uint32_t ko = k16 * 32;
            uint32_t a[2][4], bh[4][4];
#pragma unroll
            for (int mi = 0; mi < 2; mi++)
                ldsm4(st + aOff + mi * (16 * ROWB) + ko,
                      a[mi][0], a[mi][1], a[mi][2], a[mi][3]);
#pragma unroll
            for (int ni = 0; ni < 4; ni++)
                ldsm4(st + bOff + ni * (16 * ROWB) + ko,
                      bh[ni][0], bh[ni][1], bh[ni][2], bh[ni][3]);
#pragma unroll
            for (int mi = 0; mi < 2; mi++)
#pragma unroll
                for (int ni = 0; ni < 4; ni++) {
                    mma16816(acc[mi][ni * 2],     a[mi], bh[ni][0], bh[ni][2]);
                    mma16816(acc[mi][ni * 2 + 1], a[mi], bh[ni][1], bh[ni][3]);
                }
        }
    }

#pragma unroll
    for (int mi = 0; mi < 2; mi++) {
        const int row = m0 + warp_m * 32 + mi * 16 + (lane >> 2);
#pragma unroll
        for (int nj = 0; nj < 8; nj++) {
            const int col = n0 + warp_n * 64 + nj * 8 + (lane & 3) * 2;
            float* cp0 = C + (size_t)row * N + col;
            float* cp1 = C + (size_t)(row + 8) * N + col;
            *(float2*)cp0 = make_float2(acc[mi][nj][0], acc[mi][nj][1]);
            *(float2*)cp1 = make_float2(acc[mi][nj][2], acc[mi][nj][3]);
        }
    }
}

// ============================================================================
// Per-head RMSNorm + RoPE; warp-per-head, no smem/syncthreads.
// block 256 = 8 warps = 8 heads; grid = B*S*48/8 = 12288.
// q -> fp16 (*QSCALE), k -> fp16, v -> fp16 row-major.
// ============================================================================
__global__ void __launch_bounds__(256) qkv_post(
    const float* __restrict__ cosb, const float* __restrict__ sinb,
    const float* __restrict__ qw,   const float* __restrict__ kw)
{
    const int gid  = blockIdx.x * 8 + (threadIdx.x >> 5);
    const int lane = threadIdx.x & 31;
    const int bs = gid / 48;
    const int hh = gid - bs * 48;
    const int b  = bs >> 10;          // S = 1024
    const int s  = bs & 1023;

    float4 x4 = *(const float4*)(g_qkv + (size_t)bs * NQKV + hh * D + lane * 4);
    float v0 = x4.x, v1 = x4.y, v2 = x4.z, v3 = x4.w;

    if (hh < NH + NKV) {
        float ss = v0 * v0 + v1 * v1 + v2 * v2 + v3 * v3;
#pragma unroll
        for (int o = 16; o; o >>= 1) ss += __shfl_xor_sync(0xffffffffu, ss, o);
        const float inv = rsqrtf(ss * (1.0f / D) + EPS);
        const float* wp = (hh < NH) ? qw : kw;
        float4 w4 = *(const float4*)(wp + lane * 4);
        v0 *= inv * w4.x; v1 *= inv * w4.y; v2 *= inv * w4.z; v3 *= inv * w4.w;
        // rope: partner d +/- 64 lives in lane ^ 16, same sub-index
        float p0 = __shfl_xor_sync(0xffffffffu, v0, 16);
        float p1 = __shfl_xor_sync(0xffffffffu, v1, 16);
        float p2 = __shfl_xor_sync(0xffffffffu, v2, 16);
        float p3 = __shfl_xor_sync(0xffffffffu, v3, 16);
        const float sgn = (lane < 16) ? -1.f : 1.f;
        float4 c4 = *(const float4*)(cosb + (size_t)bs * D + lane * 4);
        float4 s4 = *(const float4*)(sinb + (size_t)bs * D + lane * 4);
        v0 = v0 * c4.x + sgn * p0 * s4.x;
        v1 = v1 * c4.y + sgn * p1 * s4.y;
        v2 = v2 * c4.z + sgn * p2 * s4.z;
        v3 = v3 * c4.w + sgn * p3 * s4.w;
    }

    if (hh < NH) {
        const size_t idx = (((size_t)b * NH + hh) * S + s) * D + lane * 4;
        __half2 a = __floats2half2_rn(v0 * QSCALE, v1 * QSCALE);
        __half2 c = __floats2half2_rn(v2 * QSCALE, v3 * QSCALE);
        *(uint2*)(g_qh + idx) = make_uint2(*(uint32_t*)&a, *(uint32_t*)&c);
    } else if (hh < NH + NKV) {
        const size_t idx = (((size_t)b * NKV + (hh - NH)) * S + s) * D + lane * 4;
        __half2 a = __floats2half2_rn(v0, v1);
        __half2 c = __floats2half2_rn(v2, v3);
        *(uint2*)(g_kh + idx) = make_uint2(*(uint32_t*)&a, *(uint32_t*)&c);
    } else {
        const size_t idx = (((size_t)b * NKV + (hh - NH - NKV)) * S + s) * D + lane * 4;
        __half2 a = __floats2half2_rn(v0, v1);
        __half2 c = __floats2half2_rn(v2, v3);
        *(uint2*)(g_vrow + idx) = make_uint2(*(uint32_t*)&a, *(uint32_t*)&c);
    }
}

// ============================================================================
// Tiled transpose: g_vrow [B,NKV,S,D] -> g_vth [B,NKV,D,S]. 64x64 fp16 tiles.
// ============================================================================
__global__ void __launch_bounds__(256) v_transpose()
{
    __shared__ __half tile[64][72];
    const int s0 = blockIdx.x * 64;
    const int d0 = blockIdx.y * 64;
    const size_t base = (size_t)blockIdx.z;
    const int tid = threadIdx.x;
    const __half* src = g_vrow + base * S * D;
    __half* dst = g_vth + base * D * S;

#pragma unroll
    for (int i = tid; i < 1024; i += 256) {
        const int r = i >> 4, c4 = (i & 15) << 2;
        *(uint64_t*)&tile[r][c4] = *(const uint64_t*)(src + (size_t)(s0 + r) * D + d0 + c4);
    }
    __syncthreads();
#pragma unroll
    for (int i = tid; i < 1024; i += 256) {
        const int r = i >> 4, c4 = (i & 15) << 2;
        __half2 p0, p1;
        p0.x = tile[c4 + 0][r]; p0.y = tile[c4 + 1][r];
        p1.x = tile[c4 + 2][r]; p1.y = tile[c4 + 3][r];
        *(__half2*)(dst + (size_t)(d0 + r) * S + s0 + c4)     = p0;
        *(__half2*)(dst + (size_t)(d0 + r) * S + s0 + c4 + 2) = p1;
    }
}

// ============================================================================
// Causal flash attention: 1-term QK (scale pre-folded into q), 2-term PV.
// BM=128, BN=64, 8 warps (256 threads). 2-stage KV pipeline.
// ============================================================================
#define QROW 272                       // 128 fp16 + 8 pad
#define VROW 144                       // 64 fp16 + 8 pad
#define SQH_OFF 0
#define SK0_OFF (128 * QROW)           // 34816
#define VH_SOFF (64 * QROW)            // Vh within stage (17408)
#define KSTG    (VH_SOFF + 128 * VROW) // 35840
#define FSMEM   (SK0_OFF + 2 * KSTG)   // 106496

__global__ void __launch_bounds__(256) flash_mma()
{
    extern __shared__ __align__(128) char fsm[];
    const uint32_t sb = (uint32_t)__cvta_generic_to_shared(fsm);
    const int tid = threadIdx.x, lane = tid & 31, wid = tid >> 5;
    const int qt = (int)gridDim.x - 1 - (int)blockIdx.x;   // heavy CTAs first
    const int bh = blockIdx.y;
    const int b = bh / NH, h = bh - b * NH;
    const int kvh = h / GROUPS;

    const __half* Qhp = g_qh + (((size_t)b * NH + h) * S + (size_t)qt * 128) * D;
    const __half* Khp = g_kh + ((size_t)b * NKV + kvh) * S * D;
    const __half* Vhp = g_vth + ((size_t)b * NKV + kvh) * D * S;

#pragma unroll
    for (int i = tid; i < 2048; i += 256) {
        const int r = i >> 4, c = i & 15;
        cp16(sb + SQH_OFF + r * QROW + c * 16, Qhp + r * D + c * 8);
    }

    auto fillkv = [&](int slot, int kt) {
        const uint32_t st = sb + SK0_OFF + slot * KSTG;
        const __half* kh_ = Khp + (size_t)kt * 64 * D;
#pragma unroll
        for (int i = tid; i < 1024; i += 256) {
            const int r = i >> 4, c = i & 15;
            cp16(st + r * QROW + c * 16, kh_ + r * D + c * 8);
        }
        const __half* vh_ = Vhp + (size_t)kt * 64;
#pragma unroll
        for (int i = tid; i < 1024; i += 256) {
            const int r = i >> 3, c = i & 7;
            cp16(st + VH_SOFF + r * VROW + c * 16, vh_ + (size_t)r * S + c * 8);
        }
        asm volatile("cp.async.commit_group;" ::: "memory");
    };
    fillkv(0, 0);   // Q cp.asyncs ride this group

    float m0 = -INFINITY, m1 = -INFINITY, l0 = 0.f, l1 = 0.f;
    float o[16][4];
#pragma unroll
    for (int f = 0; f < 16; f++)
#pragma unroll
        for (int e = 0; e < 4; e++) o[f][e] = 0.f;

    const uint32_t aQ = (uint32_t)((wid * 16 + (lane & 15)) * QROW + ((lane >> 4) << 4));
    const uint32_t bK = (uint32_t)((lane & 15) * QROW + ((lane >> 4) << 4));
    const uint32_t bV = (uint32_t)((lane & 15) * VROW + ((lane >> 4) << 4));

    const int ktmax = 2 * qt + 1;

    for (int kt = 0; kt <= ktmax; kt++) {
        asm volatile("cp.async.wait_group 0;" ::: "memory");
        __syncthreads();
        if (kt < ktmax) fillkv((kt + 1) & 1, kt + 1);
        const uint32_t st = sb + SK0_OFF + (kt & 1) * KSTG;

        // ---- scores: 1-term QK (q pre-scaled by 1/sqrt(D)) ----
        float s[8][4];
#pragma unroll
        for (int f = 0; f < 8; f++)
#pragma unroll
            for (int e = 0; e < 4; e++) s[f][e] = 0.f;

#pragma unroll
        for (int ks = 0; ks < 8; ks++) {
            const uint32_t ko = ks * 32;
            uint32_t qh4[4], kh4[4][4];
            ldsm4(sb + SQH_OFF + aQ + ko, qh4[0], qh4[1], qh4[2], qh4[3]);
#pragma unroll
            for (int nb = 0; nb < 4; nb++)
                ldsm4(st + bK + nb * (16 * QROW) + ko,
                      kh4[nb][0], kh4[nb][1], kh4[nb][2], kh4[nb][3]);
#pragma unroll
            for (int nb = 0; nb < 4; nb++) {
                mma16816(s[nb * 2],     qh4, kh4[nb][0], kh4[nb][2]);
                mma16816(s[nb * 2 + 1], qh4, kh4[nb][1], kh4[nb][3]);
            }
        }

        if (kt >= 2 * qt) {
            const int r0 = qt * 128 + wid * 16 + (lane >> 2);
            const int r1 = r0 + 8;
#pragma unroll
            for (int f = 0; f < 8; f++) {
                const int c0 = kt * 64 + f * 8 + (lane & 3) * 2;
                if (c0     > r0) s[f][0] = -INFINITY;
                if (c0 + 1 > r0) s[f][1] = -INFINITY;
                if (c0     > r1) s[f][2] = -INFINITY;
                if (c0 + 1 > r1) s[f][3] = -INFINITY;
            }
        }

        float a0 = -INFINITY, a1 = -INFINITY;
#pragma unroll
        for (int f = 0; f < 8; f++) {
            a0 = fmaxf(a0, fmaxf(s[f][0], s[f][1]));
            a1 = fmaxf(a1, fmaxf(s[f][2], s[f][3]));
        }
        a0 = fmaxf(a0, __shfl_xor_sync(0xffffffffu, a0, 1));
        a0 = fmaxf(a0, __shfl_xor_sync(0xffffffffu, a0, 2));
        a1 = fmaxf(a1, __shfl_xor_sync(0xffffffffu, a1, 1));
        a1 = fmaxf(a1, __shfl_xor_sync(0xffffffffu, a1, 2));
        const float mn0 = fmaxf(m0, a0), mn1 = fmaxf(m1, a1);
        const float sc0 = exp2f((m0 - mn0) * LOG2E);
        const float sc1 = exp2f((m1 - mn1) * LOG2E);
        float rs0 = 0.f, rs1 = 0.f;
#pragma unroll
        for (int f = 0; f < 8; f++) {
            s[f][0] = exp2f((s[f][0] - mn0) * LOG2E + PBIAS);
            s[f][1] = exp2f((s[f][1] - mn0) * LOG2E + PBIAS);
            s[f][2] = exp2f((s[f][2] - mn1) * LOG2E + PBIAS);
            s[f][3] = exp2f((s[f][3] - mn1) * LOG2E + PBIAS);
            rs0 += s[f][0] + s[f][1];
            rs1 += s[f][2] + s[f][3];
        }
        rs0 += __shfl_xor_sync(0xffffffffu, rs0, 1);
        rs0 += __shfl_xor_sync(0xffffffffu, rs0, 2);
        rs1 += __shfl_xor_sync(0xffffffffu, rs1, 1);
        rs1 += __shfl_xor_sync(0xffffffffu, rs1, 2);
        m0 = mn0; m1 = mn1;
        l0 = l0 * sc0 + rs0;
        l1 = l1 * sc1 + rs1;
#pragma unroll
        for (int f = 0; f < 16; f++) {
            o[f][0] *= sc0; o[f][1] *= sc0;
            o[f][2] *= sc1; o[f][3] *= sc1;
        }

        // ---- pack P into hi/lo A-frags (2-term PV) ----
        uint32_t ph[4][4], pl[4][4];
#pragma unroll
        for (int kb = 0; kb < 4; kb++) {
            split2h(s[2 * kb][0],     s[2 * kb][1],     ph[kb][0], pl[kb][0]);
            split2h(s[2 * kb][2],     s[2 * kb][3],     ph[kb][1], pl[kb][1]);
            split2h(s[2 * kb + 1][0], s[2 * kb + 1][1], ph[kb][2], pl[kb][2]);
            split2h(s[2 * kb + 1][2], s[2 * kb + 1][3], ph[kb][3], pl[kb][3]);
        }

#pragma unroll
        for (int kb = 0; kb < 4; kb++) {
            const uint32_t ko = kb * 32;
            uint32_t vh4[8][4];
#pragma unroll
            for (int nb = 0; nb < 8; nb++)
                ldsm4(st + VH_SOFF + bV + nb * (16 * VROW) + ko,
                      vh4[nb][0], vh4[nb][1], vh4[nb][2], vh4[nb][3]);
#pragma unroll
            for (int nb = 0; nb < 8; nb++) {
                mma16816(o[nb * 2],     ph[kb], vh4[nb][0], vh4[nb][2]);
                mma16816(o[nb * 2 + 1], ph[kb], vh4[nb][1], vh4[nb][3]);
            }
#pragma unroll
            for (int nb = 0; nb < 8; nb++) {
                mma16816(o[nb * 2],     pl[kb], vh4[nb][0], vh4[nb][2]);
                mma16816(o[nb * 2 + 1], pl[kb], vh4[nb][1], vh4[nb][3]);
            }
        }
    }

    // ---- epilogue: O/l, single fp16 for 1-term O-projection ----
    const float i0 = 1.f / l0, i1 = 1.f / l1;
    const int gr0 = qt * 128 + wid * 16 + (lane >> 2);
#pragma unroll
    for (int f = 0; f < 16; f++) {
        const int d0 = f * 8 + (lane & 3) * 2;
        const size_t ix0 = ((size_t)(b * S + gr0) * NH + h) * D + d0;
        const size_t ix1 = ((size_t)(b * S + gr0 + 8) * NH + h) * D + d0;
        __half2 h0 = __floats2half2_rn(o[f][0] * i0, o[f][1] * i0);
        __half2 h1 = __floats2half2_rn(o[f][2] * i1, o[f][3] * i1);
        *(__half2*)(g_aoh + ix0) = h0;
        *(__half2*)(g_aoh + ix1) = h1;
    }
}

// ============================================================================
// host launcher
// ============================================================================
extern "C" void kernel_launch(void* const* d_in, const int* in_sizes, int n_in,
                              void* d_out, int out_size)
{
    const float* hidden = (const float*)d_in[0];
    const float* cosb   = (const float*)d_in[1];
    const float* sinb   = (const float*)d_in[2];
    const float* Wq     = (const float*)d_in[3];
    const float* Wk     = (const float*)d_in[4];
    const float* Wv     = (const float*)d_in[5];
    const float* Wo     = (const float*)d_in[6];
    const float* qw     = (const float*)d_in[7];
    const float* kw     = (const float*)d_in[8];
    float* out = (float*)d_out;

    __half *xh, *wh, *woh, *aoh;
    float* qkv;
    cudaGetSymbolAddress((void**)&xh,  g_xh);
    cudaGetSymbolAddress((void**)&wh,  g_wh);
    cudaGetSymbolAddress((void**)&woh, g_woh);
    cudaGetSymbolAddress((void**)&aoh, g_aoh);
    cudaGetSymbolAddress((void**)&qkv, g_qkv);

    cudaFuncSetAttribute(gemm_mma, cudaFuncAttributeMaxDynamicSharedMemorySize, GSMEM);
    cudaFuncSetAttribute(flash_mma, cudaFuncAttributeMaxDynamicSharedMemorySize, FSMEM);

    // conversions (2 launches)
    {
        int n4 = MSEQ * H / 4;
        cvt_fp32<<<(n4 + 255) / 256, 256>>>(hidden, xh, n4);
        cvt_weights<<<(N4ALL + 255) / 256, 256>>>(Wq, Wk, Wv, Wo);
    }

    // fused QKV projection (1-term): [2048, 6144] = X * Wqkv^T
    gemm_mma<<<dim3(NQKV / 128, MSEQ / 128), 256, GSMEM>>>(
        xh, wh, qkv, MSEQ, NQKV, H);

    // norm + rope + fp16 pack (v row-major), warp-per-head
    qkv_post<<<MSEQ * (NH + 2 * NKV) / 8, 256>>>(cosb, sinb, qw, kw);

    // v transpose [B,NKV,S,D] -> [B,NKV,D,S]
    v_transpose<<<dim3(S / 64, D / 64, B * NKV), 256>>>();

    // causal flash attention on tensor cores
    flash_mma<<<dim3(S / 128, B * NH), 256, FSMEM>>>();

    // output projection (1-term): [2048, 4096] = AO * Wo^T
    gemm_mma<<<dim3(H / 128, MSEQ / 128), 256, GSMEM>>>(
        aoh, woh, out, MSEQ, H, NH * D);
}

// round 12
// speedup vs baseline: 7.4097x; 1.0435x over previous
#include <cuda_runtime.h>
#include <cuda_fp16.h>
#include <math.h>
#include <stdint.h>

// ---------------- problem constants ----------------
#define B   2
#define S   1024
#define H   4096
#define NH  32
#define NKV 8
#define D   128
#define GROUPS (NH / NKV)   // 4
#define EPS 1e-6f
#define QSCALE 0.08838834764831845f   // 1/sqrt(128)
#define MSEQ (B * S)        // 2048 rows
#define NQKV ((NH + 2 * NKV) * D)   // 6144
#define LOG2E 1.4426950408889634f
#define PBIAS  12.0f                 // P scaled by 2^12 (cancels in O/l)

// ---------------- scratch (device globals, fp16) ----------------
__device__ __align__(16) __half g_xh [MSEQ * H];       // hidden fp16
__device__ __align__(16) __half g_wh [NQKV * H];       // stacked Wq|Wk|Wv
__device__ __align__(16) __half g_woh[H * NH * D];     // Wo
__device__ __align__(16) __half g_aoh[MSEQ * NH * D];  // attn out fp16
__device__ __align__(16) __half g_qkv[MSEQ * NQKV];    // fused QKV out (fp16)
// flash inputs: q (pre-scaled by QSCALE), k row-major, v row-major
__device__ __align__(16) __half g_qh [B * NH  * S * D];
__device__ __align__(16) __half g_kh [B * NKV * S * D];
__device__ __align__(16) __half g_vrow[B * NKV * S * D];   // [B,NKV,S,D]

// ---------------- small helpers ----------------
__device__ __forceinline__ void cp16(uint32_t dst, const void* src) {
    asm volatile("cp.async.cg.shared.global [%0], [%1], 16;" :: "r"(dst), "l"(src) : "memory");
}
__device__ __forceinline__ void ldsm4(uint32_t addr, uint32_t& r0, uint32_t& r1,
                                      uint32_t& r2, uint32_t& r3) {
    asm volatile("ldmatrix.sync.aligned.m8n8.x4.shared.b16 {%0,%1,%2,%3}, [%4];"
        : "=r"(r0), "=r"(r1), "=r"(r2), "=r"(r3) : "r"(addr));
}
__device__ __forceinline__ void ldsm4t(uint32_t addr, uint32_t& r0, uint32_t& r1,
                                       uint32_t& r2, uint32_t& r3) {
    asm volatile("ldmatrix.sync.aligned.m8n8.x4.trans.shared.b16 {%0,%1,%2,%3}, [%4];"
        : "=r"(r0), "=r"(r1), "=r"(r2), "=r"(r3) : "r"(addr));
}
__device__ __forceinline__ void mma16816(float* c, const uint32_t* a,
                                         uint32_t b0, uint32_t b1) {
    asm volatile("mma.sync.aligned.m16n8k16.row.col.f32.f16.f16.f32 "
        "{%0,%1,%2,%3}, {%4,%5,%6,%7}, {%8,%9}, {%0,%1,%2,%3};"
        : "+f"(c[0]), "+f"(c[1]), "+f"(c[2]), "+f"(c[3])
        : "r"(a[0]), "r"(a[1]), "r"(a[2]), "r"(a[3]), "r"(b0), "r"(b1));
}
__device__ __forceinline__ void store2(float* p, float a, float b) {
    *(float2*)p = make_float2(a, b);
}
__device__ __forceinline__ void store2(__half* p, float a, float b) {
    *(__half2*)p = __floats2half2_rn(a, b);
}

// ============================================================================
// fp32 -> fp16 convert (hidden states)
// ============================================================================
__global__ void __launch_bounds__(256) cvt_fp32(
    const float* __restrict__ src, __half* __restrict__ dst, int n4)
{
    int i = blockIdx.x * 256 + threadIdx.x;
    if (i >= n4) return;
    float4 x = ((const float4*)src)[i];
    ((__half2*)dst)[2 * i]     = __floats2half2_rn(x.x, x.y);
    ((__half2*)dst)[2 * i + 1] = __floats2half2_rn(x.z, x.w);
}

// all four weight matrices -> fp16 in one launch
#define N4Q (NH * D * H / 4)           // 4194304
#define N4K (NKV * D * H / 4)          // 1048576
#define N4ALL (N4Q + 2 * N4K + N4Q)

__global__ void __launch_bounds__(256) cvt_weights(
    const float* __restrict__ Wq, const float* __restrict__ Wk,
    const float* __restrict__ Wv, const float* __restrict__ Wo)
{
    int i = blockIdx.x * 256 + threadIdx.x;
    if (i >= N4ALL) return;
    const float* src;
    __half* dst;
    int j = i;
    if (j < N4Q)                { src = Wq; dst = g_wh; }
    else if ((j -= N4Q) < N4K)  { src = Wk; dst = g_wh + (size_t)NH * D * H; }
    else if ((j -= N4K) < N4K)  { src = Wv; dst = g_wh + (size_t)(NH + NKV) * D * H; }
    else { j -= N4K;              src = Wo; dst = g_woh; }
    float4 x = ((const float4*)src)[j];
    ((__half2*)dst)[2 * j]     = __floats2half2_rn(x.x, x.y);
    ((__half2*)dst)[2 * j + 1] = __floats2half2_rn(x.z, x.w);
}

// ============================================================================
// mma.sync fp16 NT GEMM (1 term): C[M,N] = A[M,K]*B[N,K]^T, OutT in {half,float}.
// Block tile 128x128x32, 8 warps (4m x 2n), warp tile 32x64.
// 3-stage cp.async ring, ONE __syncthreads per K-tile, 2 CTAs/SM.
// ============================================================================
#define ROWB 80                        // bytes per 32-fp16 row (padded)
#define MATB (128 * ROWB)              // 10240 per matrix tile
#define STGB (2 * MATB)                // A|B per stage = 20480
#define GSMEM (3 * STGB)               // 61440

template<typename OutT>
__global__ void __launch_bounds__(256, 2) gemm_mma(
    const __half* __restrict__ A, const __half* __restrict__ Bm,
    OutT* __restrict__ C, int M, int N, int K)
{
    extern __shared__ __align__(128) char smem[];
    const uint32_t sbase = (uint32_t)__cvta_generic_to_shared(smem);
    const int tid  = threadIdx.x;
    const int lane = tid & 31;
    const int wid  = tid >> 5;
    const int warp_m = wid >> 1;   // 0..3 (32 rows each)
    const int warp_n = wid & 1;    // 0..1 (64 cols each)
    const int m0 = blockIdx.y * 128;
    const int n0 = blockIdx.x * 128;
    const int KT = K >> 5;         // K / 32

    float acc[2][8][4];
#pragma unroll
    for (int i = 0; i < 2; i++)
#pragma unroll
        for (int j = 0; j < 8; j++)
#pragma unroll
            for (int q = 0; q < 4; q++) acc[i][j][q] = 0.f;

    auto fill = [&](int s, int kt) {
        const uint32_t st = sbase + s * STGB;
#pragma unroll
        for (int i = 0; i < 4; i++) {
            const int v = ((i & 1) << 8) + tid;      // 0..511 within matrix
            const int r = v >> 2, c = v & 3;
            const __half* gb = (i < 2) ? A : Bm;
            const int grow = ((i < 2) ? m0 : n0) + r;
            cp16(st + (i >> 1) * MATB + r * ROWB + c * 16,
                 gb + (size_t)grow * K + (size_t)kt * 32 + c * 8);
        }
        asm volatile("cp.async.commit_group;" ::: "memory");
    };

    fill(0, 0); fill(1, 1); fill(2, 2);

    const uint32_t aOff = (uint32_t)((warp_m * 32 + (lane & 15)) * ROWB + ((lane >> 4) << 4));
    const uint32_t bOff = (uint32_t)(MATB + (warp_n * 64 + (lane & 15)) * ROWB + ((lane >> 4) << 4));

    for (int kt = 0; kt < KT; kt++) {
        asm volatile("cp.async.wait_group 1;" ::: "memory");
        __syncthreads();     // all warps done with iter kt-1 -> slot (kt-1)%3 free
        if (kt >= 1) {
            const int t = kt + 2;
            if (t < KT) fill(t % 3, t);
            else asm volatile("cp.async.commit_group;" ::: "memory");  // keep group count
        }

        const uint32_t st = sbase + (kt % 3) * STGB;
#pragma unroll
        for (int k16 = 0; k16 < 2; k16++) {
            const uint32_t ko = k16 * 32;
            uint32_t a[2][4], bh[4][4];
#pragma unroll
            for (int mi = 0; mi < 2; mi++)
                ldsm4(st + aOff + mi * (16 * ROWB) + ko,
                      a[mi][0], a[mi][1], a[mi][2], a[mi][3]);
#pragma unroll
            for (int ni = 0; ni < 4; ni++)
                ldsm4(st + bOff + ni * (16 * ROWB) + ko,
                      bh[ni][0], bh[ni][1], bh[ni][2], bh[ni][3]);
#pragma unroll
            for (int mi = 0; mi < 2; mi++)
#pragma unroll
                for (int ni = 0; ni < 4; ni++) {
                    mma16816(acc[mi][ni * 2],     a[mi], bh[ni][0], bh[ni][2]);
                    mma16816(acc[mi][ni * 2 + 1], a[mi], bh[ni][1], bh[ni][3]);
                }
        }
    }

#pragma unroll
    for (int mi = 0; mi < 2; mi++) {
        const int row = m0 + warp_m * 32 + mi * 16 + (lane >> 2);
#pragma unroll
        for (int nj = 0; nj < 8; nj++) {
            const int col = n0 + warp_n * 64 + nj * 8 + (lane & 3) * 2;
            store2(C + (size_t)row * N + col,       acc[mi][nj][0], acc[mi][nj][1]);
            store2(C + (size_t)(row + 8) * N + col, acc[mi][nj][2], acc[mi][nj][3]);
        }
    }
}

// ============================================================================
// Per-head RMSNorm + RoPE; warp-per-head, no smem/syncthreads.
// block 256 = 8 warps = 8 heads; grid = B*S*48/8 = 12288.
// reads fp16 qkv; q -> fp16 (*QSCALE), k -> fp16, v -> fp16 row-major.
// ============================================================================
__global__ void __launch_bounds__(256) qkv_post(
    const float* __restrict__ cosb, const float* __restrict__ sinb,
    const float* __restrict__ qw,   const float* __restrict__ kw)
{
    const int gid  = blockIdx.x * 8 + (threadIdx.x >> 5);
    const int lane = threadIdx.x & 31;
    const int bs = gid / 48;
    const int hh = gid - bs * 48;
    const int b  = bs >> 10;          // S = 1024
    const int s  = bs & 1023;

    uint2 u = *(const uint2*)(g_qkv + (size_t)bs * NQKV + hh * D + lane * 4);
    const __half2 ha = *(__half2*)&u.x;
    const __half2 hb = *(__half2*)&u.y;
    float v0 = __low2float(ha), v1 = __high2float(ha);
    float v2 = __low2float(hb), v3 = __high2float(hb);

    if (hh < NH + NKV) {
        float ss = v0 * v0 + v1 * v1 + v2 * v2 + v3 * v3;
#pragma unroll
        for (int o = 16; o; o >>= 1) ss += __shfl_xor_sync(0xffffffffu, ss, o);
        const float inv = rsqrtf(ss * (1.0f / D) + EPS);
        const float* wp = (hh < NH) ? qw : kw;
        float4 w4 = *(const float4*)(wp + lane * 4);
        v0 *= inv * w4.x; v1 *= inv * w4.y; v2 *= inv * w4.z; v3 *= inv * w4.w;
        // rope: partner d +/- 64 lives in lane ^ 16, same sub-index
        float p0 = __shfl_xor_sync(0xffffffffu, v0, 16);
        float p1 = __shfl_xor_sync(0xffffffffu, v1, 16);
        float p2 = __shfl_xor_sync(0xffffffffu, v2, 16);
        float p3 = __shfl_xor_sync(0xffffffffu, v3, 16);
        const float sgn = (lane < 16) ? -1.f : 1.f;
        float4 c4 = *(const float4*)(cosb + (size_t)bs * D + lane * 4);
        float4 s4 = *(const float4*)(sinb + (size_t)bs * D + lane * 4);
        v0 = v0 * c4.x + sgn * p0 * s4.x;
        v1 = v1 * c4.y + sgn * p1 * s4.y;
        v2 = v2 * c4.z + sgn * p2 * s4.z;
        v3 = v3 * c4.w + sgn * p3 * s4.w;
    }

    if (hh < NH) {
        const size_t idx = (((size_t)b * NH + hh) * S + s) * D + lane * 4;
        __half2 a = __floats2half2_rn(v0 * QSCALE, v1 * QSCALE);
        __half2 c = __floats2half2_rn(v2 * QSCALE, v3 * QSCALE);
        *(uint2*)(g_qh + idx) = make_uint2(*(uint32_t*)&a, *(uint32_t*)&c);
    } else if (hh < NH + NKV) {
        const size_t idx = (((size_t)b * NKV + (hh - NH)) * S + s) * D + lane * 4;
        __half2 a = __floats2half2_rn(v0, v1);
        __half2 c = __floats2half2_rn(v2, v3);
        *(uint2*)(g_kh + idx) = make_uint2(*(uint32_t*)&a, *(uint32_t*)&c);
    } else {
        const size_t idx = (((size_t)b * NKV + (hh - NH - NKV)) * S + s) * D + lane * 4;
        __half2 a = __floats2half2_rn(v0, v1);
        __half2 c = __floats2half2_rn(v2, v3);
        *(uint2*)(g_vrow + idx) = make_uint2(*(uint32_t*)&a, *(uint32_t*)&c);
    }
}

// ============================================================================
// Causal flash attention: 1-term QK (scale pre-folded into q), 1-term PV.
// V loaded row-major, consumed via ldmatrix.trans (no transpose kernel).
// BM=128, BN=64, 8 warps (256 threads). 2-stage KV pipeline.
// ============================================================================
#define QROW 272                       // 128 fp16 + 8 pad (17 x 16B, conflict-free)
#define SQH_OFF 0
#define SK0_OFF (128 * QROW)           // 34816
#define VH_SOFF (64 * QROW)            // V within stage (17408): 64 s-rows x 128 d
#define KSTG    (2 * 64 * QROW)        // 34816
#define FSMEM   (SK0_OFF + 2 * KSTG)   // 104448

__global__ void __launch_bounds__(256) flash_mma()
{
    extern __shared__ __align__(128) char fsm[];
    const uint32_t sb = (uint32_t)__cvta_generic_to_shared(fsm);
    const int tid = threadIdx.x, lane = tid & 31, wid = tid >> 5;
    const int qt = (int)gridDim.x - 1 - (int)blockIdx.x;   // heavy CTAs first
    const int bh = blockIdx.y;
    const int b = bh / NH, h = bh - b * NH;
    const int kvh = h / GROUPS;

    const __half* Qhp = g_qh + (((size_t)b * NH + h) * S + (size_t)qt * 128) * D;
    const __half* Khp = g_kh + ((size_t)b * NKV + kvh) * S * D;
    const __half* Vhp = g_vrow + ((size_t)b * NKV + kvh) * S * D;

#pragma unroll
    for (int i = tid; i < 2048; i += 256) {
        const int r = i >> 4, c = i & 15;
        cp16(sb + SQH_OFF + r * QROW + c * 16, Qhp + r * D + c * 8);
    }

    auto fillkv = [&](int slot, int kt) {
        const uint32_t st = sb + SK0_OFF + slot * KSTG;
        const __half* kh_ = Khp + (size_t)kt * 64 * D;
        const __half* vh_ = Vhp + (size_t)kt * 64 * D;
#pragma unroll
        for (int i = tid; i < 1024; i += 256) {
            const int r = i >> 4, c = i & 15;
            cp16(st + r * QROW + c * 16,           kh_ + r * D + c * 8);
            cp16(st + VH_SOFF + r * QROW + c * 16, vh_ + r * D + c * 8);
        }
        asm volatile("cp.async.commit_group;" ::: "memory");
    };
    fillkv(0, 0);   // Q cp.asyncs ride this group

    float m0 = -INFINITY, m1 = -INFINITY, l0 = 0.f, l1 = 0.f;
    float o[16][4];
#pragma unroll
    for (int f = 0; f < 16; f++)
#pragma unroll
        for (int e = 0; e < 4; e++) o[f][e] = 0.f;

    const uint32_t aQ = (uint32_t)((wid * 16 + (lane & 15)) * QROW + ((lane >> 4) << 4));
    const uint32_t bK = (uint32_t)((lane & 15) * QROW + ((lane >> 4) << 4));
    // V trans-load: rows = s (k dim), 16B col-half selects d 0-7 / 8-15 within pair
    const uint32_t bV = (uint32_t)((lane & 15) * QROW + ((lane >> 4) << 4));

    const int ktmax = 2 * qt + 1;

    for (int kt = 0; kt <= ktmax; kt++) {
        asm volatile("cp.async.wait_group 0;" ::: "memory");
        __syncthreads();
        if (kt < ktmax) fillkv((kt + 1) & 1, kt + 1);
        const uint32_t st = sb + SK0_OFF + (kt & 1) * KSTG;

        // ---- scores: 1-term QK (q pre-scaled by 1/sqrt(D)) ----
        float s[8][4];
#pragma unroll
        for (int f = 0; f < 8; f++)
#pragma unroll
            for (int e = 0; e < 4; e++) s[f][e] = 0.f;

#pragma unroll
        for (int ks = 0; ks < 8; ks++) {
            const uint32_t ko = ks * 32;
            uint32_t qh4[4], kh4[4][4];
            ldsm4(sb + SQH_OFF + aQ + ko, qh4[0], qh4[1], qh4[2], qh4[3]);
#pragma unroll
            for (int nb = 0; nb < 4; nb++)
                ldsm4(st + bK + nb * (16 * QROW) + ko,
                      kh4[nb][0], kh4[nb][1], kh4[nb][2], kh4[nb][3]);
#pragma unroll
            for (int nb = 0; nb < 4; nb++) {
                mma16816(s[nb * 2],     qh4, kh4[nb][0], kh4[nb][2]);
                mma16816(s[nb * 2 + 1], qh4, kh4[nb][1], kh4[nb][3]);
            }
        }

        if (kt >= 2 * qt) {
            const int r0 = qt * 128 + wid * 16 + (lane >> 2);
            const int r1 = r0 + 8;
#pragma unroll
            for (int f = 0; f < 8; f++) {
                const int c0 = kt * 64 + f * 8 + (lane & 3) * 2;
                if (c0     > r0) s[f][0] = -INFINITY;
                if (c0 + 1 > r0) s[f][1] = -INFINITY;
                if (c0     > r1) s[f][2] = -INFINITY;
                if (c0 + 1 > r1) s[f][3] = -INFINITY;
            }
        }

        float a0 = -INFINITY, a1 = -INFINITY;
#pragma unroll
        for (int f = 0; f < 8; f++) {
            a0 = fmaxf(a0, fmaxf(s[f][0], s[f][1]));
            a1 = fmaxf(a1, fmaxf(s[f][2], s[f][3]));
        }
        a0 = fmaxf(a0, __shfl_xor_sync(0xffffffffu, a0, 1));
        a0 = fmaxf(a0, __shfl_xor_sync(0xffffffffu, a0, 2));
        a1 = fmaxf(a1, __shfl_xor_sync(0xffffffffu, a1, 1));
        a1 = fmaxf(a1, __shfl_xor_sync(0xffffffffu, a1, 2));
        const float mn0 = fmaxf(m0, a0), mn1 = fmaxf(m1, a1);
        const float sc0 = exp2f((m0 - mn0) * LOG2E);
        const float sc1 = exp2f((m1 - mn1) * LOG2E);
        float rs0 = 0.f, rs1 = 0.f;
#pragma unroll
        for (int f = 0; f < 8; f++) {
            s[f][0] = exp2f((s[f][0] - mn0) * LOG2E + PBIAS);
            s[f][1] = exp2f((s[f][1] - mn0) * LOG2E + PBIAS);
            s[f][2] = exp2f((s[f][2] - mn1) * LOG2E + PBIAS);
            s[f][3] = exp2f((s[f][3] - mn1) * LOG2E + PBIAS);
            rs0 += s[f][0] + s[f][1];
            rs1 += s[f][2] + s[f][3];
        }
        rs0 += __shfl_xor_sync(0xffffffffu, rs0, 1);
        rs0 += __shfl_xor_sync(0xffffffffu, rs0, 2);
        rs1 += __shfl_xor_sync(0xffffffffu, rs1, 1);
        rs1 += __shfl_xor_sync(0xffffffffu, rs1, 2);
        m0 = mn0; m1 = mn1;
        l0 = l0 * sc0 + rs0;
        l1 = l1 * sc1 + rs1;
#pragma unroll
        for (int f = 0; f < 16; f++) {
            o[f][0] *= sc0; o[f][1] *= sc0;
            o[f][2] *= sc1; o[f][3] *= sc1;
        }

        // ---- pack P to fp16 A-frags (1-term PV) ----
        uint32_t ph[4][4];
#pragma unroll
        for (int kb = 0; kb < 4; kb++) {
            __half2 t;
            t = __floats2half2_rn(s[2 * kb][0],     s[2 * kb][1]);     ph[kb][0] = *(uint32_t*)&t;
            t = __floats2half2_rn(s[2 * kb][2],     s[2 * kb][3]);     ph[kb][1] = *(uint32_t*)&t;
            t = __floats2half2_rn(s[2 * kb + 1][0], s[2 * kb + 1][1]); ph[kb][2] = *(uint32_t*)&t;
            t = __floats2half2_rn(s[2 * kb + 1][2], s[2 * kb + 1][3]); ph[kb][3] = *(uint32_t*)&t;
        }

        // ---- PV: 1-term, row-major V via ldmatrix.trans ----
#pragma unroll
        for (int kb = 0; kb < 4; kb++) {
#pragma unroll
            for (int dp = 0; dp < 8; dp++) {
                uint32_t v0, v1, v2, v3;
                ldsm4t(st + VH_SOFF + bV + kb * (16 * QROW) + dp * 32, v0, v1, v2, v3);
                mma16816(o[dp * 2],     ph[kb], v0, v1);
                mma16816(o[dp * 2 + 1], ph[kb], v2, v3);
            }
        }
    }

    // ---- epilogue: O/l, single fp16 for 1-term O-projection ----
    const float i0 = 1.f / l0, i1 = 1.f / l1;
    const int gr0 = qt * 128 + wid * 16 + (lane >> 2);
#pragma unroll
    for (int f = 0; f < 16; f++) {
        const int d0 = f * 8 + (lane & 3) * 2;
        const size_t ix0 = ((size_t)(b * S + gr0) * NH + h) * D + d0;
        const size_t ix1 = ((size_t)(b * S + gr0 + 8) * NH + h) * D + d0;
        __half2 h0 = __floats2half2_rn(o[f][0] * i0, o[f][1] * i0);
        __half2 h1 = __floats2half2_rn(o[f][2] * i1, o[f][3] * i1);
        *(__half2*)(g_aoh + ix0) = h0;
        *(__half2*)(g_aoh + ix1) = h1;
    }
}

// ============================================================================
// host launcher
// ============================================================================
extern "C" void kernel_launch(void* const* d_in, const int* in_sizes, int n_in,
                              void* d_out, int out_size)
{
    const float* hidden = (const float*)d_in[0];
    const float* cosb   = (const float*)d_in[1];
    const float* sinb   = (const float*)d_in[2];
    const float* Wq     = (const float*)d_in[3];
    const float* Wk     = (const float*)d_in[4];
    const float* Wv     = (const float*)d_in[5];
    const float* Wo     = (const float*)d_in[6];
    const float* qw     = (const float*)d_in[7];
    const float* kw     = (const float*)d_in[8];
    float* out = (float*)d_out;

    __half *xh, *wh, *woh, *aoh, *qkv;
    cudaGetSymbolAddress((void**)&xh,  g_xh);
    cudaGetSymbolAddress((void**)&wh,  g_wh);
    cudaGetSymbolAddress((void**)&woh, g_woh);
    cudaGetSymbolAddress((void**)&aoh, g_aoh);
    cudaGetSymbolAddress((void**)&qkv, g_qkv);

    cudaFuncSetAttribute(gemm_mma<__half>, cudaFuncAttributeMaxDynamicSharedMemorySize, GSMEM);
    cudaFuncSetAttribute(gemm_mma<float>,  cudaFuncAttributeMaxDynamicSharedMemorySize, GSMEM);
    cudaFuncSetAttribute(flash_mma, cudaFuncAttributeMaxDynamicSharedMemorySize, FSMEM);

    // conversions (2 launches)
    {
        int n4 = MSEQ * H / 4;
        cvt_fp32<<<(n4 + 255) / 256, 256>>>(hidden, xh, n4);
        cvt_weights<<<(N4ALL + 255) / 256, 256>>>(Wq, Wk, Wv, Wo);
    }

    // fused QKV projection (1-term, fp16 out): [2048, 6144] = X * Wqkv^T
    gemm_mma<__half><<<dim3(NQKV / 128, MSEQ / 128), 256, GSMEM>>>(
        xh, wh, qkv, MSEQ, NQKV, H);

    // norm + rope + fp16 pack (v row-major), warp-per-head
    qkv_post<<<MSEQ * (NH + 2 * NKV) / 8, 256>>>(cosb, sinb, qw, kw);

    // causal flash attention on tensor cores
    flash_mma<<<dim3(S / 128, B * NH), 256, FSMEM>>>();

    // output projection (1-term, fp32 out): [2048, 4096] = AO * Wo^T
    gemm_mma<float><<<dim3(H / 128, MSEQ / 128), 256, GSMEM>>>(
        aoh, woh, out, MSEQ, H, NH * D);
}

// round 13
// speedup vs baseline: 7.4411x; 1.0042x over previous
#include <cuda_runtime.h>
#include <cuda_fp16.h>
#include <math.h>
#include <stdint.h>

// ---------------- problem constants ----------------
#define B   2
#define S   1024
#define H   4096
#define NH  32
#define NKV 8
#define D   128
#define GROUPS (NH / NKV)   // 4
#define EPS 1e-6f
#define QSCALE 0.08838834764831845f   // 1/sqrt(128)
#define MSEQ (B * S)        // 2048 rows
#define NQKV ((NH + 2 * NKV) * D)   // 6144
#define LOG2E 1.4426950408889634f
#define PBIAS  12.0f                 // P scaled by 2^12 (cancels in O/l)

// ---------------- scratch (device globals, fp16) ----------------
__device__ __align__(16) __half g_xh [MSEQ * H];       // hidden fp16
__device__ __align__(16) __half g_wh [NQKV * H];       // stacked Wq|Wk|Wv
__device__ __align__(16) __half g_woh[H * NH * D];     // Wo
__device__ __align__(16) __half g_aoh[MSEQ * NH * D];  // attn out fp16
// flash inputs: q (pre-scaled by QSCALE), k row-major, v row-major
__device__ __align__(16) __half g_qh [B * NH  * S * D];
__device__ __align__(16) __half g_kh [B * NKV * S * D];
__device__ __align__(16) __half g_vrow[B * NKV * S * D];   // [B,NKV,S,D]

// ---------------- small helpers ----------------
__device__ __forceinline__ void cp16(uint32_t dst, const void* src) {
    asm volatile("cp.async.cg.shared.global [%0], [%1], 16;" :: "r"(dst), "l"(src) : "memory");
}
__device__ __forceinline__ void ldsm4(uint32_t addr, uint32_t& r0, uint32_t& r1,
                                      uint32_t& r2, uint32_t& r3) {
    asm volatile("ldmatrix.sync.aligned.m8n8.x4.shared.b16 {%0,%1,%2,%3}, [%4];"
        : "=r"(r0), "=r"(r1), "=r"(r2), "=r"(r3) : "r"(addr));
}
__device__ __forceinline__ void ldsm4t(uint32_t addr, uint32_t& r0, uint32_t& r1,
                                       uint32_t& r2, uint32_t& r3) {
    asm volatile("ldmatrix.sync.aligned.m8n8.x4.trans.shared.b16 {%0,%1,%2,%3}, [%4];"
        : "=r"(r0), "=r"(r1), "=r"(r2), "=r"(r3) : "r"(addr));
}
__device__ __forceinline__ void mma16816(float* c, const uint32_t* a,
                                         uint32_t b0, uint32_t b1) {
    asm volatile("mma.sync.aligned.m16n8k16.row.col.f32.f16.f16.f32 "
        "{%0,%1,%2,%3}, {%4,%5,%6,%7}, {%8,%9}, {%0,%1,%2,%3};"
        : "+f"(c[0]), "+f"(c[1]), "+f"(c[2]), "+f"(c[3])
        : "r"(a[0]), "r"(a[1]), "r"(a[2]), "r"(a[3]), "r"(b0), "r"(b1));
}

// ============================================================================
// fp32 -> fp16 convert (hidden states)
// ============================================================================
__global__ void __launch_bounds__(256) cvt_fp32(
    const float* __restrict__ src, __half* __restrict__ dst, int n4)
{
    int i = blockIdx.x * 256 + threadIdx.x;
    if (i >= n4) return;
    float4 x = ((const float4*)src)[i];
    ((__half2*)dst)[2 * i]     = __floats2half2_rn(x.x, x.y);
    ((__half2*)dst)[2 * i + 1] = __floats2half2_rn(x.z, x.w);
}

// all four weight matrices -> fp16 in one launch
#define N4Q (NH * D * H / 4)           // 4194304
#define N4K (NKV * D * H / 4)          // 1048576
#define N4ALL (N4Q + 2 * N4K + N4Q)

__global__ void __launch_bounds__(256) cvt_weights(
    const float* __restrict__ Wq, const float* __restrict__ Wk,
    const float* __restrict__ Wv, const float* __restrict__ Wo)
{
    int i = blockIdx.x * 256 + threadIdx.x;
    if (i >= N4ALL) return;
    const float* src;
    __half* dst;
    int j = i;
    if (j < N4Q)                { src = Wq; dst = g_wh; }
    else if ((j -= N4Q) < N4K)  { src = Wk; dst = g_wh + (size_t)NH * D * H; }
    else if ((j -= N4K) < N4K)  { src = Wv; dst = g_wh + (size_t)(NH + NKV) * D * H; }
    else { j -= N4K;              src = Wo; dst = g_woh; }
    float4 x = ((const float4*)src)[j];
    ((__half2*)dst)[2 * j]     = __floats2half2_rn(x.x, x.y);
    ((__half2*)dst)[2 * j + 1] = __floats2half2_rn(x.z, x.w);
}

// ============================================================================
// mma.sync fp16 NT GEMM (1 term): C[M,N] = A[M,K]*B[N,K]^T.
// Block tile 128x128x32, 8 warps (4m x 2n), warp tile 32x64.
// 3-stage cp.async ring, ONE __syncthreads per K-tile, 2 CTAs/SM.
// FUSED=false: plain fp32 store to C.
// FUSED=true (QKV): one N-tile == one head. Epilogue applies per-row RMSNorm
//   (+ RoPE for q/k) and writes g_qh (x QSCALE) / g_kh / g_vrow directly.
// ============================================================================
#define ROWB 80                        // bytes per 32-fp16 row (padded)
#define MATB (128 * ROWB)              // 10240 per matrix tile
#define STGB (2 * MATB)                // A|B per stage = 20480
#define GSMEM_PIPE (3 * STGB)          // 61440
#define EPI_PITCH 132                  // fp32 stage row pitch (pad vs bank conflicts)
#define GSMEM_EPI  (128 * EPI_PITCH * 4 + 128 * 2 * 4)   // 67584 + 1024 = 68608
#define GSMEM_QKV  GSMEM_EPI           // > GSMEM_PIPE
#define GSMEM_O    GSMEM_PIPE

template<bool FUSED>
__global__ void __launch_bounds__(256, 2) gemm_mma(
    const __half* __restrict__ A, const __half* __restrict__ Bm,
    float* __restrict__ C, int M, int N, int K,
    const float* __restrict__ cosb, const float* __restrict__ sinb,
    const float* __restrict__ qw,   const float* __restrict__ kw)
{
    extern __shared__ __align__(128) char smem[];
    const uint32_t sbase = (uint32_t)__cvta_generic_to_shared(smem);
    const int tid  = threadIdx.x;
    const int lane = tid & 31;
    const int wid  = tid >> 5;
    const int warp_m = wid >> 1;   // 0..3 (32 rows each)
    const int warp_n = wid & 1;    // 0..1 (64 cols each)
    const int m0 = blockIdx.y * 128;
    const int n0 = blockIdx.x * 128;
    const int KT = K >> 5;         // K / 32

    float acc[2][8][4];
#pragma unroll
    for (int i = 0; i < 2; i++)
#pragma unroll
        for (int j = 0; j < 8; j++)
#pragma unroll
            for (int q = 0; q < 4; q++) acc[i][j][q] = 0.f;

    auto fill = [&](int s, int kt) {
        const uint32_t st = sbase + s * STGB;
#pragma unroll
        for (int i = 0; i < 4; i++) {
            const int v = ((i & 1) << 8) + tid;      // 0..511 within matrix
            const int r = v >> 2, c = v & 3;
            const __half* gb = (i < 2) ? A : Bm;
            const int grow = ((i < 2) ? m0 : n0) + r;
            cp16(st + (i >> 1) * MATB + r * ROWB + c * 16,
                 gb + (size_t)grow * K + (size_t)kt * 32 + c * 8);
        }
        asm volatile("cp.async.commit_group;" ::: "memory");
    };

    fill(0, 0); fill(1, 1); fill(2, 2);

    const uint32_t aOff = (uint32_t)((warp_m * 32 + (lane & 15)) * ROWB + ((lane >> 4) << 4));
    const uint32_t bOff = (uint32_t)(MATB + (warp_n * 64 + (lane & 15)) * ROWB + ((lane >> 4) << 4));

    for (int kt = 0; kt < KT; kt++) {
        asm volatile("cp.async.wait_group 1;" ::: "memory");
        __syncthreads();     // all warps done with iter kt-1 -> slot (kt-1)%3 free
        if (kt >= 1) {
            const int t = kt + 2;
            if (t < KT) fill(t % 3, t);
            else asm volatile("cp.async.commit_group;" ::: "memory");  // keep group count
        }

        const uint32_t st = sbase + (kt % 3) * STGB;
#pragma unroll
        for (int k16 = 0; k16 < 2; k16++) {
            const uint32_t ko = k16 * 32;
            uint32_t a[2][4], bh[4][4];
#pragma unroll
            for (int mi = 0; mi < 2; mi++)
                ldsm4(st + aOff + mi * (16 * ROWB) + ko,
                      a[mi][0], a[mi][1], a[mi][2], a[mi][3]);
#pragma unroll
            for (int ni = 0; ni < 4; ni++)
                ldsm4(st + bOff + ni * (16 * ROWB) + ko,
                      bh[ni][0], bh[ni][1], bh[ni][2], bh[ni][3]);
#pragma unroll
            for (int mi = 0; mi < 2; mi++)
#pragma unroll
                for (int ni = 0; ni < 4; ni++) {
                    mma16816(acc[mi][ni * 2],     a[mi], bh[ni][0], bh[ni][2]);
                    mma16816(acc[mi][ni * 2 + 1], a[mi], bh[ni][1], bh[ni][3]);
                }
        }
    }

    if (!FUSED) {
        // ---- plain fp32 epilogue ----
#pragma unroll
        for (int mi = 0; mi < 2; mi++) {
            const int row = m0 + warp_m * 32 + mi * 16 + (lane >> 2);
#pragma unroll
            for (int nj = 0; nj < 8; nj++) {
                const int col = n0 + warp_n * 64 + nj * 8 + (lane & 3) * 2;
                *(float2*)(C + (size_t)row * N + col) =
                    make_float2(acc[mi][nj][0], acc[mi][nj][1]);
                *(float2*)(C + (size_t)(row + 8) * N + col) =
                    make_float2(acc[mi][nj][2], acc[mi][nj][3]);
            }
        }
        return;
    }

    // ---- fused QKV epilogue: this N-tile is one head (hs = n0/128) ----
    asm volatile("cp.async.wait_group 0;" ::: "memory");
    __syncthreads();   // pipeline smem now free for staging

    const int hs = n0 >> 7;
    const int rbase = warp_m * 32 + (lane >> 2);   // block-local row for mi=0, half 0

    if (hs >= NH + NKV) {
        // V head: straight fp16 store, no norm
        const int vh = hs - NH - NKV;
#pragma unroll
        for (int mi = 0; mi < 2; mi++) {
            const int rl = rbase + mi * 16;
#pragma unroll
            for (int nj = 0; nj < 8; nj++) {
                const int d = warp_n * 64 + nj * 8 + (lane & 3) * 2;
                const int bs0 = m0 + rl, bs1 = bs0 + 8;
                const size_t i0 = (((size_t)(bs0 >> 10) * NKV + vh) * S + (bs0 & 1023)) * D + d;
                const size_t i1 = (((size_t)(bs1 >> 10) * NKV + vh) * S + (bs1 & 1023)) * D + d;
                *(__half2*)(g_vrow + i0) = __floats2half2_rn(acc[mi][nj][0], acc[mi][nj][1]);
                *(__half2*)(g_vrow + i1) = __floats2half2_rn(acc[mi][nj][2], acc[mi][nj][3]);
            }
        }
        return;
    }

    const bool isQ = (hs < NH);
    float* sst  = (float*)smem;                 // [128][EPI_PITCH] staged normalized tile
    float* ssum = sst + 128 * EPI_PITCH;        // [128][2] per-row half-sums

    // 1. per-row sum of squares (this warp's 64-col half)
#pragma unroll
    for (int mi = 0; mi < 2; mi++) {
        float s0 = 0.f, s1 = 0.f;
#pragma unroll
        for (int nj = 0; nj < 8; nj++) {
            s0 += acc[mi][nj][0] * acc[mi][nj][0] + acc[mi][nj][1] * acc[mi][nj][1];
            s1 += acc[mi][nj][2] * acc[mi][nj][2] + acc[mi][nj][3] * acc[mi][nj][3];
        }
        s0 += __shfl_xor_sync(0xffffffffu, s0, 1);
        s0 += __shfl_xor_sync(0xffffffffu, s0, 2);
        s1 += __shfl_xor_sync(0xffffffffu, s1, 1);
        s1 += __shfl_xor_sync(0xffffffffu, s1, 2);
        if ((lane & 3) == 0) {
            ssum[(rbase + mi * 16) * 2 + warp_n]     = s0;
            ssum[(rbase + mi * 16 + 8) * 2 + warp_n] = s1;
        }
    }
    __syncthreads();

    // 2. normalize * weight, stage fp32
    const float* wp = isQ ? qw : kw;
#pragma unroll
    for (int mi = 0; mi < 2; mi++) {
        const int r0 = rbase + mi * 16, r1 = r0 + 8;
        const float inv0 = rsqrtf((ssum[r0 * 2] + ssum[r0 * 2 + 1]) * (1.0f / D) + EPS);
        const float inv1 = rsqrtf((ssum[r1 * 2] + ssum[r1 * 2 + 1]) * (1.0f / D) + EPS);
#pragma unroll
        for (int nj = 0; nj < 8; nj++) {
            const int d = warp_n * 64 + nj * 8 + (lane & 3) * 2;
            const float2 w2 = *(const float2*)(wp + d);
            sst[r0 * EPI_PITCH + d]     = acc[mi][nj][0] * inv0 * w2.x;
            sst[r0 * EPI_PITCH + d + 1] = acc[mi][nj][1] * inv0 * w2.y;
            sst[r1 * EPI_PITCH + d]     = acc[mi][nj][2] * inv1 * w2.x;
            sst[r1 * EPI_PITCH + d + 1] = acc[mi][nj][3] * inv1 * w2.y;
        }
    }
    __syncthreads();

    // 3. rope (partner = d ^ 64) + store fp16
    const float oscale = isQ ? QSCALE : 1.0f;
#pragma unroll
    for (int mi = 0; mi < 2; mi++) {
        const int rl0 = rbase + mi * 16;
#pragma unroll
        for (int half = 0; half < 2; half++) {
            const int rl = rl0 + half * 8;
            const int bs = m0 + rl;
            const int b  = bs >> 10, s = bs & 1023;
#pragma unroll
            for (int nj = 0; nj < 8; nj++) {
                const int d = warp_n * 64 + nj * 8 + (lane & 3) * 2;
                const float2 c2 = *(const float2*)(cosb + (size_t)bs * D + d);
                const float2 s2 = *(const float2*)(sinb + (size_t)bs * D + d);
                const float v0 = sst[rl * EPI_PITCH + d];
                const float v1 = sst[rl * EPI_PITCH + d + 1];
                const float p0 = sst[rl * EPI_PITCH + (d ^ 64)];
                const float p1 = sst[rl * EPI_PITCH + (d ^ 64) + 1];
                const float sgn = (d < 64) ? -1.f : 1.f;
                const float o0 = (v0 * c2.x + sgn * p0 * s2.x) * oscale;
                const float o1 = (v1 * c2.y + sgn * p1 * s2.y) * oscale;
                if (isQ) {
                    const size_t ix = (((size_t)b * NH + hs) * S + s) * D + d;
                    *(__half2*)(g_qh + ix) = __floats2half2_rn(o0, o1);
                } else {
                    const size_t ix = (((size_t)b * NKV + (hs - NH)) * S + s) * D + d;
                    *(__half2*)(g_kh + ix) = __floats2half2_rn(o0, o1);
                }
            }
        }
    }
}

// ============================================================================
// Causal flash attention: 1-term QK (scale pre-folded into q), 1-term PV.
// V loaded row-major, consumed via ldmatrix.trans (no transpose kernel).
// BM=128, BN=64, 8 warps (256 threads). 2-stage KV pipeline.
// ============================================================================
#define QROW 272                       // 128 fp16 + 8 pad (17 x 16B, conflict-free)
#define SQH_OFF 0
#define SK0_OFF (128 * QROW)           // 34816
#define VH_SOFF (64 * QROW)            // V within stage (17408): 64 s-rows x 128 d
#define KSTG    (2 * 64 * QROW)        // 34816
#define FSMEM   (SK0_OFF + 2 * KSTG)   // 104448

__global__ void __launch_bounds__(256) flash_mma()
{
    extern __shared__ __align__(128) char fsm[];
    const uint32_t sb = (uint32_t)__cvta_generic_to_shared(fsm);
    const int tid = threadIdx.x, lane = tid & 31, wid = tid >> 5;
    const int qt = (int)gridDim.x - 1 - (int)blockIdx.x;   // heavy CTAs first
    const int bh = blockIdx.y;
    const int b = bh / NH, h = bh - b * NH;
    const int kvh = h / GROUPS;

    const __half* Qhp = g_qh + (((size_t)b * NH + h) * S + (size_t)qt * 128) * D;
    const __half* Khp = g_kh + ((size_t)b * NKV + kvh) * S * D;
    const __half* Vhp = g_vrow + ((size_t)b * NKV + kvh) * S * D;

#pragma unroll
    for (int i = tid; i < 2048; i += 256) {
        const int r = i >> 4, c = i & 15;
        cp16(sb + SQH_OFF + r * QROW + c * 16, Qhp + r * D + c * 8);
    }

    auto fillkv = [&](int slot, int kt) {
        const uint32_t st = sb + SK0_OFF + slot * KSTG;
        const __half* kh_ = Khp + (size_t)kt * 64 * D;
        const __half* vh_ = Vhp + (size_t)kt * 64 * D;
#pragma unroll
        for (int i = tid; i < 1024; i += 256) {
            const int r = i >> 4, c = i & 15;
            cp16(st + r * QROW + c * 16,           kh_ + r * D + c * 8);
            cp16(st + VH_SOFF + r * QROW + c * 16, vh_ + r * D + c * 8);
        }
        asm volatile("cp.async.commit_group;" ::: "memory");
    };
    fillkv(0, 0);   // Q cp.asyncs ride this group

    float m0 = -INFINITY, m1 = -INFINITY, l0 = 0.f, l1 = 0.f;
    float o[16][4];
#pragma unroll
    for (int f = 0; f < 16; f++)
#pragma unroll
        for (int e = 0; e < 4; e++) o[f][e] = 0.f;

    const uint32_t aQ = (uint32_t)((wid * 16 + (lane & 15)) * QROW + ((lane >> 4) << 4));
    const uint32_t bK = (uint32_t)((lane & 15) * QROW + ((lane >> 4) << 4));
    const uint32_t bV = (uint32_t)((lane & 15) * QROW + ((lane >> 4) << 4));

    const int ktmax = 2 * qt + 1;

    for (int kt = 0; kt <= ktmax; kt++) {
        asm volatile("cp.async.wait_group 0;" ::: "memory");
        __syncthreads();
        if (kt < ktmax) fillkv((kt + 1) & 1, kt + 1);
        const uint32_t st = sb + SK0_OFF + (kt & 1) * KSTG;

        // ---- scores: 1-term QK (q pre-scaled by 1/sqrt(D)) ----
        float s[8][4];
#pragma unroll
        for (int f = 0; f < 8; f++)
#pragma unroll
            for (int e = 0; e < 4; e++) s[f][e] = 0.f;

#pragma unroll
        for (int ks = 0; ks < 8; ks++) {
            const uint32_t ko = ks * 32;
            uint32_t qh4[4], kh4[4][4];
            ldsm4(sb + SQH_OFF + aQ + ko, qh4[0], qh4[1], qh4[2], qh4[3]);
#pragma unroll
            for (int nb = 0; nb < 4; nb++)
                ldsm4(st + bK + nb * (16 * QROW) + ko,
                      kh4[nb][0], kh4[nb][1], kh4[nb][2], kh4[nb][3]);
#pragma unroll
            for (int nb = 0; nb < 4; nb++) {
                mma16816(s[nb * 2],     qh4, kh4[nb][0], kh4[nb][2]);
                mma16816(s[nb * 2 + 1], qh4, kh4[nb][1], kh4[nb][3]);
            }
        }

        if (kt >= 2 * qt) {
            const int r0 = qt * 128 + wid * 16 + (lane >> 2);
            const int r1 = r0 + 8;
#pragma unroll
            for (int f = 0; f < 8; f++) {
                const int c0 = kt * 64 + f * 8 + (lane & 3) * 2;
                if (c0     > r0) s[f][0] = -INFINITY;
                if (c0 + 1 > r0) s[f][1] = -INFINITY;
                if (c0     > r1) s[f][2] = -INFINITY;
                if (c0 + 1 > r1) s[f][3] = -INFINITY;
            }
        }

        float a0 = -INFINITY, a1 = -INFINITY;
#pragma unroll
        for (int f = 0; f < 8; f++) {
            a0 = fmaxf(a0, fmaxf(s[f][0], s[f][1]));
            a1 = fmaxf(a1, fmaxf(s[f][2], s[f][3]));
        }
        a0 = fmaxf(a0, __shfl_xor_sync(0xffffffffu, a0, 1));
        a0 = fmaxf(a0, __shfl_xor_sync(0xffffffffu, a0, 2));
        a1 = fmaxf(a1, __shfl_xor_sync(0xffffffffu, a1, 1));
        a1 = fmaxf(a1, __shfl_xor_sync(0xffffffffu, a1, 2));
        const float mn0 = fmaxf(m0, a0), mn1 = fmaxf(m1, a1);
        const float sc0 = exp2f((m0 - mn0) * LOG2E);
        const float sc1 = exp2f((m1 - mn1) * LOG2E);
        float rs0 = 0.f, rs1 = 0.f;
#pragma unroll
        for (int f = 0; f < 8; f++) {
            s[f][0] = exp2f((s[f][0] - mn0) * LOG2E + PBIAS);
            s[f][1] = exp2f((s[f][1] - mn0) * LOG2E + PBIAS);
            s[f][2] = exp2f((s[f][2] - mn1) * LOG2E + PBIAS);
            s[f][3] = exp2f((s[f][3] - mn1) * LOG2E + PBIAS);
            rs0 += s[f][0] + s[f][1];
            rs1 += s[f][2] + s[f][3];
        }
        rs0 += __shfl_xor_sync(0xffffffffu, rs0, 1);
        rs0 += __shfl_xor_sync(0xffffffffu, rs0, 2);
        rs1 += __shfl_xor_sync(0xffffffffu, rs1, 1);
        rs1 += __shfl_xor_sync(0xffffffffu, rs1, 2);
        m0 = mn0; m1 = mn1;
        l0 = l0 * sc0 + rs0;
        l1 = l1 * sc1 + rs1;
#pragma unroll
        for (int f = 0; f < 16; f++) {
            o[f][0] *= sc0; o[f][1] *= sc0;
            o[f][2] *= sc1; o[f][3] *= sc1;
        }

        // ---- pack P to fp16 A-frags (1-term PV) ----
        uint32_t ph[4][4];
#pragma unroll
        for (int kb = 0; kb < 4; kb++) {
            __half2 t;
            t = __floats2half2_rn(s[2 * kb][0],     s[2 * kb][1]);     ph[kb][0] = *(uint32_t*)&t;
            t = __floats2half2_rn(s[2 * kb][2],     s[2 * kb][3]);     ph[kb][1] = *(uint32_t*)&t;
            t = __floats2half2_rn(s[2 * kb + 1][0], s[2 * kb + 1][1]); ph[kb][2] = *(uint32_t*)&t;
            t = __floats2half2_rn(s[2 * kb + 1][2], s[2 * kb + 1][3]); ph[kb][3] = *(uint32_t*)&t;
        }

        // ---- PV: 1-term, row-major V via ldmatrix.trans ----
#pragma unroll
        for (int kb = 0; kb < 4; kb++) {
#pragma unroll
            for (int dp = 0; dp < 8; dp++) {
                uint32_t v0, v1, v2, v3;
                ldsm4t(st + VH_SOFF + bV + kb * (16 * QROW) + dp * 32, v0, v1, v2, v3);
                mma16816(o[dp * 2],     ph[kb], v0, v1);
                mma16816(o[dp * 2 + 1], ph[kb], v2, v3);
            }
        }
    }

    // ---- epilogue: O/l, single fp16 for 1-term O-projection ----
    const float i0 = 1.f / l0, i1 = 1.f / l1;
    const int gr0 = qt * 128 + wid * 16 + (lane >> 2);
#pragma unroll
    for (int f = 0; f < 16; f++) {
        const int d0 = f * 8 + (lane & 3) * 2;
        const size_t ix0 = ((size_t)(b * S + gr0) * NH + h) * D + d0;
        const size_t ix1 = ((size_t)(b * S + gr0 + 8) * NH + h) * D + d0;
        __half2 h0 = __floats2half2_rn(o[f][0] * i0, o[f][1] * i0);
        __half2 h1 = __floats2half2_rn(o[f][2] * i1, o[f][3] * i1);
        *(__half2*)(g_aoh + ix0) = h0;
        *(__half2*)(g_aoh + ix1) = h1;
    }
}

// ============================================================================
// host launcher
// ============================================================================
extern "C" void kernel_launch(void* const* d_in, const int* in_sizes, int n_in,
                              void* d_out, int out_size)
{
    const float* hidden = (const float*)d_in[0];
    const float* cosb   = (const float*)d_in[1];
    const float* sinb   = (const float*)d_in[2];
    const float* Wq     = (const float*)d_in[3];
    const float* Wk     = (const float*)d_in[4];
    const float* Wv     = (const float*)d_in[5];
    const float* Wo     = (const float*)d_in[6];
    const float* qw     = (const float*)d_in[7];
    const float* kw     = (const float*)d_in[8];
    float* out = (float*)d_out;

    __half *xh, *wh, *woh, *aoh;
    cudaGetSymbolAddress((void**)&xh,  g_xh);
    cudaGetSymbolAddress((void**)&wh,  g_wh);
    cudaGetSymbolAddress((void**)&woh, g_woh);
    cudaGetSymbolAddress((void**)&aoh, g_aoh);

    cudaFuncSetAttribute(gemm_mma<true>,  cudaFuncAttributeMaxDynamicSharedMemorySize, GSMEM_QKV);
    cudaFuncSetAttribute(gemm_mma<false>, cudaFuncAttributeMaxDynamicSharedMemorySize, GSMEM_O);
    cudaFuncSetAttribute(flash_mma, cudaFuncAttributeMaxDynamicSharedMemorySize, FSMEM);

    // conversions (2 launches)
    {
        int n4 = MSEQ * H / 4;
        cvt_fp32<<<(n4 + 255) / 256, 256>>>(hidden, xh, n4);
        cvt_weights<<<(N4ALL + 255) / 256, 256>>>(Wq, Wk, Wv, Wo);
    }

    // fused QKV projection + RMSNorm + RoPE -> g_qh / g_kh / g_vrow directly
    gemm_mma<true><<<dim3(NQKV / 128, MSEQ / 128), 256, GSMEM_QKV>>>(
        xh, wh, nullptr, MSEQ, NQKV, H, cosb, sinb, qw, kw);

    // causal flash attention on tensor cores
    flash_mma<<<dim3(S / 128, B * NH), 256, FSMEM>>>();

    // output projection (fp32 out): [2048, 4096] = AO * Wo^T
    gemm_mma<false><<<dim3(H / 128, MSEQ / 128), 256, GSMEM_O>>>(
        aoh, woh, out, MSEQ, H, NH * D, nullptr, nullptr, nullptr, nullptr);
}

// round 14
// speedup vs baseline: 7.4569x; 1.0021x over previous
#include <cuda_runtime.h>
#include <cuda_fp16.h>
#include <math.h>
#include <stdint.h>

// ---------------- problem constants ----------------
#define B   2
#define S   1024
#define H   4096
#define NH  32
#define NKV 8
#define D   128
#define GROUPS (NH / NKV)   // 4
#define EPS 1e-6f
#define QSCALE 0.08838834764831845f   // 1/sqrt(128)
#define MSEQ (B * S)        // 2048 rows
#define NQKV ((NH + 2 * NKV) * D)   // 6144
#define LOG2E 1.4426950408889634f
#define PBIAS  12.0f                 // P scaled by 2^12 (cancels in O/l)

// ---------------- scratch (device globals, fp16) ----------------
__device__ __align__(16) __half g_xh [MSEQ * H];       // hidden fp16
__device__ __align__(16) __half g_wh [NQKV * H];       // stacked Wq|Wk|Wv
__device__ __align__(16) __half g_woh[H * NH * D];     // Wo
__device__ __align__(16) __half g_aoh[MSEQ * NH * D];  // attn out fp16
// flash inputs: q (pre-scaled by QSCALE), k row-major, v row-major
__device__ __align__(16) __half g_qh [B * NH  * S * D];
__device__ __align__(16) __half g_kh [B * NKV * S * D];
__device__ __align__(16) __half g_vrow[B * NKV * S * D];   // [B,NKV,S,D]

// ---------------- small helpers ----------------
__device__ __forceinline__ void cp16(uint32_t dst, const void* src) {
    asm volatile("cp.async.cg.shared.global [%0], [%1], 16;" :: "r"(dst), "l"(src) : "memory");
}
__device__ __forceinline__ void ldsm4(uint32_t addr, uint32_t& r0, uint32_t& r1,
                                      uint32_t& r2, uint32_t& r3) {
    asm volatile("ldmatrix.sync.aligned.m8n8.x4.shared.b16 {%0,%1,%2,%3}, [%4];"
        : "=r"(r0), "=r"(r1), "=r"(r2), "=r"(r3) : "r"(addr));
}
__device__ __forceinline__ void ldsm4t(uint32_t addr, uint32_t& r0, uint32_t& r1,
                                       uint32_t& r2, uint32_t& r3) {
    asm volatile("ldmatrix.sync.aligned.m8n8.x4.trans.shared.b16 {%0,%1,%2,%3}, [%4];"
        : "=r"(r0), "=r"(r1), "=r"(r2), "=r"(r3) : "r"(addr));
}
__device__ __forceinline__ void mma16816(float* c, const uint32_t* a,
                                         uint32_t b0, uint32_t b1) {
    asm volatile("mma.sync.aligned.m16n8k16.row.col.f32.f16.f16.f32 "
        "{%0,%1,%2,%3}, {%4,%5,%6,%7}, {%8,%9}, {%0,%1,%2,%3};"
        : "+f"(c[0]), "+f"(c[1]), "+f"(c[2]), "+f"(c[3])
        : "r"(a[0]), "r"(a[1]), "r"(a[2]), "r"(a[3]), "r"(b0), "r"(b1));
}

// ============================================================================
// all conversions in ONE launch: hidden -> g_xh, Wq|Wk|Wv -> g_wh, Wo -> g_woh
// ============================================================================
#define N4X (MSEQ * H / 4)             // 2097152
#define N4Q (NH * D * H / 4)           // 4194304
#define N4K (NKV * D * H / 4)          // 1048576
#define N4ALL (N4X + N4Q + 2 * N4K + N4Q)

__global__ void __launch_bounds__(256) cvt_all(
    const float* __restrict__ hidden,
    const float* __restrict__ Wq, const float* __restrict__ Wk,
    const float* __restrict__ Wv, const float* __restrict__ Wo)
{
    int i = blockIdx.x * 256 + threadIdx.x;
    if (i >= N4ALL) return;
    const float* src;
    __half* dst;
    int j = i;
    if (j < N4X)                { src = hidden; dst = g_xh; }
    else if ((j -= N4X) < N4Q)  { src = Wq; dst = g_wh; }
    else if ((j -= N4Q) < N4K)  { src = Wk; dst = g_wh + (size_t)NH * D * H; }
    else if ((j -= N4K) < N4K)  { src = Wv; dst = g_wh + (size_t)(NH + NKV) * D * H; }
    else { j -= N4K;              src = Wo; dst = g_woh; }
    float4 x = ((const float4*)src)[j];
    ((__half2*)dst)[2 * j]     = __floats2half2_rn(x.x, x.y);
    ((__half2*)dst)[2 * j + 1] = __floats2half2_rn(x.z, x.w);
}

// ============================================================================
// mma.sync fp16 NT GEMM (1 term): C[M,N] = A[M,K]*B[N,K]^T.
// Block tile 128x128x32, 8 warps (4m x 2n), warp tile 32x64.
// 3-stage cp.async ring, ONE __syncthreads per K-tile, 2 CTAs/SM.
// FUSED=true (QKV): one N-tile == one head; epilogue does RMSNorm+RoPE.
// ============================================================================
#define ROWB 80                        // bytes per 32-fp16 row (padded)
#define MATB (128 * ROWB)              // 10240 per matrix tile
#define STGB (2 * MATB)                // A|B per stage = 20480
#define GSMEM_PIPE (3 * STGB)          // 61440
#define EPI_PITCH 132                  // fp32 stage row pitch
#define GSMEM_EPI  (128 * EPI_PITCH * 4 + 128 * 2 * 4)   // 68608
#define GSMEM_QKV  GSMEM_EPI
#define GSMEM_O    GSMEM_PIPE

template<bool FUSED>
__global__ void __launch_bounds__(256, 2) gemm_mma(
    const __half* __restrict__ A, const __half* __restrict__ Bm,
    float* __restrict__ C, int M, int N, int K,
    const float* __restrict__ cosb, const float* __restrict__ sinb,
    const float* __restrict__ qw,   const float* __restrict__ kw)
{
    extern __shared__ __align__(128) char smem[];
    const uint32_t sbase = (uint32_t)__cvta_generic_to_shared(smem);
    const int tid  = threadIdx.x;
    const int lane = tid & 31;
    const int wid  = tid >> 5;
    const int warp_m = wid >> 1;   // 0..3 (32 rows each)
    const int warp_n = wid & 1;    // 0..1 (64 cols each)
    const int m0 = blockIdx.y * 128;
    const int n0 = blockIdx.x * 128;
    const int KT = K >> 5;         // K / 32

    float acc[2][8][4];
#pragma unroll
    for (int i = 0; i < 2; i++)
#pragma unroll
        for (int j = 0; j < 8; j++)
#pragma unroll
            for (int q = 0; q < 4; q++) acc[i][j][q] = 0.f;

    auto fill = [&](int s, int kt) {
        const uint32_t st = sbase + s * STGB;
#pragma unroll
        for (int i = 0; i < 4; i++) {
            const int v = ((i & 1) << 8) + tid;      // 0..511 within matrix
            const int r = v >> 2, c = v & 3;
            const __half* gb = (i < 2) ? A : Bm;
            const int grow = ((i < 2) ? m0 : n0) + r;
            cp16(st + (i >> 1) * MATB + r * ROWB + c * 16,
                 gb + (size_t)grow * K + (size_t)kt * 32 + c * 8);
        }
        asm volatile("cp.async.commit_group;" ::: "memory");
    };

    fill(0, 0); fill(1, 1); fill(2, 2);

    const uint32_t aOff = (uint32_t)((warp_m * 32 + (lane & 15)) * ROWB + ((lane >> 4) << 4));
    const uint32_t bOff = (uint32_t)(MATB + (warp_n * 64 + (lane & 15)) * ROWB + ((lane >> 4) << 4));

    for (int kt = 0; kt < KT; kt++) {
        asm volatile("cp.async.wait_group 1;" ::: "memory");
        __syncthreads();     // all warps done with iter kt-1 -> slot (kt-1)%3 free
        if (kt >= 1) {
            const int t = kt + 2;
            if (t < KT) fill(t % 3, t);
            else asm volatile("cp.async.commit_group;" ::: "memory");  // keep group count
        }

        const uint32_t st = sbase + (kt % 3) * STGB;
#pragma unroll
        for (int k16 = 0; k16 < 2; k16++) {
            const uint32_t ko = k16 * 32;
            uint32_t a[2][4], bh[4][4];
#pragma unroll
            for (int mi = 0; mi < 2; mi++)
                ldsm4(st + aOff + mi * (16 * ROWB) + ko,
                      a[mi][0], a[mi][1], a[mi][2], a[mi][3]);
#pragma unroll
            for (int ni = 0; ni < 4; ni++)
                ldsm4(st + bOff + ni * (16 * ROWB) + ko,
                      bh[ni][0], bh[ni][1], bh[ni][2], bh[ni][3]);
#pragma unroll
            for (int mi = 0; mi < 2; mi++)
#pragma unroll
                for (int ni = 0; ni < 4; ni++) {
                    mma16816(acc[mi][ni * 2],     a[mi], bh[ni][0], bh[ni][2]);
                    mma16816(acc[mi][ni * 2 + 1], a[mi], bh[ni][1], bh[ni][3]);
                }
        }
    }

    if (!FUSED) {
#pragma unroll
        for (int mi = 0; mi < 2; mi++) {
            const int row = m0 + warp_m * 32 + mi * 16 + (lane >> 2);
#pragma unroll
            for (int nj = 0; nj < 8; nj++) {
                const int col = n0 + warp_n * 64 + nj * 8 + (lane & 3) * 2;
                *(float2*)(C + (size_t)row * N + col) =
                    make_float2(acc[mi][nj][0], acc[mi][nj][1]);
                *(float2*)(C + (size_t)(row + 8) * N + col) =
                    make_float2(acc[mi][nj][2], acc[mi][nj][3]);
            }
        }
        return;
    }

    // ---- fused QKV epilogue: this N-tile is one head (hs = n0/128) ----
    asm volatile("cp.async.wait_group 0;" ::: "memory");
    __syncthreads();   // pipeline smem now free for staging

    const int hs = n0 >> 7;
    const int rbase = warp_m * 32 + (lane >> 2);

    if (hs >= NH + NKV) {
        const int vh = hs - NH - NKV;
#pragma unroll
        for (int mi = 0; mi < 2; mi++) {
            const int rl = rbase + mi * 16;
#pragma unroll
            for (int nj = 0; nj < 8; nj++) {
                const int d = warp_n * 64 + nj * 8 + (lane & 3) * 2;
                const int bs0 = m0 + rl, bs1 = bs0 + 8;
                const size_t i0 = (((size_t)(bs0 >> 10) * NKV + vh) * S + (bs0 & 1023)) * D + d;
                const size_t i1 = (((size_t)(bs1 >> 10) * NKV + vh) * S + (bs1 & 1023)) * D + d;
                *(__half2*)(g_vrow + i0) = __floats2half2_rn(acc[mi][nj][0], acc[mi][nj][1]);
                *(__half2*)(g_vrow + i1) = __floats2half2_rn(acc[mi][nj][2], acc[mi][nj][3]);
            }
        }
        return;
    }

    const bool isQ = (hs < NH);
    float* sst  = (float*)smem;                 // [128][EPI_PITCH]
    float* ssum = sst + 128 * EPI_PITCH;        // [128][2]

#pragma unroll
    for (int mi = 0; mi < 2; mi++) {
        float s0 = 0.f, s1 = 0.f;
#pragma unroll
        for (int nj = 0; nj < 8; nj++) {
            s0 += acc[mi][nj][0] * acc[mi][nj][0] + acc[mi][nj][1] * acc[mi][nj][1];
            s1 += acc[mi][nj][2] * acc[mi][nj][2] + acc[mi][nj][3] * acc[mi][nj][3];
        }
        s0 += __shfl_xor_sync(0xffffffffu, s0, 1);
        s0 += __shfl_xor_sync(0xffffffffu, s0, 2);
        s1 += __shfl_xor_sync(0xffffffffu, s1, 1);
        s1 += __shfl_xor_sync(0xffffffffu, s1, 2);
        if ((lane & 3) == 0) {
            ssum[(rbase + mi * 16) * 2 + warp_n]     = s0;
            ssum[(rbase + mi * 16 + 8) * 2 + warp_n] = s1;
        }
    }
    __syncthreads();

    const float* wp = isQ ? qw : kw;
#pragma unroll
    for (int mi = 0; mi < 2; mi++) {
        const int r0 = rbase + mi * 16, r1 = r0 + 8;
        const float inv0 = rsqrtf((ssum[r0 * 2] + ssum[r0 * 2 + 1]) * (1.0f / D) + EPS);
        const float inv1 = rsqrtf((ssum[r1 * 2] + ssum[r1 * 2 + 1]) * (1.0f / D) + EPS);
#pragma unroll
        for (int nj = 0; nj < 8; nj++) {
            const int d = warp_n * 64 + nj * 8 + (lane & 3) * 2;
            const float2 w2 = *(const float2*)(wp + d);
            sst[r0 * EPI_PITCH + d]     = acc[mi][nj][0] * inv0 * w2.x;
            sst[r0 * EPI_PITCH + d + 1] = acc[mi][nj][1] * inv0 * w2.y;
            sst[r1 * EPI_PITCH + d]     = acc[mi][nj][2] * inv1 * w2.x;
            sst[r1 * EPI_PITCH + d + 1] = acc[mi][nj][3] * inv1 * w2.y;
        }
    }
    __syncthreads();

    const float oscale = isQ ? QSCALE : 1.0f;
#pragma unroll
    for (int mi = 0; mi < 2; mi++) {
        const int rl0 = rbase + mi * 16;
#pragma unroll
        for (int half = 0; half < 2; half++) {
            const int rl = rl0 + half * 8;
            const int bs = m0 + rl;
            const int b  = bs >> 10, s = bs & 1023;
#pragma unroll
            for (int nj = 0; nj < 8; nj++) {
                const int d = warp_n * 64 + nj * 8 + (lane & 3) * 2;
                const float2 c2 = *(const float2*)(cosb + (size_t)bs * D + d);
                const float2 s2 = *(const float2*)(sinb + (size_t)bs * D + d);
                const float v0 = sst[rl * EPI_PITCH + d];
                const float v1 = sst[rl * EPI_PITCH + d + 1];
                const float p0 = sst[rl * EPI_PITCH + (d ^ 64)];
                const float p1 = sst[rl * EPI_PITCH + (d ^ 64) + 1];
                const float sgn = (d < 64) ? -1.f : 1.f;
                const float o0 = (v0 * c2.x + sgn * p0 * s2.x) * oscale;
                const float o1 = (v1 * c2.y + sgn * p1 * s2.y) * oscale;
                if (isQ) {
                    const size_t ix = (((size_t)b * NH + hs) * S + s) * D + d;
                    *(__half2*)(g_qh + ix) = __floats2half2_rn(o0, o1);
                } else {
                    const size_t ix = (((size_t)b * NKV + (hs - NH)) * S + s) * D + d;
                    *(__half2*)(g_kh + ix) = __floats2half2_rn(o0, o1);
                }
            }
        }
    }
}

// ============================================================================
// Causal flash attention: 1-term QK (scale pre-folded into q), 1-term PV.
// V row-major via ldmatrix.trans. BM=128, BN=64, 8 warps, 2-stage KV pipeline.
// 2 CTAs/SM (regs <= 128 via interleaved ldsm/mma).
// ============================================================================
#define QROW 272                       // 128 fp16 + 8 pad (17 x 16B, conflict-free)
#define SQH_OFF 0
#define SK0_OFF (128 * QROW)           // 34816
#define VH_SOFF (64 * QROW)            // V within stage (17408)
#define KSTG    (2 * 64 * QROW)        // 34816
#define FSMEM   (SK0_OFF + 2 * KSTG)   // 104448

__global__ void __launch_bounds__(256, 2) flash_mma()
{
    extern __shared__ __align__(128) char fsm[];
    const uint32_t sb = (uint32_t)__cvta_generic_to_shared(fsm);
    const int tid = threadIdx.x, lane = tid & 31, wid = tid >> 5;
    const int qt = (int)gridDim.x - 1 - (int)blockIdx.x;   // heavy CTAs first
    const int bh = blockIdx.y;
    const int b = bh / NH, h = bh - b * NH;
    const int kvh = h / GROUPS;

    const __half* Qhp = g_qh + (((size_t)b * NH + h) * S + (size_t)qt * 128) * D;
    const __half* Khp = g_kh + ((size_t)b * NKV + kvh) * S * D;
    const __half* Vhp = g_vrow + ((size_t)b * NKV + kvh) * S * D;

#pragma unroll
    for (int i = tid; i < 2048; i += 256) {
        const int r = i >> 4, c = i & 15;
        cp16(sb + SQH_OFF + r * QROW + c * 16, Qhp + r * D + c * 8);
    }

    auto fillkv = [&](int slot, int kt) {
        const uint32_t st = sb + SK0_OFF + slot * KSTG;
        const __half* kh_ = Khp + (size_t)kt * 64 * D;
        const __half* vh_ = Vhp + (size_t)kt * 64 * D;
#pragma unroll
        for (int i = tid; i < 1024; i += 256) {
            const int r = i >> 4, c = i & 15;
            cp16(st + r * QROW + c * 16,           kh_ + r * D + c * 8);
            cp16(st + VH_SOFF + r * QROW + c * 16, vh_ + r * D + c * 8);
        }
        asm volatile("cp.async.commit_group;" ::: "memory");
    };
    fillkv(0, 0);   // Q cp.asyncs ride this group

    float m0 = -INFINITY, m1 = -INFINITY, l0 = 0.f, l1 = 0.f;
    float o[16][4];
#pragma unroll
    for (int f = 0; f < 16; f++)
#pragma unroll
        for (int e = 0; e < 4; e++) o[f][e] = 0.f;

    const uint32_t aQ = (uint32_t)((wid * 16 + (lane & 15)) * QROW + ((lane >> 4) << 4));
    const uint32_t bK = (uint32_t)((lane & 15) * QROW + ((lane >> 4) << 4));

    const int ktmax = 2 * qt + 1;

    for (int kt = 0; kt <= ktmax; kt++) {
        asm volatile("cp.async.wait_group 0;" ::: "memory");
        __syncthreads();
        if (kt < ktmax) fillkv((kt + 1) & 1, kt + 1);
        const uint32_t st = sb + SK0_OFF + (kt & 1) * KSTG;

        // ---- scores: 1-term QK, ldsm/mma interleaved (low live regs) ----
        float s[8][4];
#pragma unroll
        for (int f = 0; f < 8; f++)
#pragma unroll
            for (int e = 0; e < 4; e++) s[f][e] = 0.f;

#pragma unroll
        for (int ks = 0; ks < 8; ks++) {
            const uint32_t ko = ks * 32;
            uint32_t qh4[4];
            ldsm4(sb + SQH_OFF + aQ + ko, qh4[0], qh4[1], qh4[2], qh4[3]);
#pragma unroll
            for (int nb = 0; nb < 4; nb++) {
                uint32_t k0, k1, k2, k3;
                ldsm4(st + bK + nb * (16 * QROW) + ko, k0, k1, k2, k3);
                mma16816(s[nb * 2],     qh4, k0, k2);
                mma16816(s[nb * 2 + 1], qh4, k1, k3);
            }
        }

        if (kt >= 2 * qt) {
            const int r0 = qt * 128 + wid * 16 + (lane >> 2);
            const int r1 = r0 + 8;
#pragma unroll
            for (int f = 0; f < 8; f++) {
                const int c0 = kt * 64 + f * 8 + (lane & 3) * 2;
                if (c0     > r0) s[f][0] = -INFINITY;
                if (c0 + 1 > r0) s[f][1] = -INFINITY;
                if (c0     > r1) s[f][2] = -INFINITY;
                if (c0 + 1 > r1) s[f][3] = -INFINITY;
            }
        }

        float a0 = -INFINITY, a1 = -INFINITY;
#pragma unroll
        for (int f = 0; f < 8; f++) {
            a0 = fmaxf(a0, fmaxf(s[f][0], s[f][1]));
            a1 = fmaxf(a1, fmaxf(s[f][2], s[f][3]));
        }
        a0 = fmaxf(a0, __shfl_xor_sync(0xffffffffu, a0, 1));
        a0 = fmaxf(a0, __shfl_xor_sync(0xffffffffu, a0, 2));
        a1 = fmaxf(a1, __shfl_xor_sync(0xffffffffu, a1, 1));
        a1 = fmaxf(a1, __shfl_xor_sync(0xffffffffu, a1, 2));
        const float mn0 = fmaxf(m0, a0), mn1 = fmaxf(m1, a1);
        const float sc0 = exp2f((m0 - mn0) * LOG2E);
        const float sc1 = exp2f((m1 - mn1) * LOG2E);
        float rs0 = 0.f, rs1 = 0.f;
#pragma unroll
        for (int f = 0; f < 8; f++) {
            s[f][0] = exp2f((s[f][0] - mn0) * LOG2E + PBIAS);
            s[f][1] = exp2f((s[f][1] - mn0) * LOG2E + PBIAS);
            s[f][2] = exp2f((s[f][2] - mn1) * LOG2E + PBIAS);
            s[f][3] = exp2f((s[f][3] - mn1) * LOG2E + PBIAS);
            rs0 += s[f][0] + s[f][1];
            rs1 += s[f][2] + s[f][3];
        }
        rs0 += __shfl_xor_sync(0xffffffffu, rs0, 1);
        rs0 += __shfl_xor_sync(0xffffffffu, rs0, 2);
        rs1 += __shfl_xor_sync(0xffffffffu, rs1, 1);
        rs1 += __shfl_xor_sync(0xffffffffu, rs1, 2);
        m0 = mn0; m1 = mn1;
        l0 = l0 * sc0 + rs0;
        l1 = l1 * sc1 + rs1;
#pragma unroll
        for (int f = 0; f < 16; f++) {
            o[f][0] *= sc0; o[f][1] *= sc0;
            o[f][2] *= sc1; o[f][3] *= sc1;
        }

        // ---- pack P to fp16 A-frags (reuses s registers as they die) ----
        uint32_t ph[4][4];
#pragma unroll
        for (int kb = 0; kb < 4; kb++) {
            __half2 t;
            t = __floats2half2_rn(s[2 * kb][0],     s[2 * kb][1]);     ph[kb][0] = *(uint32_t*)&t;
            t = __floats2half2_rn(s[2 * kb][2],     s[2 * kb][3]);     ph[kb][1] = *(uint32_t*)&t;
            t = __floats2half2_rn(s[2 * kb + 1][0], s[2 * kb + 1][1]); ph[kb][2] = *(uint32_t*)&t;
            t = __floats2half2_rn(s[2 * kb + 1][2], s[2 * kb + 1][3]); ph[kb][3] = *(uint32_t*)&t;
        }

        // ---- PV: 1-term, row-major V via ldmatrix.trans ----
#pragma unroll
        for (int kb = 0; kb < 4; kb++) {
#pragma unroll
            for (int dp = 0; dp < 8; dp++) {
                uint32_t v0, v1, v2, v3;
                ldsm4t(st + VH_SOFF + bK + kb * (16 * QROW) + dp * 32, v0, v1, v2, v3);
                mma16816(o[dp * 2],     ph[kb], v0, v1);
                mma16816(o[dp * 2 + 1], ph[kb], v2, v3);
            }
        }
    }

    // ---- epilogue: O/l, single fp16 for 1-term O-projection ----
    const float i0 = 1.f / l0, i1 = 1.f / l1;
    const int gr0 = qt * 128 + wid * 16 + (lane >> 2);
#pragma unroll
    for (int f = 0; f < 16; f++) {
        const int d0 = f * 8 + (lane & 3) * 2;
        const size_t ix0 = ((size_t)(b * S + gr0) * NH + h) * D + d0;
        const size_t ix1 = ((size_t)(b * S + gr0 + 8) * NH + h) * D + d0;
        __half2 h0 = __floats2half2_rn(o[f][0] * i0, o[f][1] * i0);
        __half2 h1 = __floats2half2_rn(o[f][2] * i1, o[f][3] * i1);
        *(__half2*)(g_aoh + ix0) = h0;
        *(__half2*)(g_aoh + ix1) = h1;
    }
}

// ============================================================================
// host launcher
// ============================================================================
extern "C" void kernel_launch(void* const* d_in, const int* in_sizes, int n_in,
                              void* d_out, int out_size)
{
    const float* hidden = (const float*)d_in[0];
    const float* cosb   = (const float*)d_in[1];
    const float* sinb   = (const float*)d_in[2];
    const float* Wq     = (const float*)d_in[3];
    const float* Wk     = (const float*)d_in[4];
    const float* Wv     = (const float*)d_in[5];
    const float* Wo     = (const float*)d_in[6];
    const float* qw     = (const float*)d_in[7];
    const float* kw     = (const float*)d_in[8];
    float* out = (float*)d_out;

    __half *xh, *wh, *woh, *aoh;
    cudaGetSymbolAddress((void**)&xh,  g_xh);
    cudaGetSymbolAddress((void**)&wh,  g_wh);
    cudaGetSymbolAddress((void**)&woh, g_woh);
    cudaGetSymbolAddress((void**)&aoh, g_aoh);

    cudaFuncSetAttribute(gemm_mma<true>,  cudaFuncAttributeMaxDynamicSharedMemorySize, GSMEM_QKV);
    cudaFuncSetAttribute(gemm_mma<false>, cudaFuncAttributeMaxDynamicSharedMemorySize, GSMEM_O);
    cudaFuncSetAttribute(flash_mma, cudaFuncAttributeMaxDynamicSharedMemorySize, FSMEM);

    // all conversions in one launch
    cvt_all<<<(N4ALL + 255) / 256, 256>>>(hidden, Wq, Wk, Wv, Wo);

    // fused QKV projection + RMSNorm + RoPE -> g_qh / g_kh / g_vrow directly
    gemm_mma<true><<<dim3(NQKV / 128, MSEQ / 128), 256, GSMEM_QKV>>>(
        xh, wh, nullptr, MSEQ, NQKV, H, cosb, sinb, qw, kw);

    // causal flash attention on tensor cores (2 CTAs/SM)
    flash_mma<<<dim3(S / 128, B * NH), 256, FSMEM>>>();

    // output projection (fp32 out): [2048, 4096] = AO * Wo^T
    gemm_mma<false><<<dim3(H / 128, MSEQ / 128), 256, GSMEM_O>>>(
        aoh, woh, out, MSEQ, H, NH * D, nullptr, nullptr, nullptr, nullptr);
}

// round 15
// speedup vs baseline: 7.5474x; 1.0121x over previous
#include <cuda_runtime.h>
#include <cuda_fp16.h>
#include <math.h>
#include <stdint.h>

// ---------------- problem constants ----------------
#define B   2
#define S   1024
#define H   4096
#define NH  32
#define NKV 8
#define D   128
#define GROUPS (NH / NKV)   // 4
#define EPS 1e-6f
#define QSCALE 0.08838834764831845f   // 1/sqrt(128)
#define MSEQ (B * S)        // 2048 rows
#define NQKV ((NH + 2 * NKV) * D)   // 6144
#define LOG2E 1.4426950408889634f
#define PBIAS  12.0f                 // P scaled by 2^12 (cancels in O/l)

// ---------------- scratch (device globals, fp16) ----------------
__device__ __align__(16) __half g_xh [MSEQ * H];       // hidden fp16
__device__ __align__(16) __half g_wh [NQKV * H];       // stacked Wq|Wk|Wv
__device__ __align__(16) __half g_woh[H * NH * D];     // Wo
__device__ __align__(16) __half g_aoh[MSEQ * NH * D];  // attn out fp16
// flash inputs: q (pre-scaled by QSCALE), k row-major, v row-major
__device__ __align__(16) __half g_qh [B * NH  * S * D];
__device__ __align__(16) __half g_kh [B * NKV * S * D];
__device__ __align__(16) __half g_vrow[B * NKV * S * D];   // [B,NKV,S,D]

// ---------------- small helpers ----------------
__device__ __forceinline__ void cp16(uint32_t dst, const void* src) {
    asm volatile("cp.async.cg.shared.global [%0], [%1], 16;" :: "r"(dst), "l"(src) : "memory");
}
__device__ __forceinline__ void ldsm4(uint32_t addr, uint32_t& r0, uint32_t& r1,
                                      uint32_t& r2, uint32_t& r3) {
    asm volatile("ldmatrix.sync.aligned.m8n8.x4.shared.b16 {%0,%1,%2,%3}, [%4];"
        : "=r"(r0), "=r"(r1), "=r"(r2), "=r"(r3) : "r"(addr));
}
__device__ __forceinline__ void ldsm4t(uint32_t addr, uint32_t& r0, uint32_t& r1,
                                       uint32_t& r2, uint32_t& r3) {
    asm volatile("ldmatrix.sync.aligned.m8n8.x4.trans.shared.b16 {%0,%1,%2,%3}, [%4];"
        : "=r"(r0), "=r"(r1), "=r"(r2), "=r"(r3) : "r"(addr));
}
__device__ __forceinline__ void mma16816(float* c, const uint32_t* a,
                                         uint32_t b0, uint32_t b1) {
    asm volatile("mma.sync.aligned.m16n8k16.row.col.f32.f16.f16.f32 "
        "{%0,%1,%2,%3}, {%4,%5,%6,%7}, {%8,%9}, {%0,%1,%2,%3};"
        : "+f"(c[0]), "+f"(c[1]), "+f"(c[2]), "+f"(c[3])
        : "r"(a[0]), "r"(a[1]), "r"(a[2]), "r"(a[3]), "r"(b0), "r"(b1));
}

// ============================================================================
// all conversions in ONE launch
// ============================================================================
#define N4X (MSEQ * H / 4)
#define N4Q (NH * D * H / 4)
#define N4K (NKV * D * H / 4)
#define N4ALL (N4X + N4Q + 2 * N4K + N4Q)

__global__ void __launch_bounds__(256) cvt_all(
    const float* __restrict__ hidden,
    const float* __restrict__ Wq, const float* __restrict__ Wk,
    const float* __restrict__ Wv, const float* __restrict__ Wo)
{
    int i = blockIdx.x * 256 + threadIdx.x;
    if (i >= N4ALL) return;
    const float* src;
    __half* dst;
    int j = i;
    if (j < N4X)                { src = hidden; dst = g_xh; }
    else if ((j -= N4X) < N4Q)  { src = Wq; dst = g_wh; }
    else if ((j -= N4Q) < N4K)  { src = Wk; dst = g_wh + (size_t)NH * D * H; }
    else if ((j -= N4K) < N4K)  { src = Wv; dst = g_wh + (size_t)(NH + NKV) * D * H; }
    else { j -= N4K;              src = Wo; dst = g_woh; }
    float4 x = ((const float4*)src)[j];
    ((__half2*)dst)[2 * j]     = __floats2half2_rn(x.x, x.y);
    ((__half2*)dst)[2 * j + 1] = __floats2half2_rn(x.z, x.w);
}

// ============================================================================
// mma.sync fp16 NT GEMM (1 term): C[M,N] = A[M,K]*B[N,K]^T.
// Block tile 128x128x32, 8 warps (4m x 2n), warp tile 32x64.
// 3-stage cp.async ring, ONE __syncthreads per K-tile, 2 CTAs/SM.
// FUSED=true (QKV): one N-tile == one head; epilogue does RMSNorm+RoPE.
// ============================================================================
#define ROWB 80
#define MATB (128 * ROWB)
#define STGB (2 * MATB)
#define GSMEM_PIPE (3 * STGB)          // 61440
#define EPI_PITCH 132
#define GSMEM_EPI  (128 * EPI_PITCH * 4 + 128 * 2 * 4)   // 68608
#define GSMEM_QKV  GSMEM_EPI
#define GSMEM_O    GSMEM_PIPE

template<bool FUSED>
__global__ void __launch_bounds__(256, 2) gemm_mma(
    const __half* __restrict__ A, const __half* __restrict__ Bm,
    float* __restrict__ C, int M, int N, int K,
    const float* __restrict__ cosb, const float* __restrict__ sinb,
    const float* __restrict__ qw,   const float* __restrict__ kw)
{
    extern __shared__ __align__(128) char smem[];
    const uint32_t sbase = (uint32_t)__cvta_generic_to_shared(smem);
    const int tid  = threadIdx.x;
    const int lane = tid & 31;
    const int wid  = tid >> 5;
    const int warp_m = wid >> 1;
    const int warp_n = wid & 1;
    const int m0 = blockIdx.y * 128;
    const int n0 = blockIdx.x * 128;
    const int KT = K >> 5;

    float acc[2][8][4];
#pragma unroll
    for (int i = 0; i < 2; i++)
#pragma unroll
        for (int j = 0; j < 8; j++)
#pragma unroll
            for (int q = 0; q < 4; q++) acc[i][j][q] = 0.f;

    auto fill = [&](int s, int kt) {
        const uint32_t st = sbase + s * STGB;
#pragma unroll
        for (int i = 0; i < 4; i++) {
            const int v = ((i & 1) << 8) + tid;
            const int r = v >> 2, c = v & 3;
            const __half* gb = (i < 2) ? A : Bm;
            const int grow = ((i < 2) ? m0 : n0) + r;
            cp16(st + (i >> 1) * MATB + r * ROWB + c * 16,
                 gb + (size_t)grow * K + (size_t)kt * 32 + c * 8);
        }
        asm volatile("cp.async.commit_group;" ::: "memory");
    };

    fill(0, 0); fill(1, 1); fill(2, 2);

    const uint32_t aOff = (uint32_t)((warp_m * 32 + (lane & 15)) * ROWB + ((lane >> 4) << 4));
    const uint32_t bOff = (uint32_t)(MATB + (warp_n * 64 + (lane & 15)) * ROWB + ((lane >> 4) << 4));

    for (int kt = 0; kt < KT; kt++) {
        asm volatile("cp.async.wait_group 1;" ::: "memory");
        __syncthreads();
        if (kt >= 1) {
            const int t = kt + 2;
            if (t < KT) fill(t % 3, t);
            else asm volatile("cp.async.commit_group;" ::: "memory");
        }

        const uint32_t st = sbase + (kt % 3) * STGB;
#pragma unroll
        for (int k16 = 0; k16 < 2; k16++) {
            const uint32_t ko = k16 * 32;
            uint32_t a[2][4], bh[4][4];
#pragma unroll
            for (int mi = 0; mi < 2; mi++)
                ldsm4(st + aOff + mi * (16 * ROWB) + ko,
                      a[mi][0], a[mi][1], a[mi][2], a[mi][3]);
#pragma unroll
            for (int ni = 0; ni < 4; ni++)
                ldsm4(st + bOff + ni * (16 * ROWB) + ko,
                      bh[ni][0], bh[ni][1], bh[ni][2], bh[ni][3]);
#pragma unroll
            for (int mi = 0; mi < 2; mi++)
#pragma unroll
                for (int ni = 0; ni < 4; ni++) {
                    mma16816(acc[mi][ni * 2],     a[mi], bh[ni][0], bh[ni][2]);
                    mma16816(acc[mi][ni * 2 + 1], a[mi], bh[ni][1], bh[ni][3]);
                }
        }
    }

    if (!FUSED) {
#pragma unroll
        for (int mi = 0; mi < 2; mi++) {
            const int row = m0 + warp_m * 32 + mi * 16 + (lane >> 2);
#pragma unroll
            for (int nj = 0; nj < 8; nj++) {
                const int col = n0 + warp_n * 64 + nj * 8 + (lane & 3) * 2;
                *(float2*)(C + (size_t)row * N + col) =
                    make_float2(acc[mi][nj][0], acc[mi][nj][1]);
                *(float2*)(C + (size_t)(row + 8) * N + col) =
                    make_float2(acc[mi][nj][2], acc[mi][nj][3]);
            }
        }
        return;
    }

    // ---- fused QKV epilogue ----
    asm volatile("cp.async.wait_group 0;" ::: "memory");
    __syncthreads();

    const int hs = n0 >> 7;
    const int rbase = warp_m * 32 + (lane >> 2);

    if (hs >= NH + NKV) {
        const int vh = hs - NH - NKV;
#pragma unroll
        for (int mi = 0; mi < 2; mi++) {
            const int rl = rbase + mi * 16;
#pragma unroll
            for (int nj = 0; nj < 8; nj++) {
                const int d = warp_n * 64 + nj * 8 + (lane & 3) * 2;
                const int bs0 = m0 + rl, bs1 = bs0 + 8;
                const size_t i0 = (((size_t)(bs0 >> 10) * NKV + vh) * S + (bs0 & 1023)) * D + d;
                const size_t i1 = (((size_t)(bs1 >> 10) * NKV + vh) * S + (bs1 & 1023)) * D + d;
                *(__half2*)(g_vrow + i0) = __floats2half2_rn(acc[mi][nj][0], acc[mi][nj][1]);
                *(__half2*)(g_vrow + i1) = __floats2half2_rn(acc[mi][nj][2], acc[mi][nj][3]);
            }
        }
        return;
    }

    const bool isQ = (hs < NH);
    float* sst  = (float*)smem;
    float* ssum = sst + 128 * EPI_PITCH;

#pragma unroll
    for (int mi = 0; mi < 2; mi++) {
        float s0 = 0.f, s1 = 0.f;
#pragma unroll
        for (int nj = 0; nj < 8; nj++) {
            s0 += acc[mi][nj][0] * acc[mi][nj][0] + acc[mi][nj][1] * acc[mi][nj][1];
            s1 += acc[mi][nj][2] * acc[mi][nj][2] + acc[mi][nj][3] * acc[mi][nj][3];
        }
        s0 += __shfl_xor_sync(0xffffffffu, s0, 1);
        s0 += __shfl_xor_sync(0xffffffffu, s0, 2);
        s1 += __shfl_xor_sync(0xffffffffu, s1, 1);
        s1 += __shfl_xor_sync(0xffffffffu, s1, 2);
        if ((lane & 3) == 0) {
            ssum[(rbase + mi * 16) * 2 + warp_n]     = s0;
            ssum[(rbase + mi * 16 + 8) * 2 + warp_n] = s1;
        }
    }
    __syncthreads();

    const float* wp = isQ ? qw : kw;
#pragma unroll
    for (int mi = 0; mi < 2; mi++) {
        const int r0 = rbase + mi * 16, r1 = r0 + 8;
        const float inv0 = rsqrtf((ssum[r0 * 2] + ssum[r0 * 2 + 1]) * (1.0f / D) + EPS);
        const float inv1 = rsqrtf((ssum[r1 * 2] + ssum[r1 * 2 + 1]) * (1.0f / D) + EPS);
#pragma unroll
        for (int nj = 0; nj < 8; nj++) {
            const int d = warp_n * 64 + nj * 8 + (lane & 3) * 2;
            const float2 w2 = *(const float2*)(wp + d);
            sst[r0 * EPI_PITCH + d]     = acc[mi][nj][0] * inv0 * w2.x;
            sst[r0 * EPI_PITCH + d + 1] = acc[mi][nj][1] * inv0 * w2.y;
            sst[r1 * EPI_PITCH + d]     = acc[mi][nj][2] * inv1 * w2.x;
            sst[r1 * EPI_PITCH + d + 1] = acc[mi][nj][3] * inv1 * w2.y;
        }
    }
    __syncthreads();

    const float oscale = isQ ? QSCALE : 1.0f;
#pragma unroll
    for (int mi = 0; mi < 2; mi++) {
        const int rl0 = rbase + mi * 16;
#pragma unroll
        for (int half = 0; half < 2; half++) {
            const int rl = rl0 + half * 8;
            const int bs = m0 + rl;
            const int b  = bs >> 10, s = bs & 1023;
#pragma unroll
            for (int nj = 0; nj < 8; nj++) {
                const int d = warp_n * 64 + nj * 8 + (lane & 3) * 2;
                const float2 c2 = *(const float2*)(cosb + (size_t)bs * D + d);
                const float2 s2 = *(const float2*)(sinb + (size_t)bs * D + d);
                const float v0 = sst[rl * EPI_PITCH + d];
                const float v1 = sst[rl * EPI_PITCH + d + 1];
                const float p0 = sst[rl * EPI_PITCH + (d ^ 64)];
                const float p1 = sst[rl * EPI_PITCH + (d ^ 64) + 1];
                const float sgn = (d < 64) ? -1.f : 1.f;
                const float o0 = (v0 * c2.x + sgn * p0 * s2.x) * oscale;
                const float o1 = (v1 * c2.y + sgn * p1 * s2.y) * oscale;
                if (isQ) {
                    const size_t ix = (((size_t)b * NH + hs) * S + s) * D + d;
                    *(__half2*)(g_qh + ix) = __floats2half2_rn(o0, o1);
                } else {
                    const size_t ix = (((size_t)b * NKV + (hs - NH)) * S + s) * D + d;
                    *(__half2*)(g_kh + ix) = __floats2half2_rn(o0, o1);
                }
            }
        }
    }
}

// ============================================================================
// Causal flash attention: BM=128, BN=128 (one softmax round per 128 K-cols).
// 1-term QK (scale pre-folded into q), 1-term PV, V via ldmatrix.trans.
// 8 warps, 2-stage KV pipeline, 1 CTA/SM (regs spent on ILP).
// ============================================================================
#define QROW 272                       // 128 fp16 + 8 pad
#define SQH_OFF 0
#define SK0_OFF (128 * QROW)           // 34816
#define VH_SOFF (128 * QROW)           // V within stage (34816)
#define KSTG    (2 * 128 * QROW)       // 69632
#define FSMEM   (SK0_OFF + 2 * KSTG)   // 174080

__global__ void __launch_bounds__(256) flash_mma()
{
    extern __shared__ __align__(128) char fsm[];
    const uint32_t sb = (uint32_t)__cvta_generic_to_shared(fsm);
    const int tid = threadIdx.x, lane = tid & 31, wid = tid >> 5;
    const int qt = (int)gridDim.x - 1 - (int)blockIdx.x;   // heavy CTAs first
    const int bh = blockIdx.y;
    const int b = bh / NH, h = bh - b * NH;
    const int kvh = h / GROUPS;

    const __half* Qhp = g_qh + (((size_t)b * NH + h) * S + (size_t)qt * 128) * D;
    const __half* Khp = g_kh + ((size_t)b * NKV + kvh) * S * D;
    const __half* Vhp = g_vrow + ((size_t)b * NKV + kvh) * S * D;

#pragma unroll
    for (int i = tid; i < 2048; i += 256) {
        const int r = i >> 4, c = i & 15;
        cp16(sb + SQH_OFF + r * QROW + c * 16, Qhp + r * D + c * 8);
    }

    auto fillkv = [&](int slot, int kt) {
        const uint32_t st = sb + SK0_OFF + slot * KSTG;
        const __half* kh_ = Khp + (size_t)kt * 128 * D;
        const __half* vh_ = Vhp + (size_t)kt * 128 * D;
#pragma unroll
        for (int i = tid; i < 2048; i += 256) {
            const int r = i >> 4, c = i & 15;
            cp16(st + r * QROW + c * 16,           kh_ + r * D + c * 8);
            cp16(st + VH_SOFF + r * QROW + c * 16, vh_ + r * D + c * 8);
        }
        asm volatile("cp.async.commit_group;" ::: "memory");
    };
    fillkv(0, 0);   // Q cp.asyncs ride this group

    float m0 = -INFINITY, m1 = -INFINITY, l0 = 0.f, l1 = 0.f;
    float o[16][4];
#pragma unroll
    for (int f = 0; f < 16; f++)
#pragma unroll
        for (int e = 0; e < 4; e++) o[f][e] = 0.f;

    const uint32_t aQ = (uint32_t)((wid * 16 + (lane & 15)) * QROW + ((lane >> 4) << 4));
    const uint32_t bK = (uint32_t)((lane & 15) * QROW + ((lane >> 4) << 4));

    for (int kt = 0; kt <= qt; kt++) {
        asm volatile("cp.async.wait_group 0;" ::: "memory");
        __syncthreads();
        if (kt < qt) fillkv((kt + 1) & 1, kt + 1);
        const uint32_t st = sb + SK0_OFF + (kt & 1) * KSTG;

        // ---- scores: 1-term QK over 128 cols ----
        float s[16][4];
#pragma unroll
        for (int f = 0; f < 16; f++)
#pragma unroll
            for (int e = 0; e < 4; e++) s[f][e] = 0.f;

#pragma unroll
        for (int ks = 0; ks < 8; ks++) {
            const uint32_t ko = ks * 32;
            uint32_t qh4[4];
            ldsm4(sb + SQH_OFF + aQ + ko, qh4[0], qh4[1], qh4[2], qh4[3]);
#pragma unroll
            for (int nb = 0; nb < 8; nb++) {
                uint32_t k0, k1, k2, k3;
                ldsm4(st + bK + nb * (16 * QROW) + ko, k0, k1, k2, k3);
                mma16816(s[nb * 2],     qh4, k0, k2);
                mma16816(s[nb * 2 + 1], qh4, k1, k3);
            }
        }

        // ---- causal mask (diagonal tile only) ----
        if (kt == qt) {
            const int r0 = qt * 128 + wid * 16 + (lane >> 2);
            const int r1 = r0 + 8;
#pragma unroll
            for (int f = 0; f < 16; f++) {
                const int c0 = kt * 128 + f * 8 + (lane & 3) * 2;
                if (c0     > r0) s[f][0] = -INFINITY;
                if (c0 + 1 > r0) s[f][1] = -INFINITY;
                if (c0     > r1) s[f][2] = -INFINITY;
                if (c0 + 1 > r1) s[f][3] = -INFINITY;
            }
        }

        // ---- online softmax over 128 cols ----
        float a0 = -INFINITY, a1 = -INFINITY;
#pragma unroll
        for (int f = 0; f < 16; f++) {
            a0 = fmaxf(a0, fmaxf(s[f][0], s[f][1]));
            a1 = fmaxf(a1, fmaxf(s[f][2], s[f][3]));
        }
        a0 = fmaxf(a0, __shfl_xor_sync(0xffffffffu, a0, 1));
        a0 = fmaxf(a0, __shfl_xor_sync(0xffffffffu, a0, 2));
        a1 = fmaxf(a1, __shfl_xor_sync(0xffffffffu, a1, 1));
        a1 = fmaxf(a1, __shfl_xor_sync(0xffffffffu, a1, 2));
        const float mn0 = fmaxf(m0, a0), mn1 = fmaxf(m1, a1);
        const float sc0 = exp2f((m0 - mn0) * LOG2E);
        const float sc1 = exp2f((m1 - mn1) * LOG2E);
        float rs0 = 0.f, rs1 = 0.f;
#pragma unroll
        for (int f = 0; f < 16; f++) {
            s[f][0] = exp2f((s[f][0] - mn0) * LOG2E + PBIAS);
            s[f][1] = exp2f((s[f][1] - mn0) * LOG2E + PBIAS);
            s[f][2] = exp2f((s[f][2] - mn1) * LOG2E + PBIAS);
            s[f][3] = exp2f((s[f][3] - mn1) * LOG2E + PBIAS);
            rs0 += s[f][0] + s[f][1];
            rs1 += s[f][2] + s[f][3];
        }
        rs0 += __shfl_xor_sync(0xffffffffu, rs0, 1);
        rs0 += __shfl_xor_sync(0xffffffffu, rs0, 2);
        rs1 += __shfl_xor_sync(0xffffffffu, rs1, 1);
        rs1 += __shfl_xor_sync(0xffffffffu, rs1, 2);
        m0 = mn0; m1 = mn1;
        l0 = l0 * sc0 + rs0;
        l1 = l1 * sc1 + rs1;
#pragma unroll
        for (int f = 0; f < 16; f++) {
            o[f][0] *= sc0; o[f][1] *= sc0;
            o[f][2] *= sc1; o[f][3] *= sc1;
        }

        // ---- pack P to fp16 A-frags (8 kb blocks of 16) ----
        uint32_t ph[8][4];
#pragma unroll
        for (int kb = 0; kb < 8; kb++) {
            __half2 t;
            t = __floats2half2_rn(s[2 * kb][0],     s[2 * kb][1]);     ph[kb][0] = *(uint32_t*)&t;
            t = __floats2half2_rn(s[2 * kb][2],     s[2 * kb][3]);     ph[kb][1] = *(uint32_t*)&t;
            t = __floats2half2_rn(s[2 * kb + 1][0], s[2 * kb + 1][1]); ph[kb][2] = *(uint32_t*)&t;
            t = __floats2half2_rn(s[2 * kb + 1][2], s[2 * kb + 1][3]); ph[kb][3] = *(uint32_t*)&t;
        }

        // ---- PV: 1-term, row-major V via ldmatrix.trans ----
#pragma unroll
        for (int kb = 0; kb < 8; kb++) {
#pragma unroll
            for (int dp = 0; dp < 8; dp++) {
                uint32_t v0, v1, v2, v3;
                ldsm4t(st + VH_SOFF + bK + kb * (16 * QROW) + dp * 32, v0, v1, v2, v3);
                mma16816(o[dp * 2],     ph[kb], v0, v1);
                mma16816(o[dp * 2 + 1], ph[kb], v2, v3);
            }
        }
    }

    // ---- epilogue: O/l, single fp16 for 1-term O-projection ----
    const float i0 = 1.f / l0, i1 = 1.f / l1;
    const int gr0 = qt * 128 + wid * 16 + (lane >> 2);
#pragma unroll
    for (int f = 0; f < 16; f++) {
        const int d0 = f * 8 + (lane & 3) * 2;
        const size_t ix0 = ((size_t)(b * S + gr0) * NH + h) * D + d0;
        const size_t ix1 = ((size_t)(b * S + gr0 + 8) * NH + h) * D + d0;
        __half2 h0 = __floats2half2_rn(o[f][0] * i0, o[f][1] * i0);
        __half2 h1 = __floats2half2_rn(o[f][2] * i1, o[f][3] * i1);
        *(__half2*)(g_aoh + ix0) = h0;
        *(__half2*)(g_aoh + ix1) = h1;
    }
}

// ============================================================================
// host launcher
// ============================================================================
extern "C" void kernel_launch(void* const* d_in, const int* in_sizes, int n_in,
                              void* d_out, int out_size)
{
    const float* hidden = (const float*)d_in[0];
    const float* cosb   = (const float*)d_in[1];
    const float* sinb   = (const float*)d_in[2];
    const float* Wq     = (const float*)d_in[3];
    const float* Wk     = (const float*)d_in[4];
    const float* Wv     = (const float*)d_in[5];
    const float* Wo     = (const float*)d_in[6];
    const float* qw     = (const float*)d_in[7];
    const float* kw     = (const float*)d_in[8];
    float* out = (float*)d_out;

    __half *xh, *wh, *woh, *aoh;
    cudaGetSymbolAddress((void**)&xh,  g_xh);
    cudaGetSymbolAddress((void**)&wh,  g_wh);
    cudaGetSymbolAddress((void**)&woh, g_woh);
    cudaGetSymbolAddress((void**)&aoh, g_aoh);

    cudaFuncSetAttribute(gemm_mma<true>,  cudaFuncAttributeMaxDynamicSharedMemorySize, GSMEM_QKV);
    cudaFuncSetAttribute(gemm_mma<false>, cudaFuncAttributeMaxDynamicSharedMemorySize, GSMEM_O);
    cudaFuncSetAttribute(flash_mma, cudaFuncAttributeMaxDynamicSharedMemorySize, FSMEM);

    // all conversions in one launch
    cvt_all<<<(N4ALL + 255) / 256, 256>>>(hidden, Wq, Wk, Wv, Wo);

    // fused QKV projection + RMSNorm + RoPE -> g_qh / g_kh / g_vrow
    gemm_mma<true><<<dim3(NQKV / 128, MSEQ / 128), 256, GSMEM_QKV>>>(
        xh, wh, nullptr, MSEQ, NQKV, H, cosb, sinb, qw, kw);

    // causal flash attention (BM=BN=128)
    flash_mma<<<dim3(S / 128, B * NH), 256, FSMEM>>>();

    // output projection (fp32 out): [2048, 4096] = AO * Wo^T
    gemm_mma<false><<<dim3(H / 128, MSEQ / 128), 256, GSMEM_O>>>(
        aoh, woh, out, MSEQ, H, NH * D, nullptr, nullptr, nullptr, nullptr);
}

// round 16
// speedup vs baseline: 8.3146x; 1.1017x over previous
#include <cuda_runtime.h>
#include <cuda_fp16.h>
#include <math.h>
#include <stdint.h>

// ---------------- problem constants ----------------
#define B   2
#define S   1024
#define H   4096
#define NH  32
#define NKV 8
#define D   128
#define GROUPS (NH / NKV)   // 4
#define EPS 1e-6f
#define QSCALE 0.08838834764831845f   // 1/sqrt(128)
#define MSEQ (B * S)        // 2048 rows
#define NQKV ((NH + 2 * NKV) * D)   // 6144
#define LOG2E 1.4426950408889634f
#define PBIAS  12.0f                 // P scaled by 2^12 (cancels in O/l)

// ---------------- scratch (device globals, fp16) ----------------
__device__ __align__(16) __half g_xh [MSEQ * H];       // hidden fp16
__device__ __align__(16) __half g_wh [NQKV * H];       // stacked Wq|Wk|Wv
__device__ __align__(16) __half g_woh[H * NH * D];     // Wo
__device__ __align__(16) __half g_aoh[MSEQ * NH * D];  // attn out fp16
// flash inputs: q (pre-scaled by QSCALE), k row-major, v row-major
__device__ __align__(16) __half g_qh [B * NH  * S * D];
__device__ __align__(16) __half g_kh [B * NKV * S * D];
__device__ __align__(16) __half g_vrow[B * NKV * S * D];   // [B,NKV,S,D]

// ---------------- small helpers ----------------
__device__ __forceinline__ void cp16(uint32_t dst, const void* src) {
    asm volatile("cp.async.cg.shared.global [%0], [%1], 16;" :: "r"(dst), "l"(src) : "memory");
}
__device__ __forceinline__ void ldsm4(uint32_t addr, uint32_t& r0, uint32_t& r1,
                                      uint32_t& r2, uint32_t& r3) {
    asm volatile("ldmatrix.sync.aligned.m8n8.x4.shared.b16 {%0,%1,%2,%3}, [%4];"
        : "=r"(r0), "=r"(r1), "=r"(r2), "=r"(r3) : "r"(addr));
}
__device__ __forceinline__ void ldsm4t(uint32_t addr, uint32_t& r0, uint32_t& r1,
                                       uint32_t& r2, uint32_t& r3) {
    asm volatile("ldmatrix.sync.aligned.m8n8.x4.trans.shared.b16 {%0,%1,%2,%3}, [%4];"
        : "=r"(r0), "=r"(r1), "=r"(r2), "=r"(r3) : "r"(addr));
}
__device__ __forceinline__ void mma16816(float* c, const uint32_t* a,
                                         uint32_t b0, uint32_t b1) {
    asm volatile("mma.sync.aligned.m16n8k16.row.col.f32.f16.f16.f32 "
        "{%0,%1,%2,%3}, {%4,%5,%6,%7}, {%8,%9}, {%0,%1,%2,%3};"
        : "+f"(c[0]), "+f"(c[1]), "+f"(c[2]), "+f"(c[3])
        : "r"(a[0]), "r"(a[1]), "r"(a[2]), "r"(a[3]), "r"(b0), "r"(b1));
}

// ============================================================================
// all conversions in ONE launch
// ============================================================================
#define N4X (MSEQ * H / 4)
#define N4Q (NH * D * H / 4)
#define N4K (NKV * D * H / 4)
#define N4ALL (N4X + N4Q + 2 * N4K + N4Q)

__global__ void __launch_bounds__(256) cvt_all(
    const float* __restrict__ hidden,
    const float* __restrict__ Wq, const float* __restrict__ Wk,
    const float* __restrict__ Wv, const float* __restrict__ Wo)
{
    int i = blockIdx.x * 256 + threadIdx.x;
    if (i >= N4ALL) return;
    const float* src;
    __half* dst;
    int j = i;
    if (j < N4X)                { src = hidden; dst = g_xh; }
    else if ((j -= N4X) < N4Q)  { src = Wq; dst = g_wh; }
    else if ((j -= N4Q) < N4K)  { src = Wk; dst = g_wh + (size_t)NH * D * H; }
    else if ((j -= N4K) < N4K)  { src = Wv; dst = g_wh + (size_t)(NH + NKV) * D * H; }
    else { j -= N4K;              src = Wo; dst = g_woh; }
    float4 x = ((const float4*)src)[j];
    ((__half2*)dst)[2 * j]     = __floats2half2_rn(x.x, x.y);
    ((__half2*)dst)[2 * j + 1] = __floats2half2_rn(x.z, x.w);
}

// ============================================================================
// mma.sync fp16 NT GEMM (1 term): C[M,N] = A[M,K]*B[N,K]^T.
// Block tile 128x128, K-tile 64, 8 warps (4m x 2n), warp tile 32x64.
// 3-stage cp.async ring, ONE __syncthreads per K-tile (64 K-elems), 2 CTAs/SM.
// FUSED=true (QKV): one N-tile == one head; epilogue does RMSNorm+RoPE.
// ============================================================================
#define ROWB 144                       // bytes per 64-fp16 row (128 + 16 pad)
#define MATB (128 * ROWB)              // 18432 per matrix tile
#define STGB (2 * MATB)                // A|B per stage = 36864
#define GSMEM_PIPE (3 * STGB)          // 110592
#define EPI_PITCH 132
#define GSMEM_EPI  (128 * EPI_PITCH * 4 + 128 * 2 * 4)   // 68608
#define GSMEM_QKV  GSMEM_PIPE          // 110592 (>= EPI)
#define GSMEM_O    GSMEM_PIPE

template<bool FUSED>
__global__ void __launch_bounds__(256, 2) gemm_mma(
    const __half* __restrict__ A, const __half* __restrict__ Bm,
    float* __restrict__ C, int M, int N, int K,
    const float* __restrict__ cosb, const float* __restrict__ sinb,
    const float* __restrict__ qw,   const float* __restrict__ kw)
{
    extern __shared__ __align__(128) char smem[];
    const uint32_t sbase = (uint32_t)__cvta_generic_to_shared(smem);
    const int tid  = threadIdx.x;
    const int lane = tid & 31;
    const int wid  = tid >> 5;
    const int warp_m = wid >> 1;
    const int warp_n = wid & 1;
    const int m0 = blockIdx.y * 128;
    const int n0 = blockIdx.x * 128;
    const int KT = K >> 6;         // K / 64

    float acc[2][8][4];
#pragma unroll
    for (int i = 0; i < 2; i++)
#pragma unroll
        for (int j = 0; j < 8; j++)
#pragma unroll
            for (int q = 0; q < 4; q++) acc[i][j][q] = 0.f;

    // per stage: 2 matrices x 128 rows x 8 chunks of 16B = 2048 cp16 -> 8/thread
    auto fill = [&](int s, int kt) {
        const uint32_t st = sbase + s * STGB;
#pragma unroll
        for (int i = 0; i < 8; i++) {
            const int v = ((i & 3) << 8) + tid;     // 0..1023 within matrix
            const int r = v >> 3, c = v & 7;
            const __half* gb = (i < 4) ? A : Bm;
            const int grow = ((i < 4) ? m0 : n0) + r;
            cp16(st + (i >> 2) * MATB + r * ROWB + c * 16,
                 gb + (size_t)grow * K + (size_t)kt * 64 + c * 8);
        }
        asm volatile("cp.async.commit_group;" ::: "memory");
    };

    fill(0, 0); fill(1, 1); fill(2, 2);

    const uint32_t aOff = (uint32_t)((warp_m * 32 + (lane & 15)) * ROWB + ((lane >> 4) << 4));
    const uint32_t bOff = (uint32_t)(MATB + (warp_n * 64 + (lane & 15)) * ROWB + ((lane >> 4) << 4));

    for (int kt = 0; kt < KT; kt++) {
        asm volatile("cp.async.wait_group 1;" ::: "memory");
        __syncthreads();     // all warps done with iter kt-1 -> slot (kt-1)%3 free
        if (kt >= 1) {
            const int t = kt + 2;
            if (t < KT) fill(t % 3, t);
            else asm volatile("cp.async.commit_group;" ::: "memory");
        }

        const uint32_t st = sbase + (kt % 3) * STGB;
#pragma unroll
        for (int k16 = 0; k16 < 4; k16++) {
            const uint32_t ko = k16 * 32;
            uint32_t a[2][4], bh[4][4];
#pragma unroll
            for (int mi = 0; mi < 2; mi++)
                ldsm4(st + aOff + mi * (16 * ROWB) + ko,
                      a[mi][0], a[mi][1], a[mi][2], a[mi][3]);
#pragma unroll
            for (int ni = 0; ni < 4; ni++)
                ldsm4(st + bOff + ni * (16 * ROWB) + ko,
                      bh[ni][0], bh[ni][1], bh[ni][2], bh[ni][3]);
#pragma unroll
            for (int mi = 0; mi < 2; mi++)
#pragma unroll
                for (int ni = 0; ni < 4; ni++) {
                    mma16816(acc[mi][ni * 2],     a[mi], bh[ni][0], bh[ni][2]);
                    mma16816(acc[mi][ni * 2 + 1], a[mi], bh[ni][1], bh[ni][3]);
                }
        }
    }

    if (!FUSED) {
#pragma unroll
        for (int mi = 0; mi < 2; mi++) {
            const int row = m0 + warp_m * 32 + mi * 16 + (lane >> 2);
#pragma unroll
            for (int nj = 0; nj < 8; nj++) {
                const int col = n0 + warp_n * 64 + nj * 8 + (lane & 3) * 2;
                *(float2*)(C + (size_t)row * N + col) =
                    make_float2(acc[mi][nj][0], acc[mi][nj][1]);
                *(float2*)(C + (size_t)(row + 8) * N + col) =
                    make_float2(acc[mi][nj][2], acc[mi][nj][3]);
            }
        }
        return;
    }

    // ---- fused QKV epilogue: this N-tile is one head (hs = n0/128) ----
    asm volatile("cp.async.wait_group 0;" ::: "memory");
    __syncthreads();   // pipeline smem now free for staging

    const int hs = n0 >> 7;
    const int rbase = warp_m * 32 + (lane >> 2);

    if (hs >= NH + NKV) {
        const int vh = hs - NH - NKV;
#pragma unroll
        for (int mi = 0; mi < 2; mi++) {
            const int rl = rbase + mi * 16;
#pragma unroll
            for (int nj = 0; nj < 8; nj++) {
                const int d = warp_n * 64 + nj * 8 + (lane & 3) * 2;
                const int bs0 = m0 + rl, bs1 = bs0 + 8;
                const size_t i0 = (((size_t)(bs0 >> 10) * NKV + vh) * S + (bs0 & 1023)) * D + d;
                const size_t i1 = (((size_t)(bs1 >> 10) * NKV + vh) * S + (bs1 & 1023)) * D + d;
                *(__half2*)(g_vrow + i0) = __floats2half2_rn(acc[mi][nj][0], acc[mi][nj][1]);
                *(__half2*)(g_vrow + i1) = __floats2half2_rn(acc[mi][nj][2], acc[mi][nj][3]);
            }
        }
        return;
    }

    const bool isQ = (hs < NH);
    float* sst  = (float*)smem;
    float* ssum = sst + 128 * EPI_PITCH;

#pragma unroll
    for (int mi = 0; mi < 2; mi++) {
        float s0 = 0.f, s1 = 0.f;
#pragma unroll
        for (int nj = 0; nj < 8; nj++) {
            s0 += acc[mi][nj][0] * acc[mi][nj][0] + acc[mi][nj][1] * acc[mi][nj][1];
            s1 += acc[mi][nj][2] * acc[mi][nj][2] + acc[mi][nj][3] * acc[mi][nj][3];
        }
        s0 += __shfl_xor_sync(0xffffffffu, s0, 1);
        s0 += __shfl_xor_sync(0xffffffffu, s0, 2);
        s1 += __shfl_xor_sync(0xffffffffu, s1, 1);
        s1 += __shfl_xor_sync(0xffffffffu, s1, 2);
        if ((lane & 3) == 0) {
            ssum[(rbase + mi * 16) * 2 + warp_n]     = s0;
            ssum[(rbase + mi * 16 + 8) * 2 + warp_n] = s1;
        }
    }
    __syncthreads();

    const float* wp = isQ ? qw : kw;
#pragma unroll
    for (int mi = 0; mi < 2; mi++) {
        const int r0 = rbase + mi * 16, r1 = r0 + 8;
        const float inv0 = rsqrtf((ssum[r0 * 2] + ssum[r0 * 2 + 1]) * (1.0f / D) + EPS);
        const float inv1 = rsqrtf((ssum[r1 * 2] + ssum[r1 * 2 + 1]) * (1.0f / D) + EPS);
#pragma unroll
        for (int nj = 0; nj < 8; nj++) {
            const int d = warp_n * 64 + nj * 8 + (lane & 3) * 2;
            const float2 w2 = *(const float2*)(wp + d);
            sst[r0 * EPI_PITCH + d]     = acc[mi][nj][0] * inv0 * w2.x;
            sst[r0 * EPI_PITCH + d + 1] = acc[mi][nj][1] * inv0 * w2.y;
            sst[r1 * EPI_PITCH + d]     = acc[mi][nj][2] * inv1 * w2.x;
            sst[r1 * EPI_PITCH + d + 1] = acc[mi][nj][3] * inv1 * w2.y;
        }
    }
    __syncthreads();

    const float oscale = isQ ? QSCALE : 1.0f;
#pragma unroll
    for (int mi = 0; mi < 2; mi++) {
        const int rl0 = rbase + mi * 16;
#pragma unroll
        for (int half = 0; half < 2; half++) {
            const int rl = rl0 + half * 8;
            const int bs = m0 + rl;
            const int b  = bs >> 10, s = bs & 1023;
#pragma unroll
            for (int nj = 0; nj < 8; nj++) {
                const int d = warp_n * 64 + nj * 8 + (lane & 3) * 2;
                const float2 c2 = *(const float2*)(cosb + (size_t)bs * D + d);
                const float2 s2 = *(const float2*)(sinb + (size_t)bs * D + d);
                const float v0 = sst[rl * EPI_PITCH + d];
                const float v1 = sst[rl * EPI_PITCH + d + 1];
                const float p0 = sst[rl * EPI_PITCH + (d ^ 64)];
                const float p1 = sst[rl * EPI_PITCH + (d ^ 64) + 1];
                const float sgn = (d < 64) ? -1.f : 1.f;
                const float o0 = (v0 * c2.x + sgn * p0 * s2.x) * oscale;
                const float o1 = (v1 * c2.y + sgn * p1 * s2.y) * oscale;
                if (isQ) {
                    const size_t ix = (((size_t)b * NH + hs) * S + s) * D + d;
                    *(__half2*)(g_qh + ix) = __floats2half2_rn(o0, o1);
                } else {
                    const size_t ix = (((size_t)b * NKV + (hs - NH)) * S + s) * D + d;
                    *(__half2*)(g_kh + ix) = __floats2half2_rn(o0, o1);
                }
            }
        }
    }
}

// ============================================================================
// Causal flash attention: BM=128, BN=128, 1-term QK + 1-term PV,
// V via ldmatrix.trans. 8 warps, 2-stage KV pipeline.
// ============================================================================
#define QROW 272                       // 128 fp16 + 8 pad
#define SQH_OFF 0
#define SK0_OFF (128 * QROW)           // 34816
#define VH_SOFF (128 * QROW)           // V within stage (34816)
#define KSTG    (2 * 128 * QROW)       // 69632
#define FSMEM   (SK0_OFF + 2 * KSTG)   // 174080

__global__ void __launch_bounds__(256) flash_mma()
{
    extern __shared__ __align__(128) char fsm[];
    const uint32_t sb = (uint32_t)__cvta_generic_to_shared(fsm);
    const int tid = threadIdx.x, lane = tid & 31, wid = tid >> 5;
    const int qt = (int)gridDim.x - 1 - (int)blockIdx.x;   // heavy CTAs first
    const int bh = blockIdx.y;
    const int b = bh / NH, h = bh - b * NH;
    const int kvh = h / GROUPS;

    const __half* Qhp = g_qh + (((size_t)b * NH + h) * S + (size_t)qt * 128) * D;
    const __half* Khp = g_kh + ((size_t)b * NKV + kvh) * S * D;
    const __half* Vhp = g_vrow + ((size_t)b * NKV + kvh) * S * D;

#pragma unroll
    for (int i = tid; i < 2048; i += 256) {
        const int r = i >> 4, c = i & 15;
        cp16(sb + SQH_OFF + r * QROW + c * 16, Qhp + r * D + c * 8);
    }

    auto fillkv = [&](int slot, int kt) {
        const uint32_t st = sb + SK0_OFF + slot * KSTG;
        const __half* kh_ = Khp + (size_t)kt * 128 * D;
        const __half* vh_ = Vhp + (size_t)kt * 128 * D;
#pragma unroll
        for (int i = tid; i < 2048; i += 256) {
            const int r = i >> 4, c = i & 15;
            cp16(st + r * QROW + c * 16,           kh_ + r * D + c * 8);
            cp16(st + VH_SOFF + r * QROW + c * 16, vh_ + r * D + c * 8);
        }
        asm volatile("cp.async.commit_group;" ::: "memory");
    };
    fillkv(0, 0);   // Q cp.asyncs ride this group

    float m0 = -INFINITY, m1 = -INFINITY, l0 = 0.f, l1 = 0.f;
    float o[16][4];
#pragma unroll
    for (int f = 0; f < 16; f++)
#pragma unroll
        for (int e = 0; e < 4; e++) o[f][e] = 0.f;

    const uint32_t aQ = (uint32_t)((wid * 16 + (lane & 15)) * QROW + ((lane >> 4) << 4));
    const uint32_t bK = (uint32_t)((lane & 15) * QROW + ((lane >> 4) << 4));

    for (int kt = 0; kt <= qt; kt++) {
        asm volatile("cp.async.wait_group 0;" ::: "memory");
        __syncthreads();
        if (kt < qt) fillkv((kt + 1) & 1, kt + 1);
        const uint32_t st = sb + SK0_OFF + (kt & 1) * KSTG;

        float s[16][4];
#pragma unroll
        for (int f = 0; f < 16; f++)
#pragma unroll
            for (int e = 0; e < 4; e++) s[f][e] = 0.f;

#pragma unroll
        for (int ks = 0; ks < 8; ks++) {
            const uint32_t ko = ks * 32;
            uint32_t qh4[4];
            ldsm4(sb + SQH_OFF + aQ + ko, qh4[0], qh4[1], qh4[2], qh4[3]);
#pragma unroll
            for (int nb = 0; nb < 8; nb++) {
                uint32_t k0, k1, k2, k3;
                ldsm4(st + bK + nb * (16 * QROW) + ko, k0, k1, k2, k3);
                mma16816(s[nb * 2],     qh4, k0, k2);
                mma16816(s[nb * 2 + 1], qh4, k1, k3);
            }
        }

        if (kt == qt) {
            const int r0 = qt * 128 + wid * 16 + (lane >> 2);
            const int r1 = r0 + 8;
#pragma unroll
            for (int f = 0; f < 16; f++) {
                const int c0 = kt * 128 + f * 8 + (lane & 3) * 2;
                if (c0     > r0) s[f][0] = -INFINITY;
                if (c0 + 1 > r0) s[f][1] = -INFINITY;
                if (c0     > r1) s[f][2] = -INFINITY;
                if (c0 + 1 > r1) s[f][3] = -INFINITY;
            }
        }

        float a0 = -INFINITY, a1 = -INFINITY;
#pragma unroll
        for (int f = 0; f < 16; f++) {
            a0 = fmaxf(a0, fmaxf(s[f][0], s[f][1]));
            a1 = fmaxf(a1, fmaxf(s[f][2], s[f][3]));
        }
        a0 = fmaxf(a0, __shfl_xor_sync(0xffffffffu, a0, 1));
        a0 = fmaxf(a0, __shfl_xor_sync(0xffffffffu, a0, 2));
        a1 = fmaxf(a1, __shfl_xor_sync(0xffffffffu, a1, 1));
        a1 = fmaxf(a1, __shfl_xor_sync(0xffffffffu, a1, 2));
        const float mn0 = fmaxf(m0, a0), mn1 = fmaxf(m1, a1);
        const float sc0 = exp2f((m0 - mn0) * LOG2E);
        const float sc1 = exp2f((m1 - mn1) * LOG2E);
        float rs0 = 0.f, rs1 = 0.f;
#pragma unroll
        for (int f = 0; f < 16; f++) {
            s[f][0] = exp2f((s[f][0] - mn0) * LOG2E + PBIAS);
            s[f][1] = exp2f((s[f][1] - mn0) * LOG2E + PBIAS);
            s[f][2] = exp2f((s[f][2] - mn1) * LOG2E + PBIAS);
            s[f][3] = exp2f((s[f][3] - mn1) * LOG2E + PBIAS);
            rs0 += s[f][0] + s[f][1];
            rs1 += s[f][2] + s[f][3];
        }
        rs0 += __shfl_xor_sync(0xffffffffu, rs0, 1);
        rs0 += __shfl_xor_sync(0xffffffffu, rs0, 2);
        rs1 += __shfl_xor_sync(0xffffffffu, rs1, 1);
        rs1 += __shfl_xor_sync(0xffffffffu, rs1, 2);
        m0 = mn0; m1 = mn1;
        l0 = l0 * sc0 + rs0;
        l1 = l1 * sc1 + rs1;
#pragma unroll
        for (int f = 0; f < 16; f++) {
            o[f][0] *= sc0; o[f][1] *= sc0;
            o[f][2] *= sc1; o[f][3] *= sc1;
        }

        uint32_t ph[8][4];
#pragma unroll
        for (int kb = 0; kb < 8; kb++) {
            __half2 t;
            t = __floats2half2_rn(s[2 * kb][0],     s[2 * kb][1]);     ph[kb][0] = *(uint32_t*)&t;
            t = __floats2half2_rn(s[2 * kb][2],     s[2 * kb][3]);     ph[kb][1] = *(uint32_t*)&t;
            t = __floats2half2_rn(s[2 * kb + 1][0], s[2 * kb + 1][1]); ph[kb][2] = *(uint32_t*)&t;
            t = __floats2half2_rn(s[2 * kb + 1][2], s[2 * kb + 1][3]); ph[kb][3] = *(uint32_t*)&t;
        }

#pragma unroll
        for (int kb = 0; kb < 8; kb++) {
#pragma unroll
            for (int dp = 0; dp < 8; dp++) {
                uint32_t v0, v1, v2, v3;
                ldsm4t(st + VH_SOFF + bK + kb * (16 * QROW) + dp * 32, v0, v1, v2, v3);
                mma16816(o[dp * 2],     ph[kb], v0, v1);
                mma16816(o[dp * 2 + 1], ph[kb], v2, v3);
            }
        }
    }

    const float i0 = 1.f / l0, i1 = 1.f / l1;
    const int gr0 = qt * 128 + wid * 16 + (lane >> 2);
#pragma unroll
    for (int f = 0; f < 16; f++) {
        const int d0 = f * 8 + (lane & 3) * 2;
        const size_t ix0 = ((size_t)(b * S + gr0) * NH + h) * D + d0;
        const size_t ix1 = ((size_t)(b * S + gr0 + 8) * NH + h) * D + d0;
        __half2 h0 = __floats2half2_rn(o[f][0] * i0, o[f][1] * i0);
        __half2 h1 = __floats2half2_rn(o[f][2] * i1, o[f][3] * i1);
        *(__half2*)(g_aoh + ix0) = h0;
        *(__half2*)(g_aoh + ix1) = h1;
    }
}

// ============================================================================
// host launcher
// ============================================================================
extern "C" void kernel_launch(void* const* d_in, const int* in_sizes, int n_in,
                              void* d_out, int out_size)
{
    const float* hidden = (const float*)d_in[0];
    const float* cosb   = (const float*)d_in[1];
    const float* sinb   = (const float*)d_in[2];
    const float* Wq     = (const float*)d_in[3];
    const float* Wk     = (const float*)d_in[4];
    const float* Wv     = (const float*)d_in[5];
    const float* Wo     = (const float*)d_in[6];
    const float* qw     = (const float*)d_in[7];
    const float* kw     = (const float*)d_in[8];
    float* out = (float*)d_out;

    __half *xh, *wh, *woh, *aoh;
    cudaGetSymbolAddress((void**)&xh,  g_xh);
    cudaGetSymbolAddress((void**)&wh,  g_wh);
    cudaGetSymbolAddress((void**)&woh, g_woh);
    cudaGetSymbolAddress((void**)&aoh, g_aoh);

    cudaFuncSetAttribute(gemm_mma<true>,  cudaFuncAttributeMaxDynamicSharedMemorySize, GSMEM_QKV);
    cudaFuncSetAttribute(gemm_mma<false>, cudaFuncAttributeMaxDynamicSharedMemorySize, GSMEM_O);
    cudaFuncSetAttribute(flash_mma, cudaFuncAttributeMaxDynamicSharedMemorySize, FSMEM);

    // all conversions in one launch
    cvt_all<<<(N4ALL + 255) / 256, 256>>>(hidden, Wq, Wk, Wv, Wo);

    // fused QKV projection + RMSNorm + RoPE -> g_qh / g_kh / g_vrow
    gemm_mma<true><<<dim3(NQKV / 128, MSEQ / 128), 256, GSMEM_QKV>>>(
        xh, wh, nullptr, MSEQ, NQKV, H, cosb, sinb, qw, kw);

    // causal flash attention (BM=BN=128)
    flash_mma<<<dim3(S / 128, B * NH), 256, FSMEM>>>();

    // output projection (fp32 out): [2048, 4096] = AO * Wo^T
    gemm_mma<false><<<dim3(H / 128, MSEQ / 128), 256, GSMEM_O>>>(
        aoh, woh, out, MSEQ, H, NH * D, nullptr, nullptr, nullptr, nullptr);
}